// round 1
// baseline (speedup 1.0000x reference)
#include <cuda_runtime.h>
#include <math.h>

// ---------------- problem constants ----------------
#define BB    16
#define LSEQ  2048
#define BL    (BB*LSEQ)        // 32768
#define DM    128
#define HH    4
#define HDIM  32
#define FFD   256
#define C1    128
#define C2    256
#define KK    5
#define L2HALF 1024            // L/2
#define L2OUT  1020            // valid conv2 output length
#define M2    (BB*L2OUT)       // 16320
#define EPSV  1e-5f

// ---------------- scratch (static device memory; no allocation) ----------------
__device__ float g_x0 [BL*DM];
__device__ float g_qkv[BL*3*DM];
__device__ float g_att[BL*DM];
__device__ float g_tmp[BL*DM];
__device__ float g_x1 [BL*DM];
__device__ float g_ff1[BL*FFD];
__device__ float g_x2 [BL*DM];
__device__ float g_col[BL*640];       // im2col scratch (reused for conv1 and conv2)
__device__ float g_y1 [BL*C1];
__device__ float g_p1 [BB*L2HALF*C1];
__device__ float g_y2 [M2*C2];
__device__ float g_z  [BB*C2];
__device__ float g_stats[2*C1 + 2*C2]; // sum1, sq1, sum2, sq2

// ---------------- embed ----------------
__global__ void embed_kernel(const int* __restrict__ X, const float* __restrict__ sa,
                             const int* __restrict__ ptm,
                             const float* __restrict__ emb, const float* __restrict__ pemb,
                             float* __restrict__ x0)
{
    int row = blockIdx.x;          // 0..BL-1
    int t = threadIdx.x;           // 0..127
    float v;
    if (t < 120) v = emb[X[row]*120 + t] * sa[row];
    else         v = pemb[ptm[row]*8 + (t-120)];
    x0[(size_t)row*DM + t] = v;
}

// ---------------- generic tiled GEMM: C[M,N] = A[M,K] @ W[N,K]^T + bias (+relu) ----------------
__global__ __launch_bounds__(256) void gemm_kernel(const float* __restrict__ A,
                                                   const float* __restrict__ W,
                                                   const float* __restrict__ bias,
                                                   float* __restrict__ C,
                                                   int M, int N, int K, int relu)
{
    __shared__ float As[16][68];
    __shared__ float Bs[16][68];
    int tid = threadIdx.x;
    int tx = tid & 15, ty = tid >> 4;
    int row0 = blockIdx.y * 64;
    int col0 = blockIdx.x * 64;

    float acc[4][4];
    #pragma unroll
    for (int i=0;i<4;++i)
        #pragma unroll
        for (int j=0;j<4;++j) acc[i][j]=0.f;

    for (int k0 = 0; k0 < K; k0 += 16) {
        #pragma unroll
        for (int p = 0; p < 4; ++p) {
            int m = ty + p*16;
            int r = row0 + m;
            As[tx][m] = (r < M) ? A[(size_t)r*K + k0 + tx] : 0.f;
        }
        #pragma unroll
        for (int p = 0; p < 4; ++p) {
            int n = ty + p*16;
            int c = col0 + n;
            Bs[tx][n] = (c < N) ? W[(size_t)c*K + k0 + tx] : 0.f;
        }
        __syncthreads();
        #pragma unroll
        for (int kk = 0; kk < 16; ++kk) {
            float a0 = As[kk][ty*4+0], a1 = As[kk][ty*4+1];
            float a2 = As[kk][ty*4+2], a3 = As[kk][ty*4+3];
            float b0 = Bs[kk][tx*4+0], b1 = Bs[kk][tx*4+1];
            float b2 = Bs[kk][tx*4+2], b3 = Bs[kk][tx*4+3];
            acc[0][0]+=a0*b0; acc[0][1]+=a0*b1; acc[0][2]+=a0*b2; acc[0][3]+=a0*b3;
            acc[1][0]+=a1*b0; acc[1][1]+=a1*b1; acc[1][2]+=a1*b2; acc[1][3]+=a1*b3;
            acc[2][0]+=a2*b0; acc[2][1]+=a2*b1; acc[2][2]+=a2*b2; acc[2][3]+=a2*b3;
            acc[3][0]+=a3*b0; acc[3][1]+=a3*b1; acc[3][2]+=a3*b2; acc[3][3]+=a3*b3;
        }
        __syncthreads();
    }

    #pragma unroll
    for (int i=0;i<4;++i) {
        int r = row0 + ty*4 + i;
        if (r >= M) continue;
        #pragma unroll
        for (int j=0;j<4;++j) {
            int c = col0 + tx*4 + j;
            if (c >= N) continue;
            float v = acc[i][j] + bias[c];
            if (relu) v = fmaxf(v, 0.f);
            C[(size_t)r*N + c] = v;
        }
    }
}

// ---------------- fused flash attention with relative-position bias ----------------
// grid (L/128, H, B), block 128; each thread owns one query row.
__global__ __launch_bounds__(128) void attn_kernel(const float* __restrict__ qkv,
                                                   const float* __restrict__ rpe,
                                                   float* __restrict__ o)
{
    __shared__ float ks[32][32];
    __shared__ float vs[32][32];
    __shared__ float rs[65];
    int tid = threadIdx.x;
    int b = blockIdx.z, h = blockIdx.y;
    int r = blockIdx.x * 128 + tid;
    if (tid < 65) rs[tid] = rpe[tid*HH + h];

    float q[HDIM];
    const float* qrow = qkv + ((size_t)(b*LSEQ + r))*(3*DM) + h*HDIM;
    #pragma unroll
    for (int d = 0; d < HDIM; ++d) q[d] = qrow[d];

    float m = -1e30f, lsum = 0.f;
    float oa[HDIM];
    #pragma unroll
    for (int d = 0; d < HDIM; ++d) oa[d] = 0.f;

    for (int j0 = 0; j0 < LSEQ; j0 += 32) {
        __syncthreads();
        #pragma unroll
        for (int e = tid; e < 1024; e += 128) {
            int j = e >> 5, d = e & 31;
            const float* base = qkv + ((size_t)(b*LSEQ + j0 + j))*(3*DM) + h*HDIM + d;
            ks[j][d] = base[DM];
            vs[j][d] = base[2*DM];
        }
        __syncthreads();
        #pragma unroll 2
        for (int j = 0; j < 32; ++j) {
            float s = 0.f;
            #pragma unroll
            for (int d = 0; d < HDIM; ++d) s += q[d]*ks[j][d];
            int rel = j0 + j - r;
            rel = rel < -32 ? -32 : (rel > 32 ? 32 : rel);
            s = s * 0.17677669529663687f + rs[rel + 32];
            if (s > m) {
                float corr = __expf(m - s);
                lsum *= corr;
                #pragma unroll
                for (int d = 0; d < HDIM; ++d) oa[d] *= corr;
                m = s;
            }
            float p = __expf(s - m);
            lsum += p;
            #pragma unroll
            for (int d = 0; d < HDIM; ++d) oa[d] += p * vs[j][d];
        }
    }

    float inv = 1.f / lsum;
    float* orow = o + ((size_t)(b*LSEQ + r))*DM + h*HDIM;
    #pragma unroll
    for (int d = 0; d < HDIM; ++d) orow[d] = oa[d]*inv;
}

// ---------------- residual add + layernorm over 128 ----------------
__global__ void add_ln_kernel(const float* __restrict__ a, const float* __restrict__ bres,
                              const float* __restrict__ g, const float* __restrict__ beta,
                              float* __restrict__ out)
{
    int row = blockIdx.x;
    int t = threadIdx.x;   // 128
    float v = a[(size_t)row*DM + t] + bres[(size_t)row*DM + t];
    float s = v, s2 = v*v;
    #pragma unroll
    for (int off = 16; off; off >>= 1) {
        s  += __shfl_xor_sync(0xffffffffu, s,  off);
        s2 += __shfl_xor_sync(0xffffffffu, s2, off);
    }
    __shared__ float ws[4], ws2[4];
    int w = t >> 5;
    if ((t & 31) == 0) { ws[w] = s; ws2[w] = s2; }
    __syncthreads();
    s  = ws[0]+ws[1]+ws[2]+ws[3];
    s2 = ws2[0]+ws2[1]+ws2[2]+ws2[3];
    float mean = s * (1.f/128.f);
    float var  = s2 * (1.f/128.f) - mean*mean;
    float f = rsqrtf(var + EPSV);
    out[(size_t)row*DM + t] = (v - mean)*f*g[t] + beta[t];
}

// ---------------- im2col for conv1 (pad=2) ----------------
__global__ void im2col1_kernel(const float* __restrict__ x2, float* __restrict__ col)
{
    long long e = (long long)blockIdx.x*256 + threadIdx.x;
    if (e >= (long long)BL*640) return;
    int c = (int)(e % 640); int row = (int)(e / 640);
    int ci = c/5, k = c%5;
    int b = row >> 11, l = row & 2047;
    int lx = l + k - 2;
    float v = (lx >= 0 && lx < LSEQ) ? x2[((size_t)(b*LSEQ + lx))*DM + ci] : 0.f;
    col[e] = v;
}

// ---------------- im2col for conv2 (valid) ----------------
__global__ void im2col2_kernel(const float* __restrict__ p1, float* __restrict__ col)
{
    long long e = (long long)blockIdx.x*256 + threadIdx.x;
    if (e >= (long long)M2*640) return;
    int c = (int)(e % 640); int row = (int)(e / 640);
    int c1 = c/5, k = c%5;
    int b = row / L2OUT, l = row % L2OUT;
    col[e] = p1[((size_t)(b*L2HALF + l + k))*C1 + c1];
}

// ---------------- BN stats (per-channel sum & sumsq via atomics) ----------------
__global__ void bnstats_kernel(const float* __restrict__ y, int rows, int Cc, int rpb,
                               float* __restrict__ sum, float* __restrict__ sumsq)
{
    int c = threadIdx.x;                 // blockDim.x == Cc
    int r0 = blockIdx.x * rpb;
    int r1 = r0 + rpb; if (r1 > rows) r1 = rows;
    float s = 0.f, s2 = 0.f;
    for (int r = r0; r < r1; ++r) {
        float v = y[(size_t)r*Cc + c];
        s += v; s2 += v*v;
    }
    atomicAdd(&sum[c], s);
    atomicAdd(&sumsq[c], s2);
}

__global__ void zero_kernel(float* p, int n)
{
    int i = blockIdx.x*256 + threadIdx.x;
    if (i < n) p[i] = 0.f;
}

// ---------------- BN + ReLU + maxpool(2) for conv1 output ----------------
__global__ void bnpool_kernel(const float* __restrict__ y1,
                              const float* __restrict__ sum, const float* __restrict__ sq,
                              const float* __restrict__ g, const float* __restrict__ bb,
                              float* __restrict__ p1)
{
    int c = threadIdx.x;                 // 128
    int row2 = blockIdx.x;               // BB*L2HALF
    int b = row2 >> 10, l2 = row2 & 1023;
    float mean = sum[c]*(1.f/(float)BL);
    float var  = sq[c]*(1.f/(float)BL) - mean*mean;
    float f = rsqrtf(var + EPSV)*g[c];
    float v0 = (y1[((size_t)(b*LSEQ + 2*l2  ))*C1 + c] - mean)*f + bb[c];
    float v1 = (y1[((size_t)(b*LSEQ + 2*l2+1))*C1 + c] - mean)*f + bb[c];
    v0 = fmaxf(v0, 0.f); v1 = fmaxf(v1, 0.f);
    p1[(size_t)row2*C1 + c] = fmaxf(v0, v1);
}

// ---------------- BN + ReLU + global max for conv2 output ----------------
__global__ void gmax_kernel(const float* __restrict__ y2,
                            const float* __restrict__ sum, const float* __restrict__ sq,
                            const float* __restrict__ g, const float* __restrict__ bb,
                            float* __restrict__ z)
{
    int c = threadIdx.x;                 // 256
    int b = blockIdx.x;                  // 16
    float mean = sum[c]*(1.f/(float)M2);
    float var  = sq[c]*(1.f/(float)M2) - mean*mean;
    float f = rsqrtf(var + EPSV)*g[c];
    float vm = 0.f;
    for (int l = 0; l < L2OUT; ++l) {
        float v = (y2[((size_t)(b*L2OUT + l))*C2 + c] - mean)*f + bb[c];
        v = fmaxf(v, 0.f);
        vm = fmaxf(vm, v);
    }
    z[b*C2 + c] = vm;
}

// ---------------- final fc ----------------
__global__ void fc_kernel(const float* __restrict__ z, const float* __restrict__ w,
                          const float* __restrict__ bias, float* __restrict__ out)
{
    int b = blockIdx.x, n = blockIdx.y;
    int t = threadIdx.x;   // 256
    float p = z[b*C2 + t] * w[n*C2 + t];
    #pragma unroll
    for (int off = 16; off; off >>= 1) p += __shfl_xor_sync(0xffffffffu, p, off);
    __shared__ float ws[8];
    if ((t & 31) == 0) ws[t >> 5] = p;
    __syncthreads();
    if (t == 0) {
        float s = 0.f;
        #pragma unroll
        for (int i = 0; i < 8; ++i) s += ws[i];
        out[b*2 + n] = s + bias[n];
    }
}

// ---------------- launch ----------------
extern "C" void kernel_launch(void* const* d_in, const int* in_sizes, int n_in,
                              void* d_out, int out_size)
{
    const int*   X    = (const int*)  d_in[0];
    const float* sa   = (const float*)d_in[1];
    const int*   ptm  = (const int*)  d_in[2];
    const float* emb  = (const float*)d_in[3];
    const float* pemb = (const float*)d_in[4];
    const float* rpe  = (const float*)d_in[5];
    const float* inw  = (const float*)d_in[6];
    const float* inb  = (const float*)d_in[7];
    const float* opw  = (const float*)d_in[8];
    const float* opb  = (const float*)d_in[9];
    const float* l1w  = (const float*)d_in[10];
    const float* l1b  = (const float*)d_in[11];
    const float* l2w  = (const float*)d_in[12];
    const float* l2b  = (const float*)d_in[13];
    const float* ln1g = (const float*)d_in[14];
    const float* ln1b = (const float*)d_in[15];
    const float* ln2g = (const float*)d_in[16];
    const float* ln2b = (const float*)d_in[17];
    const float* c1w  = (const float*)d_in[18];
    const float* c1b  = (const float*)d_in[19];
    const float* bn1g = (const float*)d_in[20];
    const float* bn1b = (const float*)d_in[21];
    const float* c2w  = (const float*)d_in[22];
    const float* c2b  = (const float*)d_in[23];
    const float* bn2g = (const float*)d_in[24];
    const float* bn2b = (const float*)d_in[25];
    const float* fcw  = (const float*)d_in[26];
    const float* fcb  = (const float*)d_in[27];
    float* out = (float*)d_out;

    float *x0,*qkv,*att,*tmp,*x1,*ff1,*x2,*col,*y1,*p1,*y2,*z,*stats;
    cudaGetSymbolAddress((void**)&x0,   g_x0);
    cudaGetSymbolAddress((void**)&qkv,  g_qkv);
    cudaGetSymbolAddress((void**)&att,  g_att);
    cudaGetSymbolAddress((void**)&tmp,  g_tmp);
    cudaGetSymbolAddress((void**)&x1,   g_x1);
    cudaGetSymbolAddress((void**)&ff1,  g_ff1);
    cudaGetSymbolAddress((void**)&x2,   g_x2);
    cudaGetSymbolAddress((void**)&col,  g_col);
    cudaGetSymbolAddress((void**)&y1,   g_y1);
    cudaGetSymbolAddress((void**)&p1,   g_p1);
    cudaGetSymbolAddress((void**)&y2,   g_y2);
    cudaGetSymbolAddress((void**)&z,    g_z);
    cudaGetSymbolAddress((void**)&stats,g_stats);

    // 1) embedding + concat
    embed_kernel<<<BL, 128>>>(X, sa, ptm, emb, pemb, x0);

    // 2) qkv projection [BL,384]
    gemm_kernel<<<dim3(384/64, BL/64), 256>>>(x0, inw, inb, qkv, BL, 3*DM, DM, 0);

    // 3) attention -> att [BL,128]
    attn_kernel<<<dim3(LSEQ/128, HH, BB), 128>>>(qkv, rpe, att);

    // 4) out projection
    gemm_kernel<<<dim3(DM/64, BL/64), 256>>>(att, opw, opb, tmp, BL, DM, DM, 0);

    // 5) x1 = LN(x0 + attn_out)
    add_ln_kernel<<<BL, 128>>>(x0, tmp, ln1g, ln1b, x1);

    // 6) FF
    gemm_kernel<<<dim3(FFD/64, BL/64), 256>>>(x1, l1w, l1b, ff1, BL, FFD, DM, 1);
    gemm_kernel<<<dim3(DM/64,  BL/64), 256>>>(ff1, l2w, l2b, tmp, BL, DM, FFD, 0);

    // 7) x2 = LN(x1 + ff)
    add_ln_kernel<<<BL, 128>>>(x1, tmp, ln2g, ln2b, x2);

    // 8) conv1 via im2col + GEMM
    im2col1_kernel<<<(int)(((long long)BL*640 + 255)/256), 256>>>(x2, col);
    gemm_kernel<<<dim3(C1/64, BL/64), 256>>>(col, c1w, c1b, y1, BL, C1, DM*KK, 0);

    // 9) BN1 stats
    zero_kernel<<<3, 256>>>(stats, 2*C1 + 2*C2);
    bnstats_kernel<<<128, C1>>>(y1, BL, C1, 256, stats, stats + C1);

    // 10) BN1 + ReLU + maxpool2 -> p1 [B*1024, 128]
    bnpool_kernel<<<BB*L2HALF, C1>>>(y1, stats, stats + C1, bn1g, bn1b, p1);

    // 11) conv2 via im2col + GEMM -> y2 [16320, 256]
    im2col2_kernel<<<(int)(((long long)M2*640 + 255)/256), 256>>>(p1, col);
    gemm_kernel<<<dim3(C2/64, (M2+63)/64), 256>>>(col, c2w, c2b, y2, M2, C2, C1*KK, 0);

    // 12) BN2 stats
    bnstats_kernel<<<128, C2>>>(y2, M2, C2, 128, stats + 2*C1, stats + 2*C1 + C2);

    // 13) BN2 + ReLU + global max -> z [16,256]
    gmax_kernel<<<BB, C2>>>(y2, stats + 2*C1, stats + 2*C1 + C2, bn2g, bn2b, z);

    // 14) fc -> out [16,2]
    fc_kernel<<<dim3(BB, 2), 256>>>(z, fcw, fcb, out);
}

// round 2
// speedup vs baseline: 2.5335x; 2.5335x over previous
#include <cuda_runtime.h>
#include <math.h>

// ---------------- problem constants ----------------
#define BB    16
#define LSEQ  2048
#define BL    (BB*LSEQ)        // 32768
#define DM    128
#define HH    4
#define HDIM  32
#define FFD   256
#define C1    128
#define C2    256
#define KK    5
#define L2HALF 1024
#define L2OUT  1020
#define M2    (BB*L2OUT)       // 16320
#define EPSV  1e-5f
#define SCALE 0.17677669529663687f

// ---------------- scratch ----------------
__device__ float g_x0 [BL*DM];
__device__ float g_qkv[BL*3*DM];
__device__ float g_att[BL*DM];
__device__ float g_tmp[BL*DM];
__device__ float g_x1 [BL*DM];
__device__ float g_ff1[BL*FFD];
__device__ float g_x2 [BL*DM];
__device__ float g_col[BL*640];
__device__ float g_y1 [BL*C1];
__device__ float g_p1 [BB*L2HALF*C1];
__device__ float g_y2 [M2*C2];
__device__ float g_z  [BB*C2];
__device__ float g_stats[2*C1 + 2*C2];

__device__ __forceinline__ unsigned f2tf(float f) {
    unsigned r; asm("cvt.rna.tf32.f32 %0, %1;" : "=r"(r) : "f"(f)); return r;
}

#define MMA_TF32(C, a0,a1,a2,a3, b0,b1) \
    asm volatile("mma.sync.aligned.m16n8k8.row.col.f32.tf32.tf32.f32 " \
                 "{%0,%1,%2,%3},{%4,%5,%6,%7},{%8,%9},{%0,%1,%2,%3};" \
                 : "+f"((C)[0]),"+f"((C)[1]),"+f"((C)[2]),"+f"((C)[3]) \
                 : "r"(a0),"r"(a1),"r"(a2),"r"(a3),"r"(b0),"r"(b1))

// ---------------- embed ----------------
__global__ void embed_kernel(const int* __restrict__ X, const float* __restrict__ sa,
                             const int* __restrict__ ptm,
                             const float* __restrict__ emb, const float* __restrict__ pemb,
                             float* __restrict__ x0)
{
    int row = blockIdx.x;
    int t = threadIdx.x;
    float v;
    if (t < 120) v = emb[X[row]*120 + t] * sa[row];
    else         v = pemb[ptm[row]*8 + (t-120)];
    x0[(size_t)row*DM + t] = v;
}

// ---------------- tf32 tensor-core GEMM: C[M,N] = A[M,K] @ W[N,K]^T + bias (+relu) ----------------
// block 256 threads (8 warps), tile 128(M) x 64(N), K-chunk 32. N%64==0, K%32==0.
__global__ __launch_bounds__(256) void gemm_tf32(const float* __restrict__ A,
                                                 const float* __restrict__ W,
                                                 const float* __restrict__ bias,
                                                 float* __restrict__ C,
                                                 int M, int N, int K, int relu)
{
    __shared__ unsigned As[128][36];
    __shared__ unsigned Bs[64][36];
    int tid = threadIdx.x;
    int w = tid >> 5, lane = tid & 31, g = lane >> 2, tg = lane & 3;
    int wm = w & 3, wn = w >> 2;
    int row0 = blockIdx.y * 128, col0 = blockIdx.x * 64;

    float c[2][4][4];
    #pragma unroll
    for (int mt=0; mt<2; ++mt)
        #pragma unroll
        for (int nt=0; nt<4; ++nt)
            #pragma unroll
            for (int i=0;i<4;++i) c[mt][nt][i]=0.f;

    for (int k0 = 0; k0 < K; k0 += 32) {
        __syncthreads();
        #pragma unroll
        for (int i = 0; i < 4; ++i) {
            int fidx = i*256 + tid; int r = fidx >> 3, f4 = fidx & 7;
            float4 v;
            if (row0 + r < M) v = *(const float4*)(A + (size_t)(row0+r)*K + k0 + f4*4);
            else              v = make_float4(0.f,0.f,0.f,0.f);
            uint4 t4; t4.x=f2tf(v.x); t4.y=f2tf(v.y); t4.z=f2tf(v.z); t4.w=f2tf(v.w);
            *(uint4*)&As[r][f4*4] = t4;
        }
        #pragma unroll
        for (int i = 0; i < 2; ++i) {
            int fidx = i*256 + tid; int n = fidx >> 3, f4 = fidx & 7;
            float4 v = *(const float4*)(W + (size_t)(col0+n)*K + k0 + f4*4);
            uint4 t4; t4.x=f2tf(v.x); t4.y=f2tf(v.y); t4.z=f2tf(v.z); t4.w=f2tf(v.w);
            *(uint4*)&Bs[n][f4*4] = t4;
        }
        __syncthreads();
        #pragma unroll
        for (int kc = 0; kc < 4; ++kc) {
            int kk = kc*8;
            unsigned a[2][4];
            #pragma unroll
            for (int mt = 0; mt < 2; ++mt) {
                int mr = wm*32 + mt*16;
                a[mt][0] = As[mr+g  ][kk+tg];
                a[mt][1] = As[mr+g+8][kk+tg];
                a[mt][2] = As[mr+g  ][kk+tg+4];
                a[mt][3] = As[mr+g+8][kk+tg+4];
            }
            #pragma unroll
            for (int nt = 0; nt < 4; ++nt) {
                int nr = wn*32 + nt*8;
                unsigned b0 = Bs[nr+g][kk+tg], b1 = Bs[nr+g][kk+tg+4];
                MMA_TF32(c[0][nt], a[0][0],a[0][1],a[0][2],a[0][3], b0,b1);
                MMA_TF32(c[1][nt], a[1][0],a[1][1],a[1][2],a[1][3], b0,b1);
            }
        }
    }

    #pragma unroll
    for (int mt = 0; mt < 2; ++mt) {
        int r0 = row0 + wm*32 + mt*16 + g;
        #pragma unroll
        for (int nt = 0; nt < 4; ++nt) {
            int cc = col0 + wn*32 + nt*8 + 2*tg;
            float b0v = bias[cc], b1v = bias[cc+1];
            float v0 = c[mt][nt][0] + b0v, v1 = c[mt][nt][1] + b1v;
            float v2 = c[mt][nt][2] + b0v, v3 = c[mt][nt][3] + b1v;
            if (relu) { v0=fmaxf(v0,0.f); v1=fmaxf(v1,0.f); v2=fmaxf(v2,0.f); v3=fmaxf(v3,0.f); }
            if (r0 < M)     { float2 s={v0,v1}; *(float2*)(C + (size_t)r0*N + cc) = s; }
            if (r0 + 8 < M) { float2 s={v2,v3}; *(float2*)(C + (size_t)(r0+8)*N + cc) = s; }
        }
    }
}

// ---------------- tf32 flash attention with relative-position bias ----------------
// grid (L/64, H, B), block 128 (4 warps); each warp owns 16 query rows.
__global__ __launch_bounds__(128) void attn_tf32(const float* __restrict__ qkv,
                                                 const float* __restrict__ rpe,
                                                 float* __restrict__ o)
{
    __shared__ unsigned Ks[64][36];   // [j][d]
    __shared__ unsigned Vt[32][68];   // [d][j] (transposed)
    __shared__ unsigned Ps[64][68];   // [qrow][j] tf32 probabilities
    __shared__ float rs[65];

    int tid = threadIdx.x;
    int w = tid >> 5, lane = tid & 31, g = lane >> 2, tg = lane & 3;
    int b = blockIdx.z, h = blockIdx.y;
    int q0 = blockIdx.x * 64;
    if (tid < 65) rs[tid] = rpe[tid*HH + h];

    // Q fragments (persistent): rows q0 + w*16 + {g, g+8}, cols kc*8 + {tg, tg+4}
    unsigned aq[4][4];
    {
        const float* qbase = qkv + ((size_t)(b*LSEQ))*384 + h*HDIM;
        int r0 = q0 + w*16 + g, r1 = r0 + 8;
        #pragma unroll
        for (int kc = 0; kc < 4; ++kc) {
            int k = kc*8;
            aq[kc][0] = f2tf(__ldg(qbase + (size_t)r0*384 + k + tg));
            aq[kc][1] = f2tf(__ldg(qbase + (size_t)r1*384 + k + tg));
            aq[kc][2] = f2tf(__ldg(qbase + (size_t)r0*384 + k + tg + 4));
            aq[kc][3] = f2tf(__ldg(qbase + (size_t)r1*384 + k + tg + 4));
        }
    }

    float co[4][4];
    #pragma unroll
    for (int nt=0;nt<4;++nt)
        #pragma unroll
        for (int i=0;i<4;++i) co[nt][i]=0.f;
    float sum0 = 0.f, sum1 = 0.f;
    int r0 = q0 + w*16 + g, r1 = r0 + 8;

    for (int j0 = 0; j0 < LSEQ; j0 += 64) {
        __syncthreads();
        // stage K and V (convert to tf32)
        #pragma unroll
        for (int i = 0; i < 4; ++i) {
            int fidx = i*128 + tid; int jr = fidx >> 3, f4 = fidx & 7;
            const float* rowp = qkv + ((size_t)(b*LSEQ + j0 + jr))*384 + h*HDIM;
            float4 kv = *(const float4*)(rowp + 128 + f4*4);
            uint4 t4; t4.x=f2tf(kv.x); t4.y=f2tf(kv.y); t4.z=f2tf(kv.z); t4.w=f2tf(kv.w);
            *(uint4*)&Ks[jr][f4*4] = t4;
            float4 vv = *(const float4*)(rowp + 256 + f4*4);
            Vt[f4*4+0][jr] = f2tf(vv.x);
            Vt[f4*4+1][jr] = f2tf(vv.y);
            Vt[f4*4+2][jr] = f2tf(vv.z);
            Vt[f4*4+3][jr] = f2tf(vv.w);
        }
        __syncthreads();

        // S = Q @ K^T  (per warp: 16 x 64)
        float cs[8][4];
        #pragma unroll
        for (int nt=0;nt<8;++nt)
            #pragma unroll
            for (int i=0;i<4;++i) cs[nt][i]=0.f;
        #pragma unroll
        for (int kc = 0; kc < 4; ++kc) {
            int kk = kc*8;
            #pragma unroll
            for (int nt = 0; nt < 8; ++nt) {
                unsigned b0 = Ks[nt*8+g][kk+tg], b1 = Ks[nt*8+g][kk+tg+4];
                MMA_TF32(cs[nt], aq[kc][0],aq[kc][1],aq[kc][2],aq[kc][3], b0,b1);
            }
        }

        // softmax (scores are tiny; no max-rescale, defensive clamp) + write P tiles
        #pragma unroll
        for (int nt = 0; nt < 8; ++nt) {
            int j = j0 + nt*8 + 2*tg;
            int d00 = j   - r0; d00 = d00 < -32 ? -32 : (d00 > 32 ? 32 : d00);
            int d01 = j+1 - r0; d01 = d01 < -32 ? -32 : (d01 > 32 ? 32 : d01);
            int d10 = j   - r1; d10 = d10 < -32 ? -32 : (d10 > 32 ? 32 : d10);
            int d11 = j+1 - r1; d11 = d11 < -32 ? -32 : (d11 > 32 ? 32 : d11);
            float s0 = fminf(cs[nt][0]*SCALE + rs[d00+32], 60.f);
            float s1 = fminf(cs[nt][1]*SCALE + rs[d01+32], 60.f);
            float s2 = fminf(cs[nt][2]*SCALE + rs[d10+32], 60.f);
            float s3 = fminf(cs[nt][3]*SCALE + rs[d11+32], 60.f);
            float p0 = __expf(s0), p1 = __expf(s1), p2 = __expf(s2), p3 = __expf(s3);
            sum0 += p0 + p1;
            sum1 += p2 + p3;
            uint2 u0; u0.x = f2tf(p0); u0.y = f2tf(p1);
            uint2 u1; u1.x = f2tf(p2); u1.y = f2tf(p3);
            *(uint2*)&Ps[w*16+g  ][nt*8+2*tg] = u0;
            *(uint2*)&Ps[w*16+g+8][nt*8+2*tg] = u1;
        }
        __syncwarp();

        // O += P @ V  (per warp: 16 x 32, k = 64)
        #pragma unroll
        for (int kc2 = 0; kc2 < 8; ++kc2) {
            int kk = kc2*8;
            unsigned a0 = Ps[w*16+g  ][kk+tg];
            unsigned a1 = Ps[w*16+g+8][kk+tg];
            unsigned a2 = Ps[w*16+g  ][kk+tg+4];
            unsigned a3 = Ps[w*16+g+8][kk+tg+4];
            #pragma unroll
            for (int nt2 = 0; nt2 < 4; ++nt2) {
                unsigned b0 = Vt[nt2*8+g][kk+tg], b1 = Vt[nt2*8+g][kk+tg+4];
                MMA_TF32(co[nt2], a0,a1,a2,a3, b0,b1);
            }
        }
    }

    // reduce row sums across the 4 lanes sharing each row
    sum0 += __shfl_xor_sync(0xffffffffu, sum0, 1);
    sum0 += __shfl_xor_sync(0xffffffffu, sum0, 2);
    sum1 += __shfl_xor_sync(0xffffffffu, sum1, 1);
    sum1 += __shfl_xor_sync(0xffffffffu, sum1, 2);
    float inv0 = 1.f / sum0, inv1 = 1.f / sum1;

    #pragma unroll
    for (int nt2 = 0; nt2 < 4; ++nt2) {
        int d = nt2*8 + 2*tg;
        float2 s0; s0.x = co[nt2][0]*inv0; s0.y = co[nt2][1]*inv0;
        float2 s1; s1.x = co[nt2][2]*inv1; s1.y = co[nt2][3]*inv1;
        *(float2*)(o + ((size_t)(b*LSEQ + r0))*DM + h*HDIM + d) = s0;
        *(float2*)(o + ((size_t)(b*LSEQ + r1))*DM + h*HDIM + d) = s1;
    }
}

// ---------------- residual add + layernorm ----------------
__global__ void add_ln_kernel(const float* __restrict__ a, const float* __restrict__ bres,
                              const float* __restrict__ g, const float* __restrict__ beta,
                              float* __restrict__ out)
{
    int row = blockIdx.x;
    int t = threadIdx.x;
    float v = a[(size_t)row*DM + t] + bres[(size_t)row*DM + t];
    float s = v, s2 = v*v;
    #pragma unroll
    for (int off = 16; off; off >>= 1) {
        s  += __shfl_xor_sync(0xffffffffu, s,  off);
        s2 += __shfl_xor_sync(0xffffffffu, s2, off);
    }
    __shared__ float ws[4], ws2[4];
    int w = t >> 5;
    if ((t & 31) == 0) { ws[w] = s; ws2[w] = s2; }
    __syncthreads();
    s  = ws[0]+ws[1]+ws[2]+ws[3];
    s2 = ws2[0]+ws2[1]+ws2[2]+ws2[3];
    float mean = s * (1.f/128.f);
    float var  = s2 * (1.f/128.f) - mean*mean;
    float f = rsqrtf(var + EPSV);
    out[(size_t)row*DM + t] = (v - mean)*f*g[t] + beta[t];
}

// ---------------- im2col conv1 (pad=2) ----------------
__global__ void im2col1_kernel(const float* __restrict__ x2, float* __restrict__ col)
{
    long long e = (long long)blockIdx.x*256 + threadIdx.x;
    if (e >= (long long)BL*640) return;
    int c = (int)(e % 640); int row = (int)(e / 640);
    int ci = c/5, k = c%5;
    int b = row >> 11, l = row & 2047;
    int lx = l + k - 2;
    float v = (lx >= 0 && lx < LSEQ) ? x2[((size_t)(b*LSEQ + lx))*DM + ci] : 0.f;
    col[e] = v;
}

// ---------------- im2col conv2 (valid) ----------------
__global__ void im2col2_kernel(const float* __restrict__ p1, float* __restrict__ col)
{
    long long e = (long long)blockIdx.x*256 + threadIdx.x;
    if (e >= (long long)M2*640) return;
    int c = (int)(e % 640); int row = (int)(e / 640);
    int c1 = c/5, k = c%5;
    int b = row / L2OUT, l = row % L2OUT;
    col[e] = p1[((size_t)(b*L2HALF + l + k))*C1 + c1];
}

// ---------------- BN stats ----------------
__global__ void bnstats_kernel(const float* __restrict__ y, int rows, int Cc, int rpb,
                               float* __restrict__ sum, float* __restrict__ sumsq)
{
    int c = threadIdx.x;
    int r0 = blockIdx.x * rpb;
    int r1 = r0 + rpb; if (r1 > rows) r1 = rows;
    float s = 0.f, s2 = 0.f;
    for (int r = r0; r < r1; ++r) {
        float v = y[(size_t)r*Cc + c];
        s += v; s2 += v*v;
    }
    atomicAdd(&sum[c], s);
    atomicAdd(&sumsq[c], s2);
}

__global__ void zero_kernel(float* p, int n)
{
    int i = blockIdx.x*256 + threadIdx.x;
    if (i < n) p[i] = 0.f;
}

// ---------------- BN + ReLU + maxpool(2) ----------------
__global__ void bnpool_kernel(const float* __restrict__ y1,
                              const float* __restrict__ sum, const float* __restrict__ sq,
                              const float* __restrict__ g, const float* __restrict__ bb,
                              float* __restrict__ p1)
{
    int c = threadIdx.x;
    int row2 = blockIdx.x;
    int b = row2 >> 10, l2 = row2 & 1023;
    float mean = sum[c]*(1.f/(float)BL);
    float var  = sq[c]*(1.f/(float)BL) - mean*mean;
    float f = rsqrtf(var + EPSV)*g[c];
    float v0 = (y1[((size_t)(b*LSEQ + 2*l2  ))*C1 + c] - mean)*f + bb[c];
    float v1 = (y1[((size_t)(b*LSEQ + 2*l2+1))*C1 + c] - mean)*f + bb[c];
    v0 = fmaxf(v0, 0.f); v1 = fmaxf(v1, 0.f);
    p1[(size_t)row2*C1 + c] = fmaxf(v0, v1);
}

// ---------------- BN + ReLU + global max ----------------
__global__ void gmax_kernel(const float* __restrict__ y2,
                            const float* __restrict__ sum, const float* __restrict__ sq,
                            const float* __restrict__ g, const float* __restrict__ bb,
                            float* __restrict__ z)
{
    int c = threadIdx.x;
    int b = blockIdx.x;
    float mean = sum[c]*(1.f/(float)M2);
    float var  = sq[c]*(1.f/(float)M2) - mean*mean;
    float f = rsqrtf(var + EPSV)*g[c];
    float vm = 0.f;
    for (int l = 0; l < L2OUT; ++l) {
        float v = (y2[((size_t)(b*L2OUT + l))*C2 + c] - mean)*f + bb[c];
        v = fmaxf(v, 0.f);
        vm = fmaxf(vm, v);
    }
    z[b*C2 + c] = vm;
}

// ---------------- final fc ----------------
__global__ void fc_kernel(const float* __restrict__ z, const float* __restrict__ w,
                          const float* __restrict__ bias, float* __restrict__ out)
{
    int b = blockIdx.x, n = blockIdx.y;
    int t = threadIdx.x;
    float p = z[b*C2 + t] * w[n*C2 + t];
    #pragma unroll
    for (int off = 16; off; off >>= 1) p += __shfl_xor_sync(0xffffffffu, p, off);
    __shared__ float ws[8];
    if ((t & 31) == 0) ws[t >> 5] = p;
    __syncthreads();
    if (t == 0) {
        float s = 0.f;
        #pragma unroll
        for (int i = 0; i < 8; ++i) s += ws[i];
        out[b*2 + n] = s + bias[n];
    }
}

// ---------------- launch ----------------
extern "C" void kernel_launch(void* const* d_in, const int* in_sizes, int n_in,
                              void* d_out, int out_size)
{
    const int*   X    = (const int*)  d_in[0];
    const float* sa   = (const float*)d_in[1];
    const int*   ptm  = (const int*)  d_in[2];
    const float* emb  = (const float*)d_in[3];
    const float* pemb = (const float*)d_in[4];
    const float* rpe  = (const float*)d_in[5];
    const float* inw  = (const float*)d_in[6];
    const float* inb  = (const float*)d_in[7];
    const float* opw  = (const float*)d_in[8];
    const float* opb  = (const float*)d_in[9];
    const float* l1w  = (const float*)d_in[10];
    const float* l1b  = (const float*)d_in[11];
    const float* l2w  = (const float*)d_in[12];
    const float* l2b  = (const float*)d_in[13];
    const float* ln1g = (const float*)d_in[14];
    const float* ln1b = (const float*)d_in[15];
    const float* ln2g = (const float*)d_in[16];
    const float* ln2b = (const float*)d_in[17];
    const float* c1w  = (const float*)d_in[18];
    const float* c1b  = (const float*)d_in[19];
    const float* bn1g = (const float*)d_in[20];
    const float* bn1b = (const float*)d_in[21];
    const float* c2w  = (const float*)d_in[22];
    const float* c2b  = (const float*)d_in[23];
    const float* bn2g = (const float*)d_in[24];
    const float* bn2b = (const float*)d_in[25];
    const float* fcw  = (const float*)d_in[26];
    const float* fcb  = (const float*)d_in[27];
    float* out = (float*)d_out;

    float *x0,*qkv,*att,*tmp,*x1,*ff1,*x2,*col,*y1,*p1,*y2,*z,*stats;
    cudaGetSymbolAddress((void**)&x0,   g_x0);
    cudaGetSymbolAddress((void**)&qkv,  g_qkv);
    cudaGetSymbolAddress((void**)&att,  g_att);
    cudaGetSymbolAddress((void**)&tmp,  g_tmp);
    cudaGetSymbolAddress((void**)&x1,   g_x1);
    cudaGetSymbolAddress((void**)&ff1,  g_ff1);
    cudaGetSymbolAddress((void**)&x2,   g_x2);
    cudaGetSymbolAddress((void**)&col,  g_col);
    cudaGetSymbolAddress((void**)&y1,   g_y1);
    cudaGetSymbolAddress((void**)&p1,   g_p1);
    cudaGetSymbolAddress((void**)&y2,   g_y2);
    cudaGetSymbolAddress((void**)&z,    g_z);
    cudaGetSymbolAddress((void**)&stats,g_stats);

    // 1) embedding + concat
    embed_kernel<<<BL, 128>>>(X, sa, ptm, emb, pemb, x0);

    // 2) qkv projection [BL,384]
    gemm_tf32<<<dim3(384/64, BL/128), 256>>>(x0, inw, inb, qkv, BL, 3*DM, DM, 0);

    // 3) attention
    attn_tf32<<<dim3(LSEQ/64, HH, BB), 128>>>(qkv, rpe, att);

    // 4) out projection
    gemm_tf32<<<dim3(DM/64, BL/128), 256>>>(att, opw, opb, tmp, BL, DM, DM, 0);

    // 5) x1 = LN(x0 + attn_out)
    add_ln_kernel<<<BL, 128>>>(x0, tmp, ln1g, ln1b, x1);

    // 6) FF
    gemm_tf32<<<dim3(FFD/64, BL/128), 256>>>(x1, l1w, l1b, ff1, BL, FFD, DM, 1);
    gemm_tf32<<<dim3(DM/64,  BL/128), 256>>>(ff1, l2w, l2b, tmp, BL, DM, FFD, 0);

    // 7) x2 = LN(x1 + ff)
    add_ln_kernel<<<BL, 128>>>(x1, tmp, ln2g, ln2b, x2);

    // 8) conv1 via im2col + GEMM
    im2col1_kernel<<<(int)(((long long)BL*640 + 255)/256), 256>>>(x2, col);
    gemm_tf32<<<dim3(C1/64, BL/128), 256>>>(col, c1w, c1b, y1, BL, C1, DM*KK, 0);

    // 9) BN1 stats
    zero_kernel<<<3, 256>>>(stats, 2*C1 + 2*C2);
    bnstats_kernel<<<128, C1>>>(y1, BL, C1, 256, stats, stats + C1);

    // 10) BN1 + ReLU + maxpool2
    bnpool_kernel<<<BB*L2HALF, C1>>>(y1, stats, stats + C1, bn1g, bn1b, p1);

    // 11) conv2 via im2col + GEMM
    im2col2_kernel<<<(int)(((long long)M2*640 + 255)/256), 256>>>(p1, col);
    gemm_tf32<<<dim3(C2/64, (M2+127)/128), 256>>>(col, c2w, c2b, y2, M2, C2, C1*KK, 0);

    // 12) BN2 stats
    bnstats_kernel<<<128, C2>>>(y2, M2, C2, 128, stats + 2*C1, stats + 2*C1 + C2);

    // 13) BN2 + ReLU + global max
    gmax_kernel<<<BB, C2>>>(y2, stats + 2*C1, stats + 2*C1 + C2, bn2g, bn2b, z);

    // 14) fc
    fc_kernel<<<dim3(BB, 2), 256>>>(z, fcw, fcb, out);
}

// round 3
// speedup vs baseline: 3.1132x; 1.2288x over previous
#include <cuda_runtime.h>
#include <math.h>

// ---------------- problem constants ----------------
#define BB    16
#define LSEQ  2048
#define BL    (BB*LSEQ)        // 32768
#define DM    128
#define HH    4
#define HDIM  32
#define FFD   256
#define C1    128
#define C2    256
#define KK    5
#define L2HALF 1024
#define L2OUT  1020
#define M2    (BB*L2OUT)       // 16320
#define EPSV  1e-5f
#define SCALE 0.17677669529663687f

// ---------------- scratch ----------------
__device__ float g_x0 [BL*DM];
__device__ float g_qkv[BL*3*DM];
__device__ float g_att[BL*DM];
__device__ float g_tmp[BL*DM];
__device__ float g_x1 [BL*DM];
__device__ float g_ff1[BL*FFD];
__device__ float g_x2 [BL*DM];
__device__ float g_col[BL*640];
__device__ float g_y1 [BL*C1];
__device__ float g_p1 [BB*L2HALF*C1];
__device__ float g_y2 [M2*C2];
__device__ float g_z  [BB*C2];
__device__ float g_stats[2*C1 + 2*C2];

// ---------------- helpers ----------------
__device__ __forceinline__ unsigned sptr(const void* p) {
    return (unsigned)__cvta_generic_to_shared(p);
}
#define CP16(dst, src) asm volatile("cp.async.cg.shared.global [%0], [%1], 16;" :: "r"(dst), "l"(src))
#define CP_COMMIT()    asm volatile("cp.async.commit_group;")
#define CP_WAIT1()     asm volatile("cp.async.wait_group 1;")
#define CP_WAIT0()     asm volatile("cp.async.wait_group 0;")

#define MMA_TF32(C, a0,a1,a2,a3, b0,b1) \
    asm volatile("mma.sync.aligned.m16n8k8.row.col.f32.tf32.tf32.f32 " \
                 "{%0,%1,%2,%3},{%4,%5,%6,%7},{%8,%9},{%0,%1,%2,%3};" \
                 : "+f"((C)[0]),"+f"((C)[1]),"+f"((C)[2]),"+f"((C)[3]) \
                 : "r"(a0),"r"(a1),"r"(a2),"r"(a3),"r"(b0),"r"(b1))

// ---------------- embed ----------------
__global__ void embed_kernel(const int* __restrict__ X, const float* __restrict__ sa,
                             const int* __restrict__ ptm,
                             const float* __restrict__ emb, const float* __restrict__ pemb,
                             float* __restrict__ x0)
{
    int row = blockIdx.x;
    int t = threadIdx.x;
    float v;
    if (t < 120) v = emb[X[row]*120 + t] * sa[row];
    else         v = pemb[ptm[row]*8 + (t-120)];
    x0[(size_t)row*DM + t] = v;
}

// ---------------- tf32 GEMM, cp.async double-buffered ----------------
// C[M,N] = A[M,K] @ W[N,K]^T + bias (+relu). tile 128x64, K-chunk 32, 256 thr.
// N%64==0, K%32==0; M arbitrary (row loads clamped, stores masked).
__global__ __launch_bounds__(256) void gemm_tf32(const float* __restrict__ A,
                                                 const float* __restrict__ W,
                                                 const float* __restrict__ bias,
                                                 float* __restrict__ C,
                                                 int M, int N, int K, int relu)
{
    __shared__ __align__(16) unsigned As[2][128][36];
    __shared__ __align__(16) unsigned Bs[2][64][36];
    int tid = threadIdx.x;
    int w = tid >> 5, lane = tid & 31, g = lane >> 2, tg = lane & 3;
    int wm = w & 3, wn = w >> 2;
    int row0 = blockIdx.y * 128, col0 = blockIdx.x * 64;

    // precomputed loader coordinates
    int lr = tid >> 3, lc4 = (tid & 7) * 4;       // A/B row, col within 32-k chunk
    int ar0 = row0 + lr;        if (ar0 > M-1) ar0 = M-1;
    int ar1 = row0 + lr + 32;   if (ar1 > M-1) ar1 = M-1;
    int ar2 = row0 + lr + 64;   if (ar2 > M-1) ar2 = M-1;
    int ar3 = row0 + lr + 96;   if (ar3 > M-1) ar3 = M-1;
    const float* wp0 = W + (size_t)(col0 + lr)*K + lc4;
    const float* wp1 = W + (size_t)(col0 + lr + 32)*K + lc4;

    float c[2][4][4];
    #pragma unroll
    for (int mt=0; mt<2; ++mt)
        #pragma unroll
        for (int nt=0; nt<4; ++nt)
            #pragma unroll
            for (int i=0;i<4;++i) c[mt][nt][i]=0.f;

    int kt = K >> 5;

    // ---- stage loader ----
    #define GLOAD(s, k0) do { \
        CP16(sptr(&As[s][lr     ][lc4]), A + (size_t)ar0*K + (k0) + lc4); \
        CP16(sptr(&As[s][lr + 32][lc4]), A + (size_t)ar1*K + (k0) + lc4); \
        CP16(sptr(&As[s][lr + 64][lc4]), A + (size_t)ar2*K + (k0) + lc4); \
        CP16(sptr(&As[s][lr + 96][lc4]), A + (size_t)ar3*K + (k0) + lc4); \
        CP16(sptr(&Bs[s][lr     ][lc4]), wp0 + (k0)); \
        CP16(sptr(&Bs[s][lr + 32][lc4]), wp1 + (k0)); \
        CP_COMMIT(); \
    } while (0)

    GLOAD(0, 0);

    for (int t = 0; t < kt; ++t) {
        int s = t & 1;
        if (t + 1 < kt) { GLOAD(s^1, (t+1) << 5); CP_WAIT1(); }
        else            { CP_WAIT0(); }
        __syncthreads();

        #pragma unroll
        for (int kc = 0; kc < 4; ++kc) {
            int kk = kc*8;
            unsigned a[2][4];
            #pragma unroll
            for (int mt = 0; mt < 2; ++mt) {
                int mr = wm*32 + mt*16;
                a[mt][0] = As[s][mr+g  ][kk+tg];
                a[mt][1] = As[s][mr+g+8][kk+tg];
                a[mt][2] = As[s][mr+g  ][kk+tg+4];
                a[mt][3] = As[s][mr+g+8][kk+tg+4];
            }
            #pragma unroll
            for (int nt = 0; nt < 4; ++nt) {
                int nr = wn*32 + nt*8;
                unsigned b0 = Bs[s][nr+g][kk+tg], b1 = Bs[s][nr+g][kk+tg+4];
                MMA_TF32(c[0][nt], a[0][0],a[0][1],a[0][2],a[0][3], b0,b1);
                MMA_TF32(c[1][nt], a[1][0],a[1][1],a[1][2],a[1][3], b0,b1);
            }
        }
        __syncthreads();
    }
    #undef GLOAD

    #pragma unroll
    for (int mt = 0; mt < 2; ++mt) {
        int r0 = row0 + wm*32 + mt*16 + g;
        #pragma unroll
        for (int nt = 0; nt < 4; ++nt) {
            int cc = col0 + wn*32 + nt*8 + 2*tg;
            float b0v = bias[cc], b1v = bias[cc+1];
            float v0 = c[mt][nt][0] + b0v, v1 = c[mt][nt][1] + b1v;
            float v2 = c[mt][nt][2] + b0v, v3 = c[mt][nt][3] + b1v;
            if (relu) { v0=fmaxf(v0,0.f); v1=fmaxf(v1,0.f); v2=fmaxf(v2,0.f); v3=fmaxf(v3,0.f); }
            if (r0 < M)     { float2 s2={v0,v1}; *(float2*)(C + (size_t)r0*N + cc) = s2; }
            if (r0 + 8 < M) { float2 s2={v2,v3}; *(float2*)(C + (size_t)(r0+8)*N + cc) = s2; }
        }
    }
}

// ---------------- tf32 flash attention with RPE bias ----------------
// grid (L/128, H, B), block 256 (8 warps); each warp owns 16 query rows.
__global__ __launch_bounds__(256) void attn_tf32(const float* __restrict__ qkv,
                                                 const float* __restrict__ rpe,
                                                 float* __restrict__ o)
{
    __shared__ __align__(16) unsigned Ks[64][36];   // [j][d]
    __shared__ unsigned Vt[32][68];                 // [d][j]
    __shared__ unsigned Ps[128][68];                // [qrow][j]
    __shared__ float rs[65];

    int tid = threadIdx.x;
    int w = tid >> 5, lane = tid & 31, g = lane >> 2, tg = lane & 3;
    int b = blockIdx.z, h = blockIdx.y;
    int q0 = blockIdx.x * 128;
    if (tid < 65) rs[tid] = rpe[tid*HH + h];

    int r0 = q0 + w*16 + g, r1 = r0 + 8;

    // persistent Q fragments (raw f32 bits -> tf32 truncation)
    unsigned aq[4][4];
    {
        const float* qb = qkv + (size_t)(b*LSEQ)*384 + h*HDIM;
        #pragma unroll
        for (int kc = 0; kc < 4; ++kc) {
            int k = kc*8;
            aq[kc][0] = __float_as_uint(__ldg(qb + (size_t)r0*384 + k + tg));
            aq[kc][1] = __float_as_uint(__ldg(qb + (size_t)r1*384 + k + tg));
            aq[kc][2] = __float_as_uint(__ldg(qb + (size_t)r0*384 + k + tg + 4));
            aq[kc][3] = __float_as_uint(__ldg(qb + (size_t)r1*384 + k + tg + 4));
        }
    }

    float co[4][4];
    #pragma unroll
    for (int nt=0;nt<4;++nt)
        #pragma unroll
        for (int i=0;i<4;++i) co[nt][i]=0.f;
    float sum0 = 0.f, sum1 = 0.f;

    int sjr = tid >> 3, sc4 = (tid & 7) * 4;   // staging coords: 32 rows per 256-thread pass

    for (int j0 = 0; j0 < LSEQ; j0 += 64) {
        __syncthreads();
        // stage K via cp.async (raw f32)
        const float* kb = qkv + (size_t)(b*LSEQ + j0)*384 + h*HDIM + 128;
        CP16(sptr(&Ks[sjr   ][sc4]), kb + (size_t)sjr*384 + sc4);
        CP16(sptr(&Ks[sjr+32][sc4]), kb + (size_t)(sjr+32)*384 + sc4);
        CP_COMMIT();
        // stage V transposed (manual)
        const float* vb = kb + 128;
        {
            float4 v0 = *(const float4*)(vb + (size_t)sjr*384 + sc4);
            Vt[sc4+0][sjr] = __float_as_uint(v0.x);
            Vt[sc4+1][sjr] = __float_as_uint(v0.y);
            Vt[sc4+2][sjr] = __float_as_uint(v0.z);
            Vt[sc4+3][sjr] = __float_as_uint(v0.w);
            float4 v1 = *(const float4*)(vb + (size_t)(sjr+32)*384 + sc4);
            Vt[sc4+0][sjr+32] = __float_as_uint(v1.x);
            Vt[sc4+1][sjr+32] = __float_as_uint(v1.y);
            Vt[sc4+2][sjr+32] = __float_as_uint(v1.z);
            Vt[sc4+3][sjr+32] = __float_as_uint(v1.w);
        }
        CP_WAIT0();
        __syncthreads();

        // S = Q @ K^T in two 16x32 halves (saves accumulator registers)
        #pragma unroll
        for (int hf = 0; hf < 2; ++hf) {
            float cs[4][4];
            #pragma unroll
            for (int nt=0;nt<4;++nt)
                #pragma unroll
                for (int i=0;i<4;++i) cs[nt][i]=0.f;
            #pragma unroll
            for (int kc = 0; kc < 4; ++kc) {
                int kk = kc*8;
                #pragma unroll
                for (int nt = 0; nt < 4; ++nt) {
                    int nr = (hf*4 + nt)*8;
                    unsigned b0 = Ks[nr+g][kk+tg], b1 = Ks[nr+g][kk+tg+4];
                    MMA_TF32(cs[nt], aq[kc][0],aq[kc][1],aq[kc][2],aq[kc][3], b0,b1);
                }
            }
            // softmax (no max-rescale; clamp defensively) + write P
            #pragma unroll
            for (int nt = 0; nt < 4; ++nt) {
                int j = j0 + (hf*4+nt)*8 + 2*tg;
                int d00 = j   - r0; d00 = d00 < -32 ? -32 : (d00 > 32 ? 32 : d00);
                int d01 = j+1 - r0; d01 = d01 < -32 ? -32 : (d01 > 32 ? 32 : d01);
                int d10 = j   - r1; d10 = d10 < -32 ? -32 : (d10 > 32 ? 32 : d10);
                int d11 = j+1 - r1; d11 = d11 < -32 ? -32 : (d11 > 32 ? 32 : d11);
                float s0 = fminf(cs[nt][0]*SCALE + rs[d00+32], 60.f);
                float s1 = fminf(cs[nt][1]*SCALE + rs[d01+32], 60.f);
                float s2 = fminf(cs[nt][2]*SCALE + rs[d10+32], 60.f);
                float s3 = fminf(cs[nt][3]*SCALE + rs[d11+32], 60.f);
                float p0 = __expf(s0), p1 = __expf(s1), p2 = __expf(s2), p3 = __expf(s3);
                sum0 += p0 + p1;
                sum1 += p2 + p3;
                uint2 u0; u0.x = __float_as_uint(p0); u0.y = __float_as_uint(p1);
                uint2 u1; u1.x = __float_as_uint(p2); u1.y = __float_as_uint(p3);
                *(uint2*)&Ps[w*16+g  ][(hf*4+nt)*8+2*tg] = u0;
                *(uint2*)&Ps[w*16+g+8][(hf*4+nt)*8+2*tg] = u1;
            }
        }
        __syncwarp();

        // O += P @ V
        #pragma unroll
        for (int kc2 = 0; kc2 < 8; ++kc2) {
            int kk = kc2*8;
            unsigned a0 = Ps[w*16+g  ][kk+tg];
            unsigned a1 = Ps[w*16+g+8][kk+tg];
            unsigned a2 = Ps[w*16+g  ][kk+tg+4];
            unsigned a3 = Ps[w*16+g+8][kk+tg+4];
            #pragma unroll
            for (int nt2 = 0; nt2 < 4; ++nt2) {
                unsigned b0 = Vt[nt2*8+g][kk+tg], b1 = Vt[nt2*8+g][kk+tg+4];
                MMA_TF32(co[nt2], a0,a1,a2,a3, b0,b1);
            }
        }
    }

    sum0 += __shfl_xor_sync(0xffffffffu, sum0, 1);
    sum0 += __shfl_xor_sync(0xffffffffu, sum0, 2);
    sum1 += __shfl_xor_sync(0xffffffffu, sum1, 1);
    sum1 += __shfl_xor_sync(0xffffffffu, sum1, 2);
    float inv0 = 1.f / sum0, inv1 = 1.f / sum1;

    #pragma unroll
    for (int nt2 = 0; nt2 < 4; ++nt2) {
        int d = nt2*8 + 2*tg;
        float2 s0; s0.x = co[nt2][0]*inv0; s0.y = co[nt2][1]*inv0;
        float2 s1; s1.x = co[nt2][2]*inv1; s1.y = co[nt2][3]*inv1;
        *(float2*)(o + ((size_t)(b*LSEQ + r0))*DM + h*HDIM + d) = s0;
        *(float2*)(o + ((size_t)(b*LSEQ + r1))*DM + h*HDIM + d) = s1;
    }
}

// ---------------- residual add + layernorm ----------------
__global__ void add_ln_kernel(const float* __restrict__ a, const float* __restrict__ bres,
                              const float* __restrict__ g, const float* __restrict__ beta,
                              float* __restrict__ out)
{
    int row = blockIdx.x;
    int t = threadIdx.x;
    float v = a[(size_t)row*DM + t] + bres[(size_t)row*DM + t];
    float s = v, s2 = v*v;
    #pragma unroll
    for (int off = 16; off; off >>= 1) {
        s  += __shfl_xor_sync(0xffffffffu, s,  off);
        s2 += __shfl_xor_sync(0xffffffffu, s2, off);
    }
    __shared__ float ws[4], ws2[4];
    int w = t >> 5;
    if ((t & 31) == 0) { ws[w] = s; ws2[w] = s2; }
    __syncthreads();
    s  = ws[0]+ws[1]+ws[2]+ws[3];
    s2 = ws2[0]+ws2[1]+ws2[2]+ws2[3];
    float mean = s * (1.f/128.f);
    float var  = s2 * (1.f/128.f) - mean*mean;
    float f = rsqrtf(var + EPSV);
    out[(size_t)row*DM + t] = (v - mean)*f*g[t] + beta[t];
}

// ---------------- im2col conv1 (pad=2) ----------------
__global__ void im2col1_kernel(const float* __restrict__ x2, float* __restrict__ col)
{
    long long e = (long long)blockIdx.x*256 + threadIdx.x;
    if (e >= (long long)BL*640) return;
    int c = (int)(e % 640); int row = (int)(e / 640);
    int ci = c/5, k = c%5;
    int b = row >> 11, l = row & 2047;
    int lx = l + k - 2;
    float v = (lx >= 0 && lx < LSEQ) ? x2[((size_t)(b*LSEQ + lx))*DM + ci] : 0.f;
    col[e] = v;
}

// ---------------- im2col conv2 (valid) ----------------
__global__ void im2col2_kernel(const float* __restrict__ p1, float* __restrict__ col)
{
    long long e = (long long)blockIdx.x*256 + threadIdx.x;
    if (e >= (long long)M2*640) return;
    int c = (int)(e % 640); int row = (int)(e / 640);
    int c1 = c/5, k = c%5;
    int b = row / L2OUT, l = row % L2OUT;
    col[e] = p1[((size_t)(b*L2HALF + l + k))*C1 + c1];
}

// ---------------- BN stats ----------------
__global__ void bnstats_kernel(const float* __restrict__ y, int rows, int Cc, int rpb,
                               float* __restrict__ sum, float* __restrict__ sumsq)
{
    int c = threadIdx.x;
    int r0 = blockIdx.x * rpb;
    int r1 = r0 + rpb; if (r1 > rows) r1 = rows;
    float s = 0.f, s2 = 0.f;
    for (int r = r0; r < r1; ++r) {
        float v = y[(size_t)r*Cc + c];
        s += v; s2 += v*v;
    }
    atomicAdd(&sum[c], s);
    atomicAdd(&sumsq[c], s2);
}

__global__ void zero_kernel(float* p, int n)
{
    int i = blockIdx.x*256 + threadIdx.x;
    if (i < n) p[i] = 0.f;
}

// ---------------- BN + ReLU + maxpool(2) ----------------
__global__ void bnpool_kernel(const float* __restrict__ y1,
                              const float* __restrict__ sum, const float* __restrict__ sq,
                              const float* __restrict__ g, const float* __restrict__ bb,
                              float* __restrict__ p1)
{
    int c = threadIdx.x;
    int row2 = blockIdx.x;
    int b = row2 >> 10, l2 = row2 & 1023;
    float mean = sum[c]*(1.f/(float)BL);
    float var  = sq[c]*(1.f/(float)BL) - mean*mean;
    float f = rsqrtf(var + EPSV)*g[c];
    float v0 = (y1[((size_t)(b*LSEQ + 2*l2  ))*C1 + c] - mean)*f + bb[c];
    float v1 = (y1[((size_t)(b*LSEQ + 2*l2+1))*C1 + c] - mean)*f + bb[c];
    v0 = fmaxf(v0, 0.f); v1 = fmaxf(v1, 0.f);
    p1[(size_t)row2*C1 + c] = fmaxf(v0, v1);
}

// ---------------- BN + ReLU + global max (parallel over L, atomicMax) ----------------
__global__ void gmax_kernel(const float* __restrict__ y2,
                            const float* __restrict__ sum, const float* __restrict__ sq,
                            const float* __restrict__ g, const float* __restrict__ bb,
                            float* __restrict__ z)
{
    int c = threadIdx.x;                 // 256
    int b = blockIdx.x;                  // 16
    int part = blockIdx.y;               // 8
    float mean = sum[c]*(1.f/(float)M2);
    float var  = sq[c]*(1.f/(float)M2) - mean*mean;
    float f = rsqrtf(var + EPSV)*g[c];
    int l0 = part * 128;
    int l1 = l0 + 128; if (l1 > L2OUT) l1 = L2OUT;
    float vm = 0.f;
    for (int l = l0; l < l1; ++l) {
        float v = (y2[((size_t)(b*L2OUT + l))*C2 + c] - mean)*f + bb[c];
        vm = fmaxf(vm, v);
    }
    vm = fmaxf(vm, 0.f);   // relu; also makes int-bit compare valid
    atomicMax((int*)&z[b*C2 + c], __float_as_int(vm));
}

// ---------------- final fc ----------------
__global__ void fc_kernel(const float* __restrict__ z, const float* __restrict__ w,
                          const float* __restrict__ bias, float* __restrict__ out)
{
    int b = blockIdx.x, n = blockIdx.y;
    int t = threadIdx.x;
    float p = z[b*C2 + t] * w[n*C2 + t];
    #pragma unroll
    for (int off = 16; off; off >>= 1) p += __shfl_xor_sync(0xffffffffu, p, off);
    __shared__ float ws[8];
    if ((t & 31) == 0) ws[t >> 5] = p;
    __syncthreads();
    if (t == 0) {
        float s = 0.f;
        #pragma unroll
        for (int i = 0; i < 8; ++i) s += ws[i];
        out[b*2 + n] = s + bias[n];
    }
}

// ---------------- launch ----------------
extern "C" void kernel_launch(void* const* d_in, const int* in_sizes, int n_in,
                              void* d_out, int out_size)
{
    const int*   X    = (const int*)  d_in[0];
    const float* sa   = (const float*)d_in[1];
    const int*   ptm  = (const int*)  d_in[2];
    const float* emb  = (const float*)d_in[3];
    const float* pemb = (const float*)d_in[4];
    const float* rpe  = (const float*)d_in[5];
    const float* inw  = (const float*)d_in[6];
    const float* inb  = (const float*)d_in[7];
    const float* opw  = (const float*)d_in[8];
    const float* opb  = (const float*)d_in[9];
    const float* l1w  = (const float*)d_in[10];
    const float* l1b  = (const float*)d_in[11];
    const float* l2w  = (const float*)d_in[12];
    const float* l2b  = (const float*)d_in[13];
    const float* ln1g = (const float*)d_in[14];
    const float* ln1b = (const float*)d_in[15];
    const float* ln2g = (const float*)d_in[16];
    const float* ln2b = (const float*)d_in[17];
    const float* c1w  = (const float*)d_in[18];
    const float* c1b  = (const float*)d_in[19];
    const float* bn1g = (const float*)d_in[20];
    const float* bn1b = (const float*)d_in[21];
    const float* c2w  = (const float*)d_in[22];
    const float* c2b  = (const float*)d_in[23];
    const float* bn2g = (const float*)d_in[24];
    const float* bn2b = (const float*)d_in[25];
    const float* fcw  = (const float*)d_in[26];
    const float* fcb  = (const float*)d_in[27];
    float* out = (float*)d_out;

    float *x0,*qkv,*att,*tmp,*x1,*ff1,*x2,*col,*y1,*p1,*y2,*z,*stats;
    cudaGetSymbolAddress((void**)&x0,   g_x0);
    cudaGetSymbolAddress((void**)&qkv,  g_qkv);
    cudaGetSymbolAddress((void**)&att,  g_att);
    cudaGetSymbolAddress((void**)&tmp,  g_tmp);
    cudaGetSymbolAddress((void**)&x1,   g_x1);
    cudaGetSymbolAddress((void**)&ff1,  g_ff1);
    cudaGetSymbolAddress((void**)&x2,   g_x2);
    cudaGetSymbolAddress((void**)&col,  g_col);
    cudaGetSymbolAddress((void**)&y1,   g_y1);
    cudaGetSymbolAddress((void**)&p1,   g_p1);
    cudaGetSymbolAddress((void**)&y2,   g_y2);
    cudaGetSymbolAddress((void**)&z,    g_z);
    cudaGetSymbolAddress((void**)&stats,g_stats);

    // 1) embedding + concat
    embed_kernel<<<BL, 128>>>(X, sa, ptm, emb, pemb, x0);

    // 2) qkv projection [BL,384]
    gemm_tf32<<<dim3(384/64, BL/128), 256>>>(x0, inw, inb, qkv, BL, 3*DM, DM, 0);

    // 3) attention
    attn_tf32<<<dim3(LSEQ/128, HH, BB), 256>>>(qkv, rpe, att);

    // 4) out projection
    gemm_tf32<<<dim3(DM/64, BL/128), 256>>>(att, opw, opb, tmp, BL, DM, DM, 0);

    // 5) x1 = LN(x0 + attn_out)
    add_ln_kernel<<<BL, 128>>>(x0, tmp, ln1g, ln1b, x1);

    // 6) FF
    gemm_tf32<<<dim3(FFD/64, BL/128), 256>>>(x1, l1w, l1b, ff1, BL, FFD, DM, 1);
    gemm_tf32<<<dim3(DM/64,  BL/128), 256>>>(ff1, l2w, l2b, tmp, BL, DM, FFD, 0);

    // 7) x2 = LN(x1 + ff)
    add_ln_kernel<<<BL, 128>>>(x1, tmp, ln2g, ln2b, x2);

    // 8) conv1 via im2col + GEMM
    im2col1_kernel<<<(int)(((long long)BL*640 + 255)/256), 256>>>(x2, col);
    gemm_tf32<<<dim3(C1/64, BL/128), 256>>>(col, c1w, c1b, y1, BL, C1, DM*KK, 0);

    // 9) zero stats + z, BN1 stats
    zero_kernel<<<3, 256>>>(stats, 2*C1 + 2*C2);
    zero_kernel<<<16, 256>>>(z, BB*C2);
    bnstats_kernel<<<128, C1>>>(y1, BL, C1, 256, stats, stats + C1);

    // 10) BN1 + ReLU + maxpool2
    bnpool_kernel<<<BB*L2HALF, C1>>>(y1, stats, stats + C1, bn1g, bn1b, p1);

    // 11) conv2 via im2col + GEMM
    im2col2_kernel<<<(int)(((long long)M2*640 + 255)/256), 256>>>(p1, col);
    gemm_tf32<<<dim3(C2/64, (M2+127)/128), 256>>>(col, c2w, c2b, y2, M2, C2, C1*KK, 0);

    // 12) BN2 stats
    bnstats_kernel<<<128, C2>>>(y2, M2, C2, 128, stats + 2*C1, stats + 2*C1 + C2);

    // 13) BN2 + ReLU + global max (parallel)
    gmax_kernel<<<dim3(BB, 8), C2>>>(y2, stats + 2*C1, stats + 2*C1 + C2, bn2g, bn2b, z);

    // 14) fc
    fc_kernel<<<dim3(BB, 2), 256>>>(z, fcw, fcb, out);
}

// round 4
// speedup vs baseline: 3.1704x; 1.0184x over previous
#include <cuda_runtime.h>
#include <math.h>

// ---------------- problem constants ----------------
#define BB    16
#define LSEQ  2048
#define BL    (BB*LSEQ)        // 32768
#define DM    128
#define HH    4
#define HDIM  32
#define FFD   256
#define C1    128
#define C2    256
#define KK    5
#define L2HALF 1024
#define L2OUT  1020
#define M2    (BB*L2OUT)       // 16320
#define EPSV  1e-5f
#define SCALE 0.17677669529663687f

// ---------------- scratch ----------------
__device__ float g_x0 [BL*DM];
__device__ float g_qkv[BL*3*DM];
__device__ float g_att[BL*DM];
__device__ float g_tmp[BL*DM];
__device__ float g_x1 [BL*DM];
__device__ float g_ff1[BL*FFD];
__device__ float g_x2 [BL*DM];
__device__ float g_col[BL*640];
__device__ float g_y1 [BL*C1];
__device__ float g_p1 [BB*L2HALF*C1];
__device__ float g_y2 [M2*C2];
__device__ float g_z  [BB*C2];
__device__ float g_stats[2*C1 + 2*C2];

// ---------------- helpers ----------------
__device__ __forceinline__ unsigned sptr(const void* p) {
    return (unsigned)__cvta_generic_to_shared(p);
}
#define CP16(dst, src) asm volatile("cp.async.cg.shared.global [%0], [%1], 16;" :: "r"(dst), "l"(src))
#define CP_COMMIT()    asm volatile("cp.async.commit_group;")
#define CP_WAIT1()     asm volatile("cp.async.wait_group 1;")
#define CP_WAIT0()     asm volatile("cp.async.wait_group 0;")

#define MMA_TF32(C, a0,a1,a2,a3, b0,b1) \
    asm volatile("mma.sync.aligned.m16n8k8.row.col.f32.tf32.tf32.f32 " \
                 "{%0,%1,%2,%3},{%4,%5,%6,%7},{%8,%9},{%0,%1,%2,%3};" \
                 : "+f"((C)[0]),"+f"((C)[1]),"+f"((C)[2]),"+f"((C)[3]) \
                 : "r"(a0),"r"(a1),"r"(a2),"r"(a3),"r"(b0),"r"(b1))

#define LDSM4(R0,R1,R2,R3, A) \
    asm volatile("ldmatrix.sync.aligned.m8n8.x4.shared.b16 {%0,%1,%2,%3}, [%4];" \
                 : "=r"(R0),"=r"(R1),"=r"(R2),"=r"(R3) : "r"(A))

// ---------------- embed ----------------
__global__ void embed_kernel(const int* __restrict__ X, const float* __restrict__ sa,
                             const int* __restrict__ ptm,
                             const float* __restrict__ emb, const float* __restrict__ pemb,
                             float* __restrict__ x0)
{
    int row = blockIdx.x;
    int t = threadIdx.x;
    float v;
    if (t < 120) v = emb[X[row]*120 + t] * sa[row];
    else         v = pemb[ptm[row]*8 + (t-120)];
    x0[(size_t)row*DM + t] = v;
}

// ---------------- tf32 GEMM: 3-stage cp.async + ldmatrix ----------------
// C[M,N] = A[M,K] @ W[N,K]^T + bias (+relu). tile 128x64, K-chunk 16, 256 thr.
// N%64==0, K%16==0, K>=32.
#define GST 20   // smem row stride (16 + 4 pad)
__global__ __launch_bounds__(256,3) void gemm_tf32(const float* __restrict__ A,
                                                   const float* __restrict__ W,
                                                   const float* __restrict__ bias,
                                                   float* __restrict__ C,
                                                   int M, int N, int K, int relu)
{
    __shared__ __align__(16) unsigned As[3][128*GST];
    __shared__ __align__(16) unsigned Bs[3][64*GST];
    int tid = threadIdx.x;
    int w = tid >> 5, lane = tid & 31, g = lane >> 2, tg = lane & 3;
    int wm = w & 3, wn = w >> 2;
    int row0 = blockIdx.y * 128, col0 = blockIdx.x * 64;

    // ldmatrix per-lane offsets
    int la = lane & 7, l8 = (lane >> 3) & 1, l16 = (lane >> 4) & 1;
    int rA = la + l8*8,  cA = l16*4;   // A-operand x4
    int rB = la + l16*8, cB = l8*4;    // B-operand x4 (covers 16 n-rows)

    // loader coords: 4-float groups
    int lr = tid >> 2, lg4 = (tid & 3) * 4;
    int ar0 = row0 + lr;      if (ar0 > M-1) ar0 = M-1;
    int ar1 = row0 + lr + 64; if (ar1 > M-1) ar1 = M-1;
    const float* ap0 = A + (size_t)ar0*K + lg4;
    const float* ap1 = A + (size_t)ar1*K + lg4;
    const float* wp  = W + (size_t)(col0 + lr)*K + lg4;

    float c[2][4][4];
    #pragma unroll
    for (int mt=0; mt<2; ++mt)
        #pragma unroll
        for (int nt=0; nt<4; ++nt)
            #pragma unroll
            for (int i=0;i<4;++i) c[mt][nt][i]=0.f;

    int kt = K >> 4;

    #define GLOAD(s, k0) do { \
        CP16(sptr(&As[s][lr*GST + lg4]),        ap0 + (k0)); \
        CP16(sptr(&As[s][(lr+64)*GST + lg4]),   ap1 + (k0)); \
        CP16(sptr(&Bs[s][lr*GST + lg4]),        wp  + (k0)); \
        CP_COMMIT(); \
    } while (0)

    GLOAD(0, 0);
    GLOAD(1, 16);

    for (int t = 0; t < kt; ++t) {
        int s = t % 3;
        CP_WAIT1();
        __syncthreads();
        if (t + 2 < kt) { GLOAD((t+2)%3, (t+2)*16); }
        else            { CP_COMMIT(); }

        #pragma unroll
        for (int kc = 0; kc < 2; ++kc) {
            int kk = kc*8;
            unsigned a[2][4], bq[2][4];
            #pragma unroll
            for (int mt = 0; mt < 2; ++mt)
                LDSM4(a[mt][0],a[mt][1],a[mt][2],a[mt][3],
                      sptr(&As[s][(wm*32 + mt*16 + rA)*GST + kk + cA]));
            #pragma unroll
            for (int p = 0; p < 2; ++p)
                LDSM4(bq[p][0],bq[p][1],bq[p][2],bq[p][3],
                      sptr(&Bs[s][(wn*32 + p*16 + rB)*GST + kk + cB]));
            #pragma unroll
            for (int p = 0; p < 2; ++p)
                #pragma unroll
                for (int q = 0; q < 2; ++q) {
                    MMA_TF32(c[0][p*2+q], a[0][0],a[0][1],a[0][2],a[0][3], bq[p][q*2], bq[p][q*2+1]);
                    MMA_TF32(c[1][p*2+q], a[1][0],a[1][1],a[1][2],a[1][3], bq[p][q*2], bq[p][q*2+1]);
                }
        }
    }
    #undef GLOAD

    #pragma unroll
    for (int mt = 0; mt < 2; ++mt) {
        int r0 = row0 + wm*32 + mt*16 + g;
        #pragma unroll
        for (int nt = 0; nt < 4; ++nt) {
            int cc = col0 + wn*32 + nt*8 + 2*tg;
            float b0v = bias[cc], b1v = bias[cc+1];
            float v0 = c[mt][nt][0] + b0v, v1 = c[mt][nt][1] + b1v;
            float v2 = c[mt][nt][2] + b0v, v3 = c[mt][nt][3] + b1v;
            if (relu) { v0=fmaxf(v0,0.f); v1=fmaxf(v1,0.f); v2=fmaxf(v2,0.f); v3=fmaxf(v3,0.f); }
            if (r0 < M)     { float2 s2={v0,v1}; *(float2*)(C + (size_t)r0*N + cc) = s2; }
            if (r0 + 8 < M) { float2 s2={v2,v3}; *(float2*)(C + (size_t)(r0+8)*N + cc) = s2; }
        }
    }
}

// ---------------- tf32 flash attention with RPE bias (ldmatrix fragments) ----------------
// grid (L/128, H, B), block 256 (8 warps); each warp owns 16 query rows.
#define KST 36
#define VST 68
__global__ __launch_bounds__(256,3) void attn_tf32(const float* __restrict__ qkv,
                                                   const float* __restrict__ rpe,
                                                   float* __restrict__ o)
{
    __shared__ __align__(16) unsigned Ks[64*KST];   // [j][d]
    __shared__ __align__(16) unsigned Vt[32*VST];   // [d][j]
    __shared__ __align__(16) unsigned Ps[128*VST];  // [qrow][j]
    __shared__ float rs[65];

    int tid = threadIdx.x;
    int w = tid >> 5, lane = tid & 31, g = lane >> 2, tg = lane & 3;
    int b = blockIdx.z, h = blockIdx.y;
    int q0 = blockIdx.x * 128;
    if (tid < 65) rs[tid] = rpe[tid*HH + h];

    int la = lane & 7, l8 = (lane >> 3) & 1, l16 = (lane >> 4) & 1;
    int rA = la + l8*8,  cA = l16*4;
    int rB = la + l16*8, cB = l8*4;

    int r0 = q0 + w*16 + g, r1 = r0 + 8;

    // persistent Q fragments (raw f32 bits -> tf32 truncation)
    unsigned aq[4][4];
    {
        const float* qb = qkv + (size_t)(b*LSEQ)*384 + h*HDIM;
        #pragma unroll
        for (int kc = 0; kc < 4; ++kc) {
            int k = kc*8;
            aq[kc][0] = __float_as_uint(__ldg(qb + (size_t)r0*384 + k + tg));
            aq[kc][1] = __float_as_uint(__ldg(qb + (size_t)r1*384 + k + tg));
            aq[kc][2] = __float_as_uint(__ldg(qb + (size_t)r0*384 + k + tg + 4));
            aq[kc][3] = __float_as_uint(__ldg(qb + (size_t)r1*384 + k + tg + 4));
        }
    }

    float co[4][4];
    #pragma unroll
    for (int nt=0;nt<4;++nt)
        #pragma unroll
        for (int i=0;i<4;++i) co[nt][i]=0.f;
    float sum0 = 0.f, sum1 = 0.f;

    int sjr = tid >> 3, sc4 = (tid & 7) * 4;

    for (int j0 = 0; j0 < LSEQ; j0 += 64) {
        __syncthreads();
        // stage K via cp.async (raw f32)
        const float* kb = qkv + (size_t)(b*LSEQ + j0)*384 + h*HDIM + 128;
        CP16(sptr(&Ks[sjr*KST + sc4]),      kb + (size_t)sjr*384 + sc4);
        CP16(sptr(&Ks[(sjr+32)*KST + sc4]), kb + (size_t)(sjr+32)*384 + sc4);
        CP_COMMIT();
        // stage V transposed (manual)
        const float* vb = kb + 128;
        {
            float4 v0 = *(const float4*)(vb + (size_t)sjr*384 + sc4);
            Vt[(sc4+0)*VST + sjr] = __float_as_uint(v0.x);
            Vt[(sc4+1)*VST + sjr] = __float_as_uint(v0.y);
            Vt[(sc4+2)*VST + sjr] = __float_as_uint(v0.z);
            Vt[(sc4+3)*VST + sjr] = __float_as_uint(v0.w);
            float4 v1 = *(const float4*)(vb + (size_t)(sjr+32)*384 + sc4);
            Vt[(sc4+0)*VST + sjr+32] = __float_as_uint(v1.x);
            Vt[(sc4+1)*VST + sjr+32] = __float_as_uint(v1.y);
            Vt[(sc4+2)*VST + sjr+32] = __float_as_uint(v1.z);
            Vt[(sc4+3)*VST + sjr+32] = __float_as_uint(v1.w);
        }
        CP_WAIT0();
        __syncthreads();

        // S = Q @ K^T in two 16x32 halves
        #pragma unroll
        for (int hf = 0; hf < 2; ++hf) {
            float cs[4][4];
            #pragma unroll
            for (int nt=0;nt<4;++nt)
                #pragma unroll
                for (int i=0;i<4;++i) cs[nt][i]=0.f;
            #pragma unroll
            for (int kc = 0; kc < 4; ++kc) {
                int kk = kc*8;
                unsigned bq[2][4];
                #pragma unroll
                for (int p = 0; p < 2; ++p)
                    LDSM4(bq[p][0],bq[p][1],bq[p][2],bq[p][3],
                          sptr(&Ks[(hf*32 + p*16 + rB)*KST + kk + cB]));
                #pragma unroll
                for (int p = 0; p < 2; ++p)
                    #pragma unroll
                    for (int q = 0; q < 2; ++q)
                        MMA_TF32(cs[p*2+q], aq[kc][0],aq[kc][1],aq[kc][2],aq[kc][3],
                                 bq[p][q*2], bq[p][q*2+1]);
            }
            // softmax (no max-rescale; clamp defensively) + write P
            #pragma unroll
            for (int nt = 0; nt < 4; ++nt) {
                int j = j0 + (hf*4+nt)*8 + 2*tg;
                int d00 = j   - r0; d00 = d00 < -32 ? -32 : (d00 > 32 ? 32 : d00);
                int d01 = j+1 - r0; d01 = d01 < -32 ? -32 : (d01 > 32 ? 32 : d01);
                int d10 = j   - r1; d10 = d10 < -32 ? -32 : (d10 > 32 ? 32 : d10);
                int d11 = j+1 - r1; d11 = d11 < -32 ? -32 : (d11 > 32 ? 32 : d11);
                float s0 = fminf(cs[nt][0]*SCALE + rs[d00+32], 60.f);
                float s1 = fminf(cs[nt][1]*SCALE + rs[d01+32], 60.f);
                float s2 = fminf(cs[nt][2]*SCALE + rs[d10+32], 60.f);
                float s3 = fminf(cs[nt][3]*SCALE + rs[d11+32], 60.f);
                float p0 = __expf(s0), p1 = __expf(s1), p2 = __expf(s2), p3 = __expf(s3);
                sum0 += p0 + p1;
                sum1 += p2 + p3;
                uint2 u0; u0.x = __float_as_uint(p0); u0.y = __float_as_uint(p1);
                uint2 u1; u1.x = __float_as_uint(p2); u1.y = __float_as_uint(p3);
                *(uint2*)&Ps[(w*16+g  )*VST + (hf*4+nt)*8 + 2*tg] = u0;
                *(uint2*)&Ps[(w*16+g+8)*VST + (hf*4+nt)*8 + 2*tg] = u1;
            }
        }
        __syncwarp();

        // O += P @ V
        #pragma unroll
        for (int kc2 = 0; kc2 < 8; ++kc2) {
            int kk = kc2*8;
            unsigned a0,a1,a2,a3;
            LDSM4(a0,a1,a2,a3, sptr(&Ps[(w*16 + rA)*VST + kk + cA]));
            unsigned bq[2][4];
            #pragma unroll
            for (int p = 0; p < 2; ++p)
                LDSM4(bq[p][0],bq[p][1],bq[p][2],bq[p][3],
                      sptr(&Vt[(p*16 + rB)*VST + kk + cB]));
            #pragma unroll
            for (int p = 0; p < 2; ++p)
                #pragma unroll
                for (int q = 0; q < 2; ++q)
                    MMA_TF32(co[p*2+q], a0,a1,a2,a3, bq[p][q*2], bq[p][q*2+1]);
        }
    }

    sum0 += __shfl_xor_sync(0xffffffffu, sum0, 1);
    sum0 += __shfl_xor_sync(0xffffffffu, sum0, 2);
    sum1 += __shfl_xor_sync(0xffffffffu, sum1, 1);
    sum1 += __shfl_xor_sync(0xffffffffu, sum1, 2);
    float inv0 = 1.f / sum0, inv1 = 1.f / sum1;

    #pragma unroll
    for (int nt2 = 0; nt2 < 4; ++nt2) {
        int d = nt2*8 + 2*tg;
        float2 s0; s0.x = co[nt2][0]*inv0; s0.y = co[nt2][1]*inv0;
        float2 s1; s1.x = co[nt2][2]*inv1; s1.y = co[nt2][3]*inv1;
        *(float2*)(o + ((size_t)(b*LSEQ + r0))*DM + h*HDIM + d) = s0;
        *(float2*)(o + ((size_t)(b*LSEQ + r1))*DM + h*HDIM + d) = s1;
    }
}

// ---------------- residual add + layernorm ----------------
__global__ void add_ln_kernel(const float* __restrict__ a, const float* __restrict__ bres,
                              const float* __restrict__ g, const float* __restrict__ beta,
                              float* __restrict__ out)
{
    int row = blockIdx.x;
    int t = threadIdx.x;
    float v = a[(size_t)row*DM + t] + bres[(size_t)row*DM + t];
    float s = v, s2 = v*v;
    #pragma unroll
    for (int off = 16; off; off >>= 1) {
        s  += __shfl_xor_sync(0xffffffffu, s,  off);
        s2 += __shfl_xor_sync(0xffffffffu, s2, off);
    }
    __shared__ float ws[4], ws2[4];
    int w = t >> 5;
    if ((t & 31) == 0) { ws[w] = s; ws2[w] = s2; }
    __syncthreads();
    s  = ws[0]+ws[1]+ws[2]+ws[3];
    s2 = ws2[0]+ws2[1]+ws2[2]+ws2[3];
    float mean = s * (1.f/128.f);
    float var  = s2 * (1.f/128.f) - mean*mean;
    float f = rsqrtf(var + EPSV);
    out[(size_t)row*DM + t] = (v - mean)*f*g[t] + beta[t];
}

// ---------------- im2col conv1 (pad=2) ----------------
__global__ void im2col1_kernel(const float* __restrict__ x2, float* __restrict__ col)
{
    long long e = (long long)blockIdx.x*256 + threadIdx.x;
    if (e >= (long long)BL*640) return;
    int c = (int)(e % 640); int row = (int)(e / 640);
    int ci = c/5, k = c%5;
    int b = row >> 11, l = row & 2047;
    int lx = l + k - 2;
    float v = (lx >= 0 && lx < LSEQ) ? x2[((size_t)(b*LSEQ + lx))*DM + ci] : 0.f;
    col[e] = v;
}

// ---------------- im2col conv2 (valid) ----------------
__global__ void im2col2_kernel(const float* __restrict__ p1, float* __restrict__ col)
{
    long long e = (long long)blockIdx.x*256 + threadIdx.x;
    if (e >= (long long)M2*640) return;
    int c = (int)(e % 640); int row = (int)(e / 640);
    int c1 = c/5, k = c%5;
    int b = row / L2OUT, l = row % L2OUT;
    col[e] = p1[((size_t)(b*L2HALF + l + k))*C1 + c1];
}

// ---------------- BN stats ----------------
__global__ void bnstats_kernel(const float* __restrict__ y, int rows, int Cc, int rpb,
                               float* __restrict__ sum, float* __restrict__ sumsq)
{
    int c = threadIdx.x;
    int r0 = blockIdx.x * rpb;
    int r1 = r0 + rpb; if (r1 > rows) r1 = rows;
    float s = 0.f, s2 = 0.f;
    for (int r = r0; r < r1; ++r) {
        float v = y[(size_t)r*Cc + c];
        s += v; s2 += v*v;
    }
    atomicAdd(&sum[c], s);
    atomicAdd(&sumsq[c], s2);
}

__global__ void zero_kernel(float* p, int n)
{
    int i = blockIdx.x*256 + threadIdx.x;
    if (i < n) p[i] = 0.f;
}

// ---------------- BN + ReLU + maxpool(2) ----------------
__global__ void bnpool_kernel(const float* __restrict__ y1,
                              const float* __restrict__ sum, const float* __restrict__ sq,
                              const float* __restrict__ g, const float* __restrict__ bb,
                              float* __restrict__ p1)
{
    int c = threadIdx.x;
    int row2 = blockIdx.x;
    int b = row2 >> 10, l2 = row2 & 1023;
    float mean = sum[c]*(1.f/(float)BL);
    float var  = sq[c]*(1.f/(float)BL) - mean*mean;
    float f = rsqrtf(var + EPSV)*g[c];
    float v0 = (y1[((size_t)(b*LSEQ + 2*l2  ))*C1 + c] - mean)*f + bb[c];
    float v1 = (y1[((size_t)(b*LSEQ + 2*l2+1))*C1 + c] - mean)*f + bb[c];
    v0 = fmaxf(v0, 0.f); v1 = fmaxf(v1, 0.f);
    p1[(size_t)row2*C1 + c] = fmaxf(v0, v1);
}

// ---------------- BN + ReLU + global max (parallel over L, atomicMax) ----------------
__global__ void gmax_kernel(const float* __restrict__ y2,
                            const float* __restrict__ sum, const float* __restrict__ sq,
                            const float* __restrict__ g, const float* __restrict__ bb,
                            float* __restrict__ z)
{
    int c = threadIdx.x;                 // 256
    int b = blockIdx.x;                  // 16
    int part = blockIdx.y;               // 8
    float mean = sum[c]*(1.f/(float)M2);
    float var  = sq[c]*(1.f/(float)M2) - mean*mean;
    float f = rsqrtf(var + EPSV)*g[c];
    int l0 = part * 128;
    int l1 = l0 + 128; if (l1 > L2OUT) l1 = L2OUT;
    float vm = 0.f;
    for (int l = l0; l < l1; ++l) {
        float v = (y2[((size_t)(b*L2OUT + l))*C2 + c] - mean)*f + bb[c];
        vm = fmaxf(vm, v);
    }
    vm = fmaxf(vm, 0.f);
    atomicMax((int*)&z[b*C2 + c], __float_as_int(vm));
}

// ---------------- final fc ----------------
__global__ void fc_kernel(const float* __restrict__ z, const float* __restrict__ w,
                          const float* __restrict__ bias, float* __restrict__ out)
{
    int b = blockIdx.x, n = blockIdx.y;
    int t = threadIdx.x;
    float p = z[b*C2 + t] * w[n*C2 + t];
    #pragma unroll
    for (int off = 16; off; off >>= 1) p += __shfl_xor_sync(0xffffffffu, p, off);
    __shared__ float ws[8];
    if ((t & 31) == 0) ws[t >> 5] = p;
    __syncthreads();
    if (t == 0) {
        float s = 0.f;
        #pragma unroll
        for (int i = 0; i < 8; ++i) s += ws[i];
        out[b*2 + n] = s + bias[n];
    }
}

// ---------------- launch ----------------
extern "C" void kernel_launch(void* const* d_in, const int* in_sizes, int n_in,
                              void* d_out, int out_size)
{
    const int*   X    = (const int*)  d_in[0];
    const float* sa   = (const float*)d_in[1];
    const int*   ptm  = (const int*)  d_in[2];
    const float* emb  = (const float*)d_in[3];
    const float* pemb = (const float*)d_in[4];
    const float* rpe  = (const float*)d_in[5];
    const float* inw  = (const float*)d_in[6];
    const float* inb  = (const float*)d_in[7];
    const float* opw  = (const float*)d_in[8];
    const float* opb  = (const float*)d_in[9];
    const float* l1w  = (const float*)d_in[10];
    const float* l1b  = (const float*)d_in[11];
    const float* l2w  = (const float*)d_in[12];
    const float* l2b  = (const float*)d_in[13];
    const float* ln1g = (const float*)d_in[14];
    const float* ln1b = (const float*)d_in[15];
    const float* ln2g = (const float*)d_in[16];
    const float* ln2b = (const float*)d_in[17];
    const float* c1w  = (const float*)d_in[18];
    const float* c1b  = (const float*)d_in[19];
    const float* bn1g = (const float*)d_in[20];
    const float* bn1b = (const float*)d_in[21];
    const float* c2w  = (const float*)d_in[22];
    const float* c2b  = (const float*)d_in[23];
    const float* bn2g = (const float*)d_in[24];
    const float* bn2b = (const float*)d_in[25];
    const float* fcw  = (const float*)d_in[26];
    const float* fcb  = (const float*)d_in[27];
    float* out = (float*)d_out;

    float *x0,*qkv,*att,*tmp,*x1,*ff1,*x2,*col,*y1,*p1,*y2,*z,*stats;
    cudaGetSymbolAddress((void**)&x0,   g_x0);
    cudaGetSymbolAddress((void**)&qkv,  g_qkv);
    cudaGetSymbolAddress((void**)&att,  g_att);
    cudaGetSymbolAddress((void**)&tmp,  g_tmp);
    cudaGetSymbolAddress((void**)&x1,   g_x1);
    cudaGetSymbolAddress((void**)&ff1,  g_ff1);
    cudaGetSymbolAddress((void**)&x2,   g_x2);
    cudaGetSymbolAddress((void**)&col,  g_col);
    cudaGetSymbolAddress((void**)&y1,   g_y1);
    cudaGetSymbolAddress((void**)&p1,   g_p1);
    cudaGetSymbolAddress((void**)&y2,   g_y2);
    cudaGetSymbolAddress((void**)&z,    g_z);
    cudaGetSymbolAddress((void**)&stats,g_stats);

    // 1) embedding + concat
    embed_kernel<<<BL, 128>>>(X, sa, ptm, emb, pemb, x0);

    // 2) qkv projection [BL,384]
    gemm_tf32<<<dim3(384/64, BL/128), 256>>>(x0, inw, inb, qkv, BL, 3*DM, DM, 0);

    // 3) attention
    attn_tf32<<<dim3(LSEQ/128, HH, BB), 256>>>(qkv, rpe, att);

    // 4) out projection
    gemm_tf32<<<dim3(DM/64, BL/128), 256>>>(att, opw, opb, tmp, BL, DM, DM, 0);

    // 5) x1 = LN(x0 + attn_out)
    add_ln_kernel<<<BL, 128>>>(x0, tmp, ln1g, ln1b, x1);

    // 6) FF
    gemm_tf32<<<dim3(FFD/64, BL/128), 256>>>(x1, l1w, l1b, ff1, BL, FFD, DM, 1);
    gemm_tf32<<<dim3(DM/64,  BL/128), 256>>>(ff1, l2w, l2b, tmp, BL, DM, FFD, 0);

    // 7) x2 = LN(x1 + ff)
    add_ln_kernel<<<BL, 128>>>(x1, tmp, ln2g, ln2b, x2);

    // 8) conv1 via im2col + GEMM
    im2col1_kernel<<<(int)(((long long)BL*640 + 255)/256), 256>>>(x2, col);
    gemm_tf32<<<dim3(C1/64, BL/128), 256>>>(col, c1w, c1b, y1, BL, C1, DM*KK, 0);

    // 9) zero stats + z, BN1 stats
    zero_kernel<<<3, 256>>>(stats, 2*C1 + 2*C2);
    zero_kernel<<<16, 256>>>(z, BB*C2);
    bnstats_kernel<<<128, C1>>>(y1, BL, C1, 256, stats, stats + C1);

    // 10) BN1 + ReLU + maxpool2
    bnpool_kernel<<<BB*L2HALF, C1>>>(y1, stats, stats + C1, bn1g, bn1b, p1);

    // 11) conv2 via im2col + GEMM
    im2col2_kernel<<<(int)(((long long)M2*640 + 255)/256), 256>>>(p1, col);
    gemm_tf32<<<dim3(C2/64, (M2+127)/128), 256>>>(col, c2w, c2b, y2, M2, C2, C1*KK, 0);

    // 12) BN2 stats
    bnstats_kernel<<<128, C2>>>(y2, M2, C2, 128, stats + 2*C1, stats + 2*C1 + C2);

    // 13) BN2 + ReLU + global max (parallel)
    gmax_kernel<<<dim3(BB, 8), C2>>>(y2, stats + 2*C1, stats + 2*C1 + C2, bn2g, bn2b, z);

    // 14) fc
    fc_kernel<<<dim3(BB, 2), 256>>>(z, fcw, fcb, out);
}

// round 5
// speedup vs baseline: 3.2764x; 1.0334x over previous
#include <cuda_runtime.h>
#include <math.h>

// ---------------- problem constants ----------------
#define BB    16
#define LSEQ  2048
#define BL    (BB*LSEQ)        // 32768
#define DM    128
#define HH    4
#define HDIM  32
#define FFD   256
#define C1    128
#define C2    256
#define KK    5
#define L2HALF 1024
#define L2OUT  1020
#define M2    (BB*L2OUT)       // 16320
#define EPSV  1e-5f
#define SCALE 0.17677669529663687f

// ---------------- scratch ----------------
__device__ float g_x0 [BL*DM];
__device__ float g_qkv[BL*3*DM];
__device__ float g_att[BL*DM];
__device__ float g_tmp[BL*DM];
__device__ float g_x1 [BL*DM];
__device__ float g_ff1[BL*FFD];
__device__ float g_x2 [BL*DM];
__device__ float g_col[BL*640];
__device__ float g_y1 [BL*C1];
__device__ float g_p1 [BB*L2HALF*C1];
__device__ float g_y2 [M2*C2];
__device__ float g_z  [BB*C2];
__device__ float g_stats[2*C1 + 2*C2];

// ---------------- helpers ----------------
__device__ __forceinline__ unsigned sptr(const void* p) {
    return (unsigned)__cvta_generic_to_shared(p);
}
#define CP16(dst, src) asm volatile("cp.async.cg.shared.global [%0], [%1], 16;" :: "r"(dst), "l"(src))
#define CP_COMMIT()    asm volatile("cp.async.commit_group;")
#define CP_WAIT1()     asm volatile("cp.async.wait_group 1;")
#define CP_WAIT0()     asm volatile("cp.async.wait_group 0;")

#define MMA_TF32(C, a0,a1,a2,a3, b0,b1) \
    asm volatile("mma.sync.aligned.m16n8k8.row.col.f32.tf32.tf32.f32 " \
                 "{%0,%1,%2,%3},{%4,%5,%6,%7},{%8,%9},{%0,%1,%2,%3};" \
                 : "+f"((C)[0]),"+f"((C)[1]),"+f"((C)[2]),"+f"((C)[3]) \
                 : "r"(a0),"r"(a1),"r"(a2),"r"(a3),"r"(b0),"r"(b1))

#define LDSM4(R0,R1,R2,R3, A) \
    asm volatile("ldmatrix.sync.aligned.m8n8.x4.shared.b16 {%0,%1,%2,%3}, [%4];" \
                 : "=r"(R0),"=r"(R1),"=r"(R2),"=r"(R3) : "r"(A))

// ---------------- embed ----------------
__global__ void embed_kernel(const int* __restrict__ X, const float* __restrict__ sa,
                             const int* __restrict__ ptm,
                             const float* __restrict__ emb, const float* __restrict__ pemb,
                             float* __restrict__ x0)
{
    int row = blockIdx.x;
    int t = threadIdx.x;
    float v;
    if (t < 120) v = emb[X[row]*120 + t] * sa[row];
    else         v = pemb[ptm[row]*8 + (t-120)];
    x0[(size_t)row*DM + t] = v;
}

// ---------------- tf32 GEMM: 128x128 tile, 3-stage cp.async + ldmatrix ----------------
// C[M,N] = A[M,K] @ W[N,K]^T + bias (+relu). 256 thr, warp = 32x64, K-chunk 16.
// N%128==0, K%16==0, K>=32.
#define GST 20   // smem row stride (16 + 4 pad)
__global__ __launch_bounds__(256,2) void gemm_tf32(const float* __restrict__ A,
                                                   const float* __restrict__ W,
                                                   const float* __restrict__ bias,
                                                   float* __restrict__ C,
                                                   int M, int N, int K, int relu)
{
    __shared__ __align__(16) unsigned As[3][128*GST];
    __shared__ __align__(16) unsigned Bs[3][128*GST];
    int tid = threadIdx.x;
    int w = tid >> 5, lane = tid & 31, g = lane >> 2, tg = lane & 3;
    int wm = w & 3, wn = w >> 2;         // 4 m-quadrants x 2 n-halves
    int row0 = blockIdx.y * 128, col0 = blockIdx.x * 128;

    // ldmatrix per-lane offsets
    int la = lane & 7, l8 = (lane >> 3) & 1, l16 = (lane >> 4) & 1;
    int rA = la + l8*8,  cA = l16*4;   // A-operand x4
    int rB = la + l16*8, cB = l8*4;    // B-operand x4 (16 n-rows)

    // loader coords
    int lr = tid >> 2, lg4 = (tid & 3) * 4;
    int ar0 = row0 + lr;      if (ar0 > M-1) ar0 = M-1;
    int ar1 = row0 + lr + 64; if (ar1 > M-1) ar1 = M-1;
    const float* ap0 = A + (size_t)ar0*K + lg4;
    const float* ap1 = A + (size_t)ar1*K + lg4;
    const float* wp0 = W + (size_t)(col0 + lr)*K + lg4;
    const float* wp1 = W + (size_t)(col0 + lr + 64)*K + lg4;

    float c[2][8][4];
    #pragma unroll
    for (int mt=0; mt<2; ++mt)
        #pragma unroll
        for (int nt=0; nt<8; ++nt)
            #pragma unroll
            for (int i=0;i<4;++i) c[mt][nt][i]=0.f;

    int kt = K >> 4;

    #define GLOAD(s, k0) do { \
        CP16(sptr(&As[s][lr*GST + lg4]),      ap0 + (k0)); \
        CP16(sptr(&As[s][(lr+64)*GST + lg4]), ap1 + (k0)); \
        CP16(sptr(&Bs[s][lr*GST + lg4]),      wp0 + (k0)); \
        CP16(sptr(&Bs[s][(lr+64)*GST + lg4]), wp1 + (k0)); \
        CP_COMMIT(); \
    } while (0)

    GLOAD(0, 0);
    GLOAD(1, 16);

    for (int t = 0; t < kt; ++t) {
        int s = t % 3;
        CP_WAIT1();
        __syncthreads();
        if (t + 2 < kt) { GLOAD((t+2)%3, (t+2)*16); }
        else            { CP_COMMIT(); }

        #pragma unroll
        for (int kc = 0; kc < 2; ++kc) {
            int kk = kc*8;
            unsigned a[2][4], bq[4][4];
            #pragma unroll
            for (int mt = 0; mt < 2; ++mt)
                LDSM4(a[mt][0],a[mt][1],a[mt][2],a[mt][3],
                      sptr(&As[s][(wm*32 + mt*16 + rA)*GST + kk + cA]));
            #pragma unroll
            for (int p = 0; p < 4; ++p)
                LDSM4(bq[p][0],bq[p][1],bq[p][2],bq[p][3],
                      sptr(&Bs[s][(wn*64 + p*16 + rB)*GST + kk + cB]));
            #pragma unroll
            for (int p = 0; p < 4; ++p)
                #pragma unroll
                for (int q = 0; q < 2; ++q) {
                    int nt = p*2 + q;
                    MMA_TF32(c[0][nt], a[0][0],a[0][1],a[0][2],a[0][3], bq[p][q*2], bq[p][q*2+1]);
                    MMA_TF32(c[1][nt], a[1][0],a[1][1],a[1][2],a[1][3], bq[p][q*2], bq[p][q*2+1]);
                }
        }
    }
    #undef GLOAD

    #pragma unroll
    for (int mt = 0; mt < 2; ++mt) {
        int r0 = row0 + wm*32 + mt*16 + g;
        #pragma unroll
        for (int nt = 0; nt < 8; ++nt) {
            int cc = col0 + wn*64 + nt*8 + 2*tg;
            float b0v = bias[cc], b1v = bias[cc+1];
            float v0 = c[mt][nt][0] + b0v, v1 = c[mt][nt][1] + b1v;
            float v2 = c[mt][nt][2] + b0v, v3 = c[mt][nt][3] + b1v;
            if (relu) { v0=fmaxf(v0,0.f); v1=fmaxf(v1,0.f); v2=fmaxf(v2,0.f); v3=fmaxf(v3,0.f); }
            if (r0 < M)     { float2 s2={v0,v1}; *(float2*)(C + (size_t)r0*N + cc) = s2; }
            if (r0 + 8 < M) { float2 s2={v2,v3}; *(float2*)(C + (size_t)(r0+8)*N + cc) = s2; }
        }
    }
}

// ---------------- tf32 flash attention with RPE bias (ldmatrix fragments) ----------------
// grid (L/128, H, B), block 256 (8 warps); each warp owns 16 query rows.
#define KST 36
#define VST 68
__global__ __launch_bounds__(256,3) void attn_tf32(const float* __restrict__ qkv,
                                                   const float* __restrict__ rpe,
                                                   float* __restrict__ o)
{
    __shared__ __align__(16) unsigned Ks[64*KST];   // [j][d]
    __shared__ __align__(16) unsigned Vt[32*VST];   // [d][j]
    __shared__ __align__(16) unsigned Ps[128*VST];  // [qrow][j]
    __shared__ float rs[65];

    int tid = threadIdx.x;
    int w = tid >> 5, lane = tid & 31, g = lane >> 2, tg = lane & 3;
    int b = blockIdx.z, h = blockIdx.y;
    int q0 = blockIdx.x * 128;
    if (tid < 65) rs[tid] = rpe[tid*HH + h];

    int la = lane & 7, l8 = (lane >> 3) & 1, l16 = (lane >> 4) & 1;
    int rA = la + l8*8,  cA = l16*4;
    int rB = la + l16*8, cB = l8*4;

    int r0 = q0 + w*16 + g, r1 = r0 + 8;

    // persistent Q fragments (raw f32 bits -> tf32 truncation)
    unsigned aq[4][4];
    {
        const float* qb = qkv + (size_t)(b*LSEQ)*384 + h*HDIM;
        #pragma unroll
        for (int kc = 0; kc < 4; ++kc) {
            int k = kc*8;
            aq[kc][0] = __float_as_uint(__ldg(qb + (size_t)r0*384 + k + tg));
            aq[kc][1] = __float_as_uint(__ldg(qb + (size_t)r1*384 + k + tg));
            aq[kc][2] = __float_as_uint(__ldg(qb + (size_t)r0*384 + k + tg + 4));
            aq[kc][3] = __float_as_uint(__ldg(qb + (size_t)r1*384 + k + tg + 4));
        }
    }

    float co[4][4];
    #pragma unroll
    for (int nt=0;nt<4;++nt)
        #pragma unroll
        for (int i=0;i<4;++i) co[nt][i]=0.f;
    float sum0 = 0.f, sum1 = 0.f;

    int sjr = tid >> 3, sc4 = (tid & 7) * 4;

    for (int j0 = 0; j0 < LSEQ; j0 += 64) {
        __syncthreads();
        const float* kb = qkv + (size_t)(b*LSEQ + j0)*384 + h*HDIM + 128;
        CP16(sptr(&Ks[sjr*KST + sc4]),      kb + (size_t)sjr*384 + sc4);
        CP16(sptr(&Ks[(sjr+32)*KST + sc4]), kb + (size_t)(sjr+32)*384 + sc4);
        CP_COMMIT();
        const float* vb = kb + 128;
        {
            float4 v0 = *(const float4*)(vb + (size_t)sjr*384 + sc4);
            Vt[(sc4+0)*VST + sjr] = __float_as_uint(v0.x);
            Vt[(sc4+1)*VST + sjr] = __float_as_uint(v0.y);
            Vt[(sc4+2)*VST + sjr] = __float_as_uint(v0.z);
            Vt[(sc4+3)*VST + sjr] = __float_as_uint(v0.w);
            float4 v1 = *(const float4*)(vb + (size_t)(sjr+32)*384 + sc4);
            Vt[(sc4+0)*VST + sjr+32] = __float_as_uint(v1.x);
            Vt[(sc4+1)*VST + sjr+32] = __float_as_uint(v1.y);
            Vt[(sc4+2)*VST + sjr+32] = __float_as_uint(v1.z);
            Vt[(sc4+3)*VST + sjr+32] = __float_as_uint(v1.w);
        }
        CP_WAIT0();
        __syncthreads();

        // S = Q @ K^T in two 16x32 halves
        #pragma unroll
        for (int hf = 0; hf < 2; ++hf) {
            float cs[4][4];
            #pragma unroll
            for (int nt=0;nt<4;++nt)
                #pragma unroll
                for (int i=0;i<4;++i) cs[nt][i]=0.f;
            #pragma unroll
            for (int kc = 0; kc < 4; ++kc) {
                int kk = kc*8;
                unsigned bq[2][4];
                #pragma unroll
                for (int p = 0; p < 2; ++p)
                    LDSM4(bq[p][0],bq[p][1],bq[p][2],bq[p][3],
                          sptr(&Ks[(hf*32 + p*16 + rB)*KST + kk + cB]));
                #pragma unroll
                for (int p = 0; p < 2; ++p)
                    #pragma unroll
                    for (int q = 0; q < 2; ++q)
                        MMA_TF32(cs[p*2+q], aq[kc][0],aq[kc][1],aq[kc][2],aq[kc][3],
                                 bq[p][q*2], bq[p][q*2+1]);
            }
            #pragma unroll
            for (int nt = 0; nt < 4; ++nt) {
                int j = j0 + (hf*4+nt)*8 + 2*tg;
                int d00 = j   - r0; d00 = d00 < -32 ? -32 : (d00 > 32 ? 32 : d00);
                int d01 = j+1 - r0; d01 = d01 < -32 ? -32 : (d01 > 32 ? 32 : d01);
                int d10 = j   - r1; d10 = d10 < -32 ? -32 : (d10 > 32 ? 32 : d10);
                int d11 = j+1 - r1; d11 = d11 < -32 ? -32 : (d11 > 32 ? 32 : d11);
                float s0 = fminf(cs[nt][0]*SCALE + rs[d00+32], 60.f);
                float s1 = fminf(cs[nt][1]*SCALE + rs[d01+32], 60.f);
                float s2 = fminf(cs[nt][2]*SCALE + rs[d10+32], 60.f);
                float s3 = fminf(cs[nt][3]*SCALE + rs[d11+32], 60.f);
                float p0 = __expf(s0), p1 = __expf(s1), p2 = __expf(s2), p3 = __expf(s3);
                sum0 += p0 + p1;
                sum1 += p2 + p3;
                uint2 u0; u0.x = __float_as_uint(p0); u0.y = __float_as_uint(p1);
                uint2 u1; u1.x = __float_as_uint(p2); u1.y = __float_as_uint(p3);
                *(uint2*)&Ps[(w*16+g  )*VST + (hf*4+nt)*8 + 2*tg] = u0;
                *(uint2*)&Ps[(w*16+g+8)*VST + (hf*4+nt)*8 + 2*tg] = u1;
            }
        }
        __syncwarp();

        // O += P @ V
        #pragma unroll
        for (int kc2 = 0; kc2 < 8; ++kc2) {
            int kk = kc2*8;
            unsigned a0,a1,a2,a3;
            LDSM4(a0,a1,a2,a3, sptr(&Ps[(w*16 + rA)*VST + kk + cA]));
            unsigned bq[2][4];
            #pragma unroll
            for (int p = 0; p < 2; ++p)
                LDSM4(bq[p][0],bq[p][1],bq[p][2],bq[p][3],
                      sptr(&Vt[(p*16 + rB)*VST + kk + cB]));
            #pragma unroll
            for (int p = 0; p < 2; ++p)
                #pragma unroll
                for (int q = 0; q < 2; ++q)
                    MMA_TF32(co[p*2+q], a0,a1,a2,a3, bq[p][q*2], bq[p][q*2+1]);
        }
    }

    sum0 += __shfl_xor_sync(0xffffffffu, sum0, 1);
    sum0 += __shfl_xor_sync(0xffffffffu, sum0, 2);
    sum1 += __shfl_xor_sync(0xffffffffu, sum1, 1);
    sum1 += __shfl_xor_sync(0xffffffffu, sum1, 2);
    float inv0 = 1.f / sum0, inv1 = 1.f / sum1;

    #pragma unroll
    for (int nt2 = 0; nt2 < 4; ++nt2) {
        int d = nt2*8 + 2*tg;
        float2 s0; s0.x = co[nt2][0]*inv0; s0.y = co[nt2][1]*inv0;
        float2 s1; s1.x = co[nt2][2]*inv1; s1.y = co[nt2][3]*inv1;
        *(float2*)(o + ((size_t)(b*LSEQ + r0))*DM + h*HDIM + d) = s0;
        *(float2*)(o + ((size_t)(b*LSEQ + r1))*DM + h*HDIM + d) = s1;
    }
}

// ---------------- residual add + layernorm ----------------
__global__ void add_ln_kernel(const float* __restrict__ a, const float* __restrict__ bres,
                              const float* __restrict__ g, const float* __restrict__ beta,
                              float* __restrict__ out)
{
    int row = blockIdx.x;
    int t = threadIdx.x;
    float v = a[(size_t)row*DM + t] + bres[(size_t)row*DM + t];
    float s = v, s2 = v*v;
    #pragma unroll
    for (int off = 16; off; off >>= 1) {
        s  += __shfl_xor_sync(0xffffffffu, s,  off);
        s2 += __shfl_xor_sync(0xffffffffu, s2, off);
    }
    __shared__ float ws[4], ws2[4];
    int w = t >> 5;
    if ((t & 31) == 0) { ws[w] = s; ws2[w] = s2; }
    __syncthreads();
    s  = ws[0]+ws[1]+ws[2]+ws[3];
    s2 = ws2[0]+ws2[1]+ws2[2]+ws2[3];
    float mean = s * (1.f/128.f);
    float var  = s2 * (1.f/128.f) - mean*mean;
    float f = rsqrtf(var + EPSV);
    out[(size_t)row*DM + t] = (v - mean)*f*g[t] + beta[t];
}

// ---------------- im2col conv1 (pad=2) ----------------
__global__ void im2col1_kernel(const float* __restrict__ x2, float* __restrict__ col)
{
    long long e = (long long)blockIdx.x*256 + threadIdx.x;
    if (e >= (long long)BL*640) return;
    int c = (int)(e % 640); int row = (int)(e / 640);
    int ci = c/5, k = c%5;
    int b = row >> 11, l = row & 2047;
    int lx = l + k - 2;
    float v = (lx >= 0 && lx < LSEQ) ? x2[((size_t)(b*LSEQ + lx))*DM + ci] : 0.f;
    col[e] = v;
}

// ---------------- im2col conv2 (valid) ----------------
__global__ void im2col2_kernel(const float* __restrict__ p1, float* __restrict__ col)
{
    long long e = (long long)blockIdx.x*256 + threadIdx.x;
    if (e >= (long long)M2*640) return;
    int c = (int)(e % 640); int row = (int)(e / 640);
    int c1 = c/5, k = c%5;
    int b = row / L2OUT, l = row % L2OUT;
    col[e] = p1[((size_t)(b*L2HALF + l + k))*C1 + c1];
}

// ---------------- BN stats ----------------
__global__ void bnstats_kernel(const float* __restrict__ y, int rows, int Cc, int rpb,
                               float* __restrict__ sum, float* __restrict__ sumsq)
{
    int c = threadIdx.x;
    int r0 = blockIdx.x * rpb;
    int r1 = r0 + rpb; if (r1 > rows) r1 = rows;
    float s = 0.f, s2 = 0.f;
    for (int r = r0; r < r1; ++r) {
        float v = y[(size_t)r*Cc + c];
        s += v; s2 += v*v;
    }
    atomicAdd(&sum[c], s);
    atomicAdd(&sumsq[c], s2);
}

__global__ void zero_kernel(float* p, int n)
{
    int i = blockIdx.x*256 + threadIdx.x;
    if (i < n) p[i] = 0.f;
}

// ---------------- BN + ReLU + maxpool(2) ----------------
__global__ void bnpool_kernel(const float* __restrict__ y1,
                              const float* __restrict__ sum, const float* __restrict__ sq,
                              const float* __restrict__ g, const float* __restrict__ bb,
                              float* __restrict__ p1)
{
    int c = threadIdx.x;
    int row2 = blockIdx.x;
    int b = row2 >> 10, l2 = row2 & 1023;
    float mean = sum[c]*(1.f/(float)BL);
    float var  = sq[c]*(1.f/(float)BL) - mean*mean;
    float f = rsqrtf(var + EPSV)*g[c];
    float v0 = (y1[((size_t)(b*LSEQ + 2*l2  ))*C1 + c] - mean)*f + bb[c];
    float v1 = (y1[((size_t)(b*LSEQ + 2*l2+1))*C1 + c] - mean)*f + bb[c];
    v0 = fmaxf(v0, 0.f); v1 = fmaxf(v1, 0.f);
    p1[(size_t)row2*C1 + c] = fmaxf(v0, v1);
}

// ---------------- BN + ReLU + global max (parallel over L, atomicMax) ----------------
__global__ void gmax_kernel(const float* __restrict__ y2,
                            const float* __restrict__ sum, const float* __restrict__ sq,
                            const float* __restrict__ g, const float* __restrict__ bb,
                            float* __restrict__ z)
{
    int c = threadIdx.x;                 // 256
    int b = blockIdx.x;                  // 16
    int part = blockIdx.y;               // 8
    float mean = sum[c]*(1.f/(float)M2);
    float var  = sq[c]*(1.f/(float)M2) - mean*mean;
    float f = rsqrtf(var + EPSV)*g[c];
    int l0 = part * 128;
    int l1 = l0 + 128; if (l1 > L2OUT) l1 = L2OUT;
    float vm = 0.f;
    for (int l = l0; l < l1; ++l) {
        float v = (y2[((size_t)(b*L2OUT + l))*C2 + c] - mean)*f + bb[c];
        vm = fmaxf(vm, v);
    }
    vm = fmaxf(vm, 0.f);
    atomicMax((int*)&z[b*C2 + c], __float_as_int(vm));
}

// ---------------- final fc ----------------
__global__ void fc_kernel(const float* __restrict__ z, const float* __restrict__ w,
                          const float* __restrict__ bias, float* __restrict__ out)
{
    int b = blockIdx.x, n = blockIdx.y;
    int t = threadIdx.x;
    float p = z[b*C2 + t] * w[n*C2 + t];
    #pragma unroll
    for (int off = 16; off; off >>= 1) p += __shfl_xor_sync(0xffffffffu, p, off);
    __shared__ float ws[8];
    if ((t & 31) == 0) ws[t >> 5] = p;
    __syncthreads();
    if (t == 0) {
        float s = 0.f;
        #pragma unroll
        for (int i = 0; i < 8; ++i) s += ws[i];
        out[b*2 + n] = s + bias[n];
    }
}

// ---------------- launch ----------------
extern "C" void kernel_launch(void* const* d_in, const int* in_sizes, int n_in,
                              void* d_out, int out_size)
{
    const int*   X    = (const int*)  d_in[0];
    const float* sa   = (const float*)d_in[1];
    const int*   ptm  = (const int*)  d_in[2];
    const float* emb  = (const float*)d_in[3];
    const float* pemb = (const float*)d_in[4];
    const float* rpe  = (const float*)d_in[5];
    const float* inw  = (const float*)d_in[6];
    const float* inb  = (const float*)d_in[7];
    const float* opw  = (const float*)d_in[8];
    const float* opb  = (const float*)d_in[9];
    const float* l1w  = (const float*)d_in[10];
    const float* l1b  = (const float*)d_in[11];
    const float* l2w  = (const float*)d_in[12];
    const float* l2b  = (const float*)d_in[13];
    const float* ln1g = (const float*)d_in[14];
    const float* ln1b = (const float*)d_in[15];
    const float* ln2g = (const float*)d_in[16];
    const float* ln2b = (const float*)d_in[17];
    const float* c1w  = (const float*)d_in[18];
    const float* c1b  = (const float*)d_in[19];
    const float* bn1g = (const float*)d_in[20];
    const float* bn1b = (const float*)d_in[21];
    const float* c2w  = (const float*)d_in[22];
    const float* c2b  = (const float*)d_in[23];
    const float* bn2g = (const float*)d_in[24];
    const float* bn2b = (const float*)d_in[25];
    const float* fcw  = (const float*)d_in[26];
    const float* fcb  = (const float*)d_in[27];
    float* out = (float*)d_out;

    float *x0,*qkv,*att,*tmp,*x1,*ff1,*x2,*col,*y1,*p1,*y2,*z,*stats;
    cudaGetSymbolAddress((void**)&x0,   g_x0);
    cudaGetSymbolAddress((void**)&qkv,  g_qkv);
    cudaGetSymbolAddress((void**)&att,  g_att);
    cudaGetSymbolAddress((void**)&tmp,  g_tmp);
    cudaGetSymbolAddress((void**)&x1,   g_x1);
    cudaGetSymbolAddress((void**)&ff1,  g_ff1);
    cudaGetSymbolAddress((void**)&x2,   g_x2);
    cudaGetSymbolAddress((void**)&col,  g_col);
    cudaGetSymbolAddress((void**)&y1,   g_y1);
    cudaGetSymbolAddress((void**)&p1,   g_p1);
    cudaGetSymbolAddress((void**)&y2,   g_y2);
    cudaGetSymbolAddress((void**)&z,    g_z);
    cudaGetSymbolAddress((void**)&stats,g_stats);

    // 1) embedding + concat
    embed_kernel<<<BL, 128>>>(X, sa, ptm, emb, pemb, x0);

    // 2) qkv projection [BL,384]
    gemm_tf32<<<dim3(384/128, BL/128), 256>>>(x0, inw, inb, qkv, BL, 3*DM, DM, 0);

    // 3) attention
    attn_tf32<<<dim3(LSEQ/128, HH, BB), 256>>>(qkv, rpe, att);

    // 4) out projection
    gemm_tf32<<<dim3(DM/128, BL/128), 256>>>(att, opw, opb, tmp, BL, DM, DM, 0);

    // 5) x1 = LN(x0 + attn_out)
    add_ln_kernel<<<BL, 128>>>(x0, tmp, ln1g, ln1b, x1);

    // 6) FF
    gemm_tf32<<<dim3(FFD/128, BL/128), 256>>>(x1, l1w, l1b, ff1, BL, FFD, DM, 1);
    gemm_tf32<<<dim3(DM/128,  BL/128), 256>>>(ff1, l2w, l2b, tmp, BL, DM, FFD, 0);

    // 7) x2 = LN(x1 + ff)
    add_ln_kernel<<<BL, 128>>>(x1, tmp, ln2g, ln2b, x2);

    // 8) conv1 via im2col + GEMM
    im2col1_kernel<<<(int)(((long long)BL*640 + 255)/256), 256>>>(x2, col);
    gemm_tf32<<<dim3(C1/128, BL/128), 256>>>(col, c1w, c1b, y1, BL, C1, DM*KK, 0);

    // 9) zero stats + z, BN1 stats
    zero_kernel<<<3, 256>>>(stats, 2*C1 + 2*C2);
    zero_kernel<<<16, 256>>>(z, BB*C2);
    bnstats_kernel<<<128, C1>>>(y1, BL, C1, 256, stats, stats + C1);

    // 10) BN1 + ReLU + maxpool2
    bnpool_kernel<<<BB*L2HALF, C1>>>(y1, stats, stats + C1, bn1g, bn1b, p1);

    // 11) conv2 via im2col + GEMM
    im2col2_kernel<<<(int)(((long long)M2*640 + 255)/256), 256>>>(p1, col);
    gemm_tf32<<<dim3(C2/128, (M2+127)/128), 256>>>(col, c2w, c2b, y2, M2, C2, C1*KK, 0);

    // 12) BN2 stats
    bnstats_kernel<<<128, C2>>>(y2, M2, C2, 128, stats + 2*C1, stats + 2*C1 + C2);

    // 13) BN2 + ReLU + global max (parallel)
    gmax_kernel<<<dim3(BB, 8), C2>>>(y2, stats + 2*C1, stats + 2*C1 + C2, bn2g, bn2b, z);

    // 14) fc
    fc_kernel<<<dim3(BB, 2), 256>>>(z, fcw, fcb, out);
}

// round 7
// speedup vs baseline: 4.5297x; 1.3825x over previous
#include <cuda_runtime.h>
#include <cuda_fp16.h>
#include <math.h>

// ---------------- problem constants ----------------
#define BB    16
#define LSEQ  2048
#define BL    (BB*LSEQ)        // 32768
#define DM    128
#define HH    4
#define HDIM  32
#define FFD   256
#define C1    128
#define C2    256
#define KK    5
#define L2HALF 1024
#define L2OUT  1020
#define M2    (BB*L2OUT)       // 16320
#define EPSV  1e-5f
#define SCALE 0.17677669529663687f

// ---------------- scratch ----------------
__device__ float  g_x0 [BL*DM];
__device__ __half g_x0h[BL*DM];
__device__ __half g_qkvh[BL*3*DM];
__device__ __half g_atth[BL*DM];
__device__ float  g_tmp[BL*DM];
__device__ float  g_x1 [BL*DM];
__device__ __half g_x1h[BL*DM];
__device__ __half g_ff1h[BL*FFD];
__device__ float  g_x2 [BL*DM];
__device__ __half g_colh[BL*640];
__device__ float  g_y1 [BL*C1];
__device__ float  g_p1 [BB*L2HALF*C1];
__device__ float  g_y2 [M2*C2];
__device__ float  g_z  [BB*C2];
__device__ float  g_stats[2*C1 + 2*C2];
// weight fp16 pool: inw(49152) opw(16384) l1w(32768) l2w(32768) c1w(81920) c2w(163840) = 376832
__device__ __half g_wh[376832];

// ---------------- helpers ----------------
__device__ __forceinline__ unsigned sptr(const void* p) {
    return (unsigned)__cvta_generic_to_shared(p);
}
#define CP16(dst, src) asm volatile("cp.async.cg.shared.global [%0], [%1], 16;" :: "r"(dst), "l"(src))
#define CP_COMMIT()    asm volatile("cp.async.commit_group;")
#define CP_WAIT1()     asm volatile("cp.async.wait_group 1;")
#define CP_WAIT0()     asm volatile("cp.async.wait_group 0;")

#define MMA_F16(C, a0,a1,a2,a3, b0,b1) \
    asm volatile("mma.sync.aligned.m16n8k16.row.col.f32.f16.f16.f32 " \
                 "{%0,%1,%2,%3},{%4,%5,%6,%7},{%8,%9},{%0,%1,%2,%3};" \
                 : "+f"((C)[0]),"+f"((C)[1]),"+f"((C)[2]),"+f"((C)[3]) \
                 : "r"(a0),"r"(a1),"r"(a2),"r"(a3),"r"(b0),"r"(b1))

#define LDSM4(R0,R1,R2,R3, A) \
    asm volatile("ldmatrix.sync.aligned.m8n8.x4.shared.b16 {%0,%1,%2,%3}, [%4];" \
                 : "=r"(R0),"=r"(R1),"=r"(R2),"=r"(R3) : "r"(A))
#define LDSM4T(R0,R1,R2,R3, A) \
    asm volatile("ldmatrix.sync.aligned.m8n8.x4.trans.shared.b16 {%0,%1,%2,%3}, [%4];" \
                 : "=r"(R0),"=r"(R1),"=r"(R2),"=r"(R3) : "r"(A))

// ---------------- f32 -> f16 ----------------
__global__ void f2h_kernel(const float* __restrict__ src, __half* __restrict__ dst, int n)
{
    int i = blockIdx.x*256 + threadIdx.x;
    if (i < n) dst[i] = __float2half_rn(src[i]);
}

// ---------------- embed (writes f32 + f16) ----------------
__global__ void embed_kernel(const int* __restrict__ X, const float* __restrict__ sa,
                             const int* __restrict__ ptm,
                             const float* __restrict__ emb, const float* __restrict__ pemb,
                             float* __restrict__ x0, __half* __restrict__ x0h)
{
    int row = blockIdx.x;
    int t = threadIdx.x;
    float v;
    if (t < 120) v = emb[X[row]*120 + t] * sa[row];
    else         v = pemb[ptm[row]*8 + (t-120)];
    x0[(size_t)row*DM + t] = v;
    x0h[(size_t)row*DM + t] = __float2half_rn(v);
}

// ---------------- fp16 GEMM: 128x128 tile, 3-stage cp.async + ldmatrix ----------------
// C = A[M,K] @ W[N,K]^T + bias (+relu). 256 thr, warp 32x64, K-chunk 32 halves.
// N%128==0, K%32==0, K>=64. Writes Cf (f32) and/or Ch (f16).
#define GSTH 40   // smem row stride in halves (32 + 8 pad)
__global__ __launch_bounds__(256,2) void gemm_f16(const __half* __restrict__ A,
                                                  const __half* __restrict__ W,
                                                  const float* __restrict__ bias,
                                                  float* __restrict__ Cf,
                                                  __half* __restrict__ Ch,
                                                  int M, int N, int K, int relu)
{
    __shared__ __align__(16) __half As[3][128*GSTH];
    __shared__ __align__(16) __half Bs[3][128*GSTH];
    int tid = threadIdx.x;
    int w = tid >> 5, lane = tid & 31, g = lane >> 2, tg = lane & 3;
    int wm = w & 3, wn = w >> 2;
    int row0 = blockIdx.y * 128, col0 = blockIdx.x * 128;

    int la = lane & 7, l8 = (lane >> 3) & 1, l16 = (lane >> 4) & 1;
    int rA = la + l8*8, cA = l16*8;
    int rB = la + l8*8, cB = l16*8;

    int lr = tid >> 2, lc8 = (tid & 3) * 8;
    int ar0 = row0 + lr;      if (ar0 > M-1) ar0 = M-1;
    int ar1 = row0 + lr + 64; if (ar1 > M-1) ar1 = M-1;
    const __half* ap0 = A + (size_t)ar0*K + lc8;
    const __half* ap1 = A + (size_t)ar1*K + lc8;
    const __half* wp0 = W + (size_t)(col0 + lr)*K + lc8;
    const __half* wp1 = W + (size_t)(col0 + lr + 64)*K + lc8;

    float c[2][8][4];
    #pragma unroll
    for (int mt=0; mt<2; ++mt)
        #pragma unroll
        for (int nt=0; nt<8; ++nt)
            #pragma unroll
            for (int i=0;i<4;++i) c[mt][nt][i]=0.f;

    int kt = K >> 5;

    #define GLOAD(s, k0) do { \
        CP16(sptr(&As[s][lr*GSTH + lc8]),      ap0 + (k0)); \
        CP16(sptr(&As[s][(lr+64)*GSTH + lc8]), ap1 + (k0)); \
        CP16(sptr(&Bs[s][lr*GSTH + lc8]),      wp0 + (k0)); \
        CP16(sptr(&Bs[s][(lr+64)*GSTH + lc8]), wp1 + (k0)); \
        CP_COMMIT(); \
    } while (0)

    GLOAD(0, 0);
    GLOAD(1, 32);

    for (int t = 0; t < kt; ++t) {
        int s = t % 3;
        CP_WAIT1();
        __syncthreads();
        if (t + 2 < kt) { GLOAD((t+2)%3, (t+2)*32); }
        else            { CP_COMMIT(); }

        #pragma unroll
        for (int ks = 0; ks < 2; ++ks) {
            int kk = ks*16;
            unsigned a[2][4], bq[4][4];
            #pragma unroll
            for (int mt = 0; mt < 2; ++mt)
                LDSM4(a[mt][0],a[mt][1],a[mt][2],a[mt][3],
                      sptr(&As[s][(wm*32 + mt*16 + rA)*GSTH + kk + cA]));
            #pragma unroll
            for (int p = 0; p < 4; ++p)
                LDSM4(bq[p][0],bq[p][1],bq[p][2],bq[p][3],
                      sptr(&Bs[s][(wn*64 + p*16 + rB)*GSTH + kk + cB]));
            #pragma unroll
            for (int p = 0; p < 4; ++p)
                #pragma unroll
                for (int q = 0; q < 2; ++q) {
                    int nt = p*2 + q;
                    MMA_F16(c[0][nt], a[0][0],a[0][1],a[0][2],a[0][3], bq[p][q], bq[p][q+2]);
                    MMA_F16(c[1][nt], a[1][0],a[1][1],a[1][2],a[1][3], bq[p][q], bq[p][q+2]);
                }
        }
    }
    #undef GLOAD

    #pragma unroll
    for (int mt = 0; mt < 2; ++mt) {
        int r0 = row0 + wm*32 + mt*16 + g;
        #pragma unroll
        for (int nt = 0; nt < 8; ++nt) {
            int cc = col0 + wn*64 + nt*8 + 2*tg;
            float b0v = bias[cc], b1v = bias[cc+1];
            float v0 = c[mt][nt][0] + b0v, v1 = c[mt][nt][1] + b1v;
            float v2 = c[mt][nt][2] + b0v, v3 = c[mt][nt][3] + b1v;
            if (relu) { v0=fmaxf(v0,0.f); v1=fmaxf(v1,0.f); v2=fmaxf(v2,0.f); v3=fmaxf(v3,0.f); }
            if (Cf) {
                if (r0 < M)     { float2 s2={v0,v1}; *(float2*)(Cf + (size_t)r0*N + cc) = s2; }
                if (r0 + 8 < M) { float2 s2={v2,v3}; *(float2*)(Cf + (size_t)(r0+8)*N + cc) = s2; }
            }
            if (Ch) {
                if (r0 < M)     *(__half2*)(Ch + (size_t)r0*N + cc)     = __floats2half2_rn(v0, v1);
                if (r0 + 8 < M) *(__half2*)(Ch + (size_t)(r0+8)*N + cc) = __floats2half2_rn(v2, v3);
            }
        }
    }
}

// ---------------- fp16 flash attention with RPE bias ----------------
// grid (L/128, H, B), block 256 (8 warps); each warp owns 16 query rows.
#define KSTH 40
#define PSTH 72
__global__ __launch_bounds__(256,3) void attn_f16(const __half* __restrict__ qkv,
                                                  const float* __restrict__ rpe,
                                                  __half* __restrict__ o)
{
    __shared__ __align__(16) __half Ks[64*KSTH];   // [j][d]
    __shared__ __align__(16) __half Vs[64*KSTH];   // [j][d]
    __shared__ __align__(16) __half Ps[128*PSTH];  // [qrow][j]
    __shared__ float rs[65];

    int tid = threadIdx.x;
    int w = tid >> 5, lane = tid & 31, g = lane >> 2, tg = lane & 3;
    int b = blockIdx.z, h = blockIdx.y;
    int q0 = blockIdx.x * 128;
    if (tid < 65) rs[tid] = rpe[tid*HH + h];

    int la = lane & 7, l8 = (lane >> 3) & 1, l16 = (lane >> 4) & 1;
    int rA = la + l8*8, cA = l16*8;
    int rB = la + l8*8, cB = l16*8;

    int r0 = q0 + w*16 + g, r1 = r0 + 8;

    // persistent Q fragments: 2 k16 steps x 4 regs (half2 each)
    unsigned aq[2][4];
    {
        const __half* qb = qkv + (size_t)(b*LSEQ)*384 + h*HDIM;
        #pragma unroll
        for (int kc = 0; kc < 2; ++kc) {
            int k = kc*16;
            aq[kc][0] = *(const unsigned*)(qb + (size_t)r0*384 + k + 2*tg);
            aq[kc][1] = *(const unsigned*)(qb + (size_t)r1*384 + k + 2*tg);
            aq[kc][2] = *(const unsigned*)(qb + (size_t)r0*384 + k + 2*tg + 8);
            aq[kc][3] = *(const unsigned*)(qb + (size_t)r1*384 + k + 2*tg + 8);
        }
    }

    float co[4][4];
    #pragma unroll
    for (int nt=0;nt<4;++nt)
        #pragma unroll
        for (int i=0;i<4;++i) co[nt][i]=0.f;
    float sum0 = 0.f, sum1 = 0.f;

    int srow = tid >> 2, scol = (tid & 3) * 8;

    for (int j0 = 0; j0 < LSEQ; j0 += 64) {
        __syncthreads();
        const __half* kb = qkv + (size_t)(b*LSEQ + j0)*384 + h*HDIM + 128;
        const __half* vb = kb + 128;
        CP16(sptr(&Ks[srow*KSTH + scol]), kb + (size_t)srow*384 + scol);
        CP16(sptr(&Vs[srow*KSTH + scol]), vb + (size_t)srow*384 + scol);
        CP_COMMIT();
        CP_WAIT0();
        __syncthreads();

        // S = Q @ K^T in two 16x32 halves
        #pragma unroll
        for (int hf = 0; hf < 2; ++hf) {
            float cs[4][4];
            #pragma unroll
            for (int nt=0;nt<4;++nt)
                #pragma unroll
                for (int i=0;i<4;++i) cs[nt][i]=0.f;
            #pragma unroll
            for (int kc = 0; kc < 2; ++kc) {
                int kk = kc*16;
                unsigned bq[2][4];
                #pragma unroll
                for (int p = 0; p < 2; ++p)
                    LDSM4(bq[p][0],bq[p][1],bq[p][2],bq[p][3],
                          sptr(&Ks[(hf*32 + p*16 + rB)*KSTH + kk + cB]));
                #pragma unroll
                for (int p = 0; p < 2; ++p)
                    #pragma unroll
                    for (int q = 0; q < 2; ++q)
                        MMA_F16(cs[p*2+q], aq[kc][0],aq[kc][1],aq[kc][2],aq[kc][3],
                                bq[p][q], bq[p][q+2]);
            }
            #pragma unroll
            for (int nt = 0; nt < 4; ++nt) {
                int j = j0 + (hf*4+nt)*8 + 2*tg;
                int d00 = j   - r0; d00 = d00 < -32 ? -32 : (d00 > 32 ? 32 : d00);
                int d01 = j+1 - r0; d01 = d01 < -32 ? -32 : (d01 > 32 ? 32 : d01);
                int d10 = j   - r1; d10 = d10 < -32 ? -32 : (d10 > 32 ? 32 : d10);
                int d11 = j+1 - r1; d11 = d11 < -32 ? -32 : (d11 > 32 ? 32 : d11);
                float s0 = fminf(cs[nt][0]*SCALE + rs[d00+32], 60.f);
                float s1 = fminf(cs[nt][1]*SCALE + rs[d01+32], 60.f);
                float s2 = fminf(cs[nt][2]*SCALE + rs[d10+32], 60.f);
                float s3 = fminf(cs[nt][3]*SCALE + rs[d11+32], 60.f);
                float p0 = __expf(s0), p1 = __expf(s1), p2 = __expf(s2), p3 = __expf(s3);
                sum0 += p0 + p1;
                sum1 += p2 + p3;
                *(__half2*)&Ps[(w*16+g  )*PSTH + (hf*4+nt)*8 + 2*tg] = __floats2half2_rn(p0, p1);
                *(__half2*)&Ps[(w*16+g+8)*PSTH + (hf*4+nt)*8 + 2*tg] = __floats2half2_rn(p2, p3);
            }
        }
        __syncwarp();

        // O += P @ V  (16 x 32, k = 64 via ldmatrix.trans on Vs[j][d])
        #pragma unroll
        for (int ks = 0; ks < 4; ++ks) {
            int kk = ks*16;
            unsigned a0,a1,a2,a3;
            LDSM4(a0,a1,a2,a3, sptr(&Ps[(w*16 + rA)*PSTH + kk + cA]));
            unsigned bv[2][4];
            #pragma unroll
            for (int dg = 0; dg < 2; ++dg)
                LDSM4T(bv[dg][0],bv[dg][1],bv[dg][2],bv[dg][3],
                       sptr(&Vs[(kk + la + l8*8)*KSTH + dg*16 + l16*8]));
            #pragma unroll
            for (int dg = 0; dg < 2; ++dg)
                #pragma unroll
                for (int q = 0; q < 2; ++q)
                    MMA_F16(co[dg*2+q], a0,a1,a2,a3, bv[dg][q*2], bv[dg][q*2+1]);
        }
    }

    sum0 += __shfl_xor_sync(0xffffffffu, sum0, 1);
    sum0 += __shfl_xor_sync(0xffffffffu, sum0, 2);
    sum1 += __shfl_xor_sync(0xffffffffu, sum1, 1);
    sum1 += __shfl_xor_sync(0xffffffffu, sum1, 2);
    float inv0 = 1.f / sum0, inv1 = 1.f / sum1;

    #pragma unroll
    for (int nt2 = 0; nt2 < 4; ++nt2) {
        int d = nt2*8 + 2*tg;
        *(__half2*)(o + ((size_t)(b*LSEQ + r0))*DM + h*HDIM + d) =
            __floats2half2_rn(co[nt2][0]*inv0, co[nt2][1]*inv0);
        *(__half2*)(o + ((size_t)(b*LSEQ + r1))*DM + h*HDIM + d) =
            __floats2half2_rn(co[nt2][2]*inv1, co[nt2][3]*inv1);
    }
}

// ---------------- residual add + layernorm (f32 out + optional f16 copy) ----------------
__global__ void add_ln_kernel(const float* __restrict__ a, const float* __restrict__ bres,
                              const float* __restrict__ g, const float* __restrict__ beta,
                              float* __restrict__ out, __half* __restrict__ outh)
{
    int row = blockIdx.x;
    int t = threadIdx.x;
    float v = a[(size_t)row*DM + t] + bres[(size_t)row*DM + t];
    float s = v, s2 = v*v;
    #pragma unroll
    for (int off = 16; off; off >>= 1) {
        s  += __shfl_xor_sync(0xffffffffu, s,  off);
        s2 += __shfl_xor_sync(0xffffffffu, s2, off);
    }
    __shared__ float ws[4], ws2[4];
    int w = t >> 5;
    if ((t & 31) == 0) { ws[w] = s; ws2[w] = s2; }
    __syncthreads();
    s  = ws[0]+ws[1]+ws[2]+ws[3];
    s2 = ws2[0]+ws2[1]+ws2[2]+ws2[3];
    float mean = s * (1.f/128.f);
    float var  = s2 * (1.f/128.f) - mean*mean;
    float f = rsqrtf(var + EPSV);
    float r = (v - mean)*f*g[t] + beta[t];
    out[(size_t)row*DM + t] = r;
    if (outh) outh[(size_t)row*DM + t] = __float2half_rn(r);
}

// ---------------- im2col conv1 (pad=2), f16 out ----------------
__global__ void im2col1_kernel(const float* __restrict__ x2, __half* __restrict__ col)
{
    long long e = (long long)blockIdx.x*256 + threadIdx.x;
    if (e >= (long long)BL*640) return;
    int c = (int)(e % 640); int row = (int)(e / 640);
    int ci = c/5, k = c%5;
    int b = row >> 11, l = row & 2047;
    int lx = l + k - 2;
    float v = (lx >= 0 && lx < LSEQ) ? x2[((size_t)(b*LSEQ + lx))*DM + ci] : 0.f;
    col[e] = __float2half_rn(v);
}

// ---------------- im2col conv2 (valid), f16 out ----------------
__global__ void im2col2_kernel(const float* __restrict__ p1, __half* __restrict__ col)
{
    long long e = (long long)blockIdx.x*256 + threadIdx.x;
    if (e >= (long long)M2*640) return;
    int c = (int)(e % 640); int row = (int)(e / 640);
    int c1 = c/5, k = c%5;
    int b = row / L2OUT, l = row % L2OUT;
    col[e] = __float2half_rn(p1[((size_t)(b*L2HALF + l + k))*C1 + c1]);
}

// ---------------- BN stats ----------------
__global__ void bnstats_kernel(const float* __restrict__ y, int rows, int Cc, int rpb,
                               float* __restrict__ sum, float* __restrict__ sumsq)
{
    int c = threadIdx.x;
    int r0 = blockIdx.x * rpb;
    int r1 = r0 + rpb; if (r1 > rows) r1 = rows;
    float s = 0.f, s2 = 0.f;
    for (int r = r0; r < r1; ++r) {
        float v = y[(size_t)r*Cc + c];
        s += v; s2 += v*v;
    }
    atomicAdd(&sum[c], s);
    atomicAdd(&sumsq[c], s2);
}

__global__ void zero_kernel(float* p, int n)
{
    int i = blockIdx.x*256 + threadIdx.x;
    if (i < n) p[i] = 0.f;
}

// ---------------- BN + ReLU + maxpool(2) ----------------
__global__ void bnpool_kernel(const float* __restrict__ y1,
                              const float* __restrict__ sum, const float* __restrict__ sq,
                              const float* __restrict__ g, const float* __restrict__ bb,
                              float* __restrict__ p1)
{
    int c = threadIdx.x;
    int row2 = blockIdx.x;
    int b = row2 >> 10, l2 = row2 & 1023;
    float mean = sum[c]*(1.f/(float)BL);
    float var  = sq[c]*(1.f/(float)BL) - mean*mean;
    float f = rsqrtf(var + EPSV)*g[c];
    float v0 = (y1[((size_t)(b*LSEQ + 2*l2  ))*C1 + c] - mean)*f + bb[c];
    float v1 = (y1[((size_t)(b*LSEQ + 2*l2+1))*C1 + c] - mean)*f + bb[c];
    v0 = fmaxf(v0, 0.f); v1 = fmaxf(v1, 0.f);
    p1[(size_t)row2*C1 + c] = fmaxf(v0, v1);
}

// ---------------- BN + ReLU + global max (parallel, atomicMax) ----------------
__global__ void gmax_kernel(const float* __restrict__ y2,
                            const float* __restrict__ sum, const float* __restrict__ sq,
                            const float* __restrict__ g, const float* __restrict__ bb,
                            float* __restrict__ z)
{
    int c = threadIdx.x;
    int b = blockIdx.x;
    int part = blockIdx.y;
    float mean = sum[c]*(1.f/(float)M2);
    float var  = sq[c]*(1.f/(float)M2) - mean*mean;
    float f = rsqrtf(var + EPSV)*g[c];
    int l0 = part * 128;
    int l1 = l0 + 128; if (l1 > L2OUT) l1 = L2OUT;
    float vm = 0.f;
    for (int l = l0; l < l1; ++l) {
        float v = (y2[((size_t)(b*L2OUT + l))*C2 + c] - mean)*f + bb[c];
        vm = fmaxf(vm, v);
    }
    vm = fmaxf(vm, 0.f);
    atomicMax((int*)&z[b*C2 + c], __float_as_int(vm));
}

// ---------------- final fc ----------------
__global__ void fc_kernel(const float* __restrict__ z, const float* __restrict__ w,
                          const float* __restrict__ bias, float* __restrict__ out)
{
    int b = blockIdx.x, n = blockIdx.y;
    int t = threadIdx.x;
    float p = z[b*C2 + t] * w[n*C2 + t];
    #pragma unroll
    for (int off = 16; off; off >>= 1) p += __shfl_xor_sync(0xffffffffu, p, off);
    __shared__ float ws[8];
    if ((t & 31) == 0) ws[t >> 5] = p;
    __syncthreads();
    if (t == 0) {
        float s = 0.f;
        #pragma unroll
        for (int i = 0; i < 8; ++i) s += ws[i];
        out[b*2 + n] = s + bias[n];
    }
}

// ---------------- launch ----------------
extern "C" void kernel_launch(void* const* d_in, const int* in_sizes, int n_in,
                              void* d_out, int out_size)
{
    const int*   X    = (const int*)  d_in[0];
    const float* sa   = (const float*)d_in[1];
    const int*   ptm  = (const int*)  d_in[2];
    const float* emb  = (const float*)d_in[3];
    const float* pemb = (const float*)d_in[4];
    const float* rpe  = (const float*)d_in[5];
    const float* inw  = (const float*)d_in[6];
    const float* inb  = (const float*)d_in[7];
    const float* opw  = (const float*)d_in[8];
    const float* opb  = (const float*)d_in[9];
    const float* l1w  = (const float*)d_in[10];
    const float* l1b  = (const float*)d_in[11];
    const float* l2w  = (const float*)d_in[12];
    const float* l2b  = (const float*)d_in[13];
    const float* ln1g = (const float*)d_in[14];
    const float* ln1b = (const float*)d_in[15];
    const float* ln2g = (const float*)d_in[16];
    const float* ln2b = (const float*)d_in[17];
    const float* c1w  = (const float*)d_in[18];
    const float* c1b  = (const float*)d_in[19];
    const float* bn1g = (const float*)d_in[20];
    const float* bn1b = (const float*)d_in[21];
    const float* c2w  = (const float*)d_in[22];
    const float* c2b  = (const float*)d_in[23];
    const float* bn2g = (const float*)d_in[24];
    const float* bn2b = (const float*)d_in[25];
    const float* fcw  = (const float*)d_in[26];
    const float* fcb  = (const float*)d_in[27];
    float* out = (float*)d_out;

    float *x0,*tmp,*x1,*x2,*y1,*p1,*y2,*z,*stats;
    __half *x0h,*qkvh,*atth,*x1h,*ff1h,*colh,*wh;
    cudaGetSymbolAddress((void**)&x0,   g_x0);
    cudaGetSymbolAddress((void**)&x0h,  g_x0h);
    cudaGetSymbolAddress((void**)&qkvh, g_qkvh);
    cudaGetSymbolAddress((void**)&atth, g_atth);
    cudaGetSymbolAddress((void**)&tmp,  g_tmp);
    cudaGetSymbolAddress((void**)&x1,   g_x1);
    cudaGetSymbolAddress((void**)&x1h,  g_x1h);
    cudaGetSymbolAddress((void**)&ff1h, g_ff1h);
    cudaGetSymbolAddress((void**)&x2,   g_x2);
    cudaGetSymbolAddress((void**)&colh, g_colh);
    cudaGetSymbolAddress((void**)&y1,   g_y1);
    cudaGetSymbolAddress((void**)&p1,   g_p1);
    cudaGetSymbolAddress((void**)&y2,   g_y2);
    cudaGetSymbolAddress((void**)&z,    g_z);
    cudaGetSymbolAddress((void**)&stats,g_stats);
    cudaGetSymbolAddress((void**)&wh,   g_wh);

    // pool offsets (sizes: 49152,16384,32768,32768,81920,163840)
    __half* inwh = wh;
    __half* opwh = wh + 49152;
    __half* l1wh = wh + 65536;
    __half* l2wh = wh + 98304;
    __half* c1wh = wh + 131072;
    __half* c2wh = wh + 212992;

    // 0) weight conversions (f32 -> f16)
    f2h_kernel<<<192, 256>>>(inw, inwh, 49152);
    f2h_kernel<<<64,  256>>>(opw, opwh, 16384);
    f2h_kernel<<<128, 256>>>(l1w, l1wh, 32768);
    f2h_kernel<<<128, 256>>>(l2w, l2wh, 32768);
    f2h_kernel<<<320, 256>>>(c1w, c1wh, 81920);
    f2h_kernel<<<640, 256>>>(c2w, c2wh, 163840);   // 256*128*5 = 163840 (was the OOB bug)

    // 1) embedding + concat (f32 + f16)
    embed_kernel<<<BL, 128>>>(X, sa, ptm, emb, pemb, x0, x0h);

    // 2) qkv projection -> f16 [BL,384]
    gemm_f16<<<dim3(384/128, BL/128), 256>>>(x0h, inwh, inb, nullptr, qkvh, BL, 3*DM, DM, 0);

    // 3) attention -> f16
    attn_f16<<<dim3(LSEQ/128, HH, BB), 256>>>(qkvh, rpe, atth);

    // 4) out projection -> f32 tmp
    gemm_f16<<<dim3(DM/128, BL/128), 256>>>(atth, opwh, opb, tmp, nullptr, BL, DM, DM, 0);

    // 5) x1 = LN(x0 + attn_out) (f32 + f16)
    add_ln_kernel<<<BL, 128>>>(x0, tmp, ln1g, ln1b, x1, x1h);

    // 6) FF
    gemm_f16<<<dim3(FFD/128, BL/128), 256>>>(x1h, l1wh, l1b, nullptr, ff1h, BL, FFD, DM, 1);
    gemm_f16<<<dim3(DM/128,  BL/128), 256>>>(ff1h, l2wh, l2b, tmp, nullptr, BL, DM, FFD, 0);

    // 7) x2 = LN(x1 + ff) (f32 only)
    add_ln_kernel<<<BL, 128>>>(x1, tmp, ln2g, ln2b, x2, nullptr);

    // 8) conv1 via im2col (f16) + GEMM
    im2col1_kernel<<<(int)(((long long)BL*640 + 255)/256), 256>>>(x2, colh);
    gemm_f16<<<dim3(C1/128, BL/128), 256>>>(colh, c1wh, c1b, y1, nullptr, BL, C1, DM*KK, 0);

    // 9) zero stats + z, BN1 stats
    zero_kernel<<<3, 256>>>(stats, 2*C1 + 2*C2);
    zero_kernel<<<16, 256>>>(z, BB*C2);
    bnstats_kernel<<<128, C1>>>(y1, BL, C1, 256, stats, stats + C1);

    // 10) BN1 + ReLU + maxpool2
    bnpool_kernel<<<BB*L2HALF, C1>>>(y1, stats, stats + C1, bn1g, bn1b, p1);

    // 11) conv2 via im2col (f16) + GEMM
    im2col2_kernel<<<(int)(((long long)M2*640 + 255)/256), 256>>>(p1, colh);
    gemm_f16<<<dim3(C2/128, (M2+127)/128), 256>>>(colh, c2wh, c2b, y2, nullptr, M2, C2, C1*KK, 0);

    // 12) BN2 stats
    bnstats_kernel<<<128, C2>>>(y2, M2, C2, 128, stats + 2*C1, stats + 2*C1 + C2);

    // 13) BN2 + ReLU + global max
    gmax_kernel<<<dim3(BB, 8), C2>>>(y2, stats + 2*C1, stats + 2*C1 + C2, bn2g, bn2b, z);

    // 14) fc
    fc_kernel<<<dim3(BB, 2), 256>>>(z, fcw, fcb, out);
}

// round 9
// speedup vs baseline: 4.9823x; 1.0999x over previous
#include <cuda_runtime.h>
#include <cuda_fp16.h>
#include <math.h>

// ---------------- problem constants ----------------
#define BB    16
#define LSEQ  2048
#define BL    (BB*LSEQ)        // 32768
#define DM    128
#define HH    4
#define HDIM  32
#define FFD   256
#define C1    128
#define C2    256
#define KK    5
#define L2HALF 1024
#define L2OUT  1020
#define M2    (BB*L2OUT)       // 16320
#define EPSV  1e-5f
#define SCALE 0.17677669529663687f

// ---------------- scratch ----------------
__device__ float  g_x0 [BL*DM];
__device__ __half g_x0h[BL*DM];
__device__ __half g_qkvh[BL*3*DM];
__device__ __half g_atth[BL*DM];
__device__ float  g_tmp[BL*DM];
__device__ float  g_x1 [BL*DM];
__device__ __half g_x1h[BL*DM];
__device__ __half g_ff1h[BL*FFD];
__device__ float  g_x2 [BL*DM];
__device__ __half g_colh[BL*640];
__device__ float  g_y1 [BL*C1];
__device__ float  g_p1 [BB*L2HALF*C1];
__device__ float  g_y2 [M2*C2];
__device__ float  g_z  [BB*C2];
__device__ float  g_stats[2*C1 + 2*C2];
// fp16 weight pool: inw(49152) opw(16384) l1w(32768) l2w(32768) c1w(81920) c2w(163840) = 376832
__device__ __half g_wh[376832];

// ---------------- helpers ----------------
__device__ __forceinline__ unsigned sptr(const void* p) {
    return (unsigned)__cvta_generic_to_shared(p);
}
__device__ __forceinline__ unsigned h2u(__half2 h) {
    unsigned u; asm("mov.b32 %0, %1;" : "=r"(u) : "r"(*(unsigned*)&h)); return u;
}
#define CP16(dst, src) asm volatile("cp.async.cg.shared.global [%0], [%1], 16;" :: "r"(dst), "l"(src))
#define CP_COMMIT()    asm volatile("cp.async.commit_group;")
#define CP_WAIT1()     asm volatile("cp.async.wait_group 1;")
#define CP_WAIT0()     asm volatile("cp.async.wait_group 0;")

#define MMA_F16(C, a0,a1,a2,a3, b0,b1) \
    asm volatile("mma.sync.aligned.m16n8k16.row.col.f32.f16.f16.f32 " \
                 "{%0,%1,%2,%3},{%4,%5,%6,%7},{%8,%9},{%0,%1,%2,%3};" \
                 : "+f"((C)[0]),"+f"((C)[1]),"+f"((C)[2]),"+f"((C)[3]) \
                 : "r"(a0),"r"(a1),"r"(a2),"r"(a3),"r"(b0),"r"(b1))

#define LDSM4(R0,R1,R2,R3, A) \
    asm volatile("ldmatrix.sync.aligned.m8n8.x4.shared.b16 {%0,%1,%2,%3}, [%4];" \
                 : "=r"(R0),"=r"(R1),"=r"(R2),"=r"(R3) : "r"(A))
#define LDSM4T(R0,R1,R2,R3, A) \
    asm volatile("ldmatrix.sync.aligned.m8n8.x4.trans.shared.b16 {%0,%1,%2,%3}, [%4];" \
                 : "=r"(R0),"=r"(R1),"=r"(R2),"=r"(R3) : "r"(A))

// ---------------- merged f32 -> f16 weight conversion ----------------
__global__ void f2h_all(const float* __restrict__ s0, const float* __restrict__ s1,
                        const float* __restrict__ s2, const float* __restrict__ s3,
                        const float* __restrict__ s4, const float* __restrict__ s5,
                        __half* __restrict__ dst)
{
    int i = blockIdx.x*256 + threadIdx.x;
    const float* src; int off;
    if      (i < 49152)  { src = s0; off = 0; }
    else if (i < 65536)  { src = s1; off = 49152; }
    else if (i < 98304)  { src = s2; off = 65536; }
    else if (i < 131072) { src = s3; off = 98304; }
    else if (i < 212992) { src = s4; off = 131072; }
    else if (i < 376832) { src = s5; off = 212992; }
    else return;
    dst[i] = __float2half_rn(src[i - off]);
}

// ---------------- embed (writes f32 + f16) ----------------
__global__ void embed_kernel(const int* __restrict__ X, const float* __restrict__ sa,
                             const int* __restrict__ ptm,
                             const float* __restrict__ emb, const float* __restrict__ pemb,
                             float* __restrict__ x0, __half* __restrict__ x0h)
{
    int row = blockIdx.x;
    int t = threadIdx.x;
    float v;
    if (t < 120) v = emb[X[row]*120 + t] * sa[row];
    else         v = pemb[ptm[row]*8 + (t-120)];
    x0[(size_t)row*DM + t] = v;
    x0h[(size_t)row*DM + t] = __float2half_rn(v);
}

// ---------------- fp16 GEMM: 128x128 tile, 3-stage cp.async + ldmatrix ----------------
#define GSTH 40
__global__ __launch_bounds__(256,2) void gemm_f16(const __half* __restrict__ A,
                                                  const __half* __restrict__ W,
                                                  const float* __restrict__ bias,
                                                  float* __restrict__ Cf,
                                                  __half* __restrict__ Ch,
                                                  int M, int N, int K, int relu)
{
    __shared__ __align__(16) __half As[3][128*GSTH];
    __shared__ __align__(16) __half Bs[3][128*GSTH];
    int tid = threadIdx.x;
    int w = tid >> 5, lane = tid & 31, g = lane >> 2, tg = lane & 3;
    int wm = w & 3, wn = w >> 2;
    int row0 = blockIdx.y * 128, col0 = blockIdx.x * 128;

    int la = lane & 7, l8 = (lane >> 3) & 1, l16 = (lane >> 4) & 1;
    int rA = la + l8*8, cA = l16*8;
    int rB = la + l8*8, cB = l16*8;

    int lr = tid >> 2, lc8 = (tid & 3) * 8;
    int ar0 = row0 + lr;      if (ar0 > M-1) ar0 = M-1;
    int ar1 = row0 + lr + 64; if (ar1 > M-1) ar1 = M-1;
    const __half* ap0 = A + (size_t)ar0*K + lc8;
    const __half* ap1 = A + (size_t)ar1*K + lc8;
    const __half* wp0 = W + (size_t)(col0 + lr)*K + lc8;
    const __half* wp1 = W + (size_t)(col0 + lr + 64)*K + lc8;

    float c[2][8][4];
    #pragma unroll
    for (int mt=0; mt<2; ++mt)
        #pragma unroll
        for (int nt=0; nt<8; ++nt)
            #pragma unroll
            for (int i=0;i<4;++i) c[mt][nt][i]=0.f;

    int kt = K >> 5;

    #define GLOAD(s, k0) do { \
        CP16(sptr(&As[s][lr*GSTH + lc8]),      ap0 + (k0)); \
        CP16(sptr(&As[s][(lr+64)*GSTH + lc8]), ap1 + (k0)); \
        CP16(sptr(&Bs[s][lr*GSTH + lc8]),      wp0 + (k0)); \
        CP16(sptr(&Bs[s][(lr+64)*GSTH + lc8]), wp1 + (k0)); \
        CP_COMMIT(); \
    } while (0)

    GLOAD(0, 0);
    GLOAD(1, 32);

    for (int t = 0; t < kt; ++t) {
        int s = t % 3;
        CP_WAIT1();
        __syncthreads();
        if (t + 2 < kt) { GLOAD((t+2)%3, (t+2)*32); }
        else            { CP_COMMIT(); }

        #pragma unroll
        for (int ks = 0; ks < 2; ++ks) {
            int kk = ks*16;
            unsigned a[2][4], bq[4][4];
            #pragma unroll
            for (int mt = 0; mt < 2; ++mt)
                LDSM4(a[mt][0],a[mt][1],a[mt][2],a[mt][3],
                      sptr(&As[s][(wm*32 + mt*16 + rA)*GSTH + kk + cA]));
            #pragma unroll
            for (int p = 0; p < 4; ++p)
                LDSM4(bq[p][0],bq[p][1],bq[p][2],bq[p][3],
                      sptr(&Bs[s][(wn*64 + p*16 + rB)*GSTH + kk + cB]));
            #pragma unroll
            for (int p = 0; p < 4; ++p)
                #pragma unroll
                for (int q = 0; q < 2; ++q) {
                    int nt = p*2 + q;
                    MMA_F16(c[0][nt], a[0][0],a[0][1],a[0][2],a[0][3], bq[p][q], bq[p][q+2]);
                    MMA_F16(c[1][nt], a[1][0],a[1][1],a[1][2],a[1][3], bq[p][q], bq[p][q+2]);
                }
        }
    }
    #undef GLOAD

    #pragma unroll
    for (int mt = 0; mt < 2; ++mt) {
        int r0 = row0 + wm*32 + mt*16 + g;
        #pragma unroll
        for (int nt = 0; nt < 8; ++nt) {
            int cc = col0 + wn*64 + nt*8 + 2*tg;
            float b0v = bias[cc], b1v = bias[cc+1];
            float v0 = c[mt][nt][0] + b0v, v1 = c[mt][nt][1] + b1v;
            float v2 = c[mt][nt][2] + b0v, v3 = c[mt][nt][3] + b1v;
            if (relu) { v0=fmaxf(v0,0.f); v1=fmaxf(v1,0.f); v2=fmaxf(v2,0.f); v3=fmaxf(v3,0.f); }
            if (Cf) {
                if (r0 < M)     { float2 s2={v0,v1}; *(float2*)(Cf + (size_t)r0*N + cc) = s2; }
                if (r0 + 8 < M) { float2 s2={v2,v3}; *(float2*)(Cf + (size_t)(r0+8)*N + cc) = s2; }
            }
            if (Ch) {
                if (r0 < M)     *(__half2*)(Ch + (size_t)r0*N + cc)     = __floats2half2_rn(v0, v1);
                if (r0 + 8 < M) *(__half2*)(Ch + (size_t)(r0+8)*N + cc) = __floats2half2_rn(v2, v3);
            }
        }
    }
}

// ---------------- fp16 flash attention: register-resident P + double-buffered K/V ----------------
// grid (L/128, H, B), block 256 (8 warps); each warp owns 16 query rows x 64 keys.
#define KSTH 40
__global__ __launch_bounds__(256,2) void attn_f16(const __half* __restrict__ qkv,
                                                  const float* __restrict__ rpe,
                                                  __half* __restrict__ o)
{
    __shared__ __align__(16) __half Ks[2][64*KSTH];   // [j][d]
    __shared__ __align__(16) __half Vs[2][64*KSTH];   // [j][d]
    __shared__ float rs[65];

    int tid = threadIdx.x;
    int w = tid >> 5, lane = tid & 31, g = lane >> 2, tg = lane & 3;
    int b = blockIdx.z, h = blockIdx.y;
    int q0 = blockIdx.x * 128;
    if (tid < 65) rs[tid] = rpe[tid*HH + h];

    int la = lane & 7, l8 = (lane >> 3) & 1, l16 = (lane >> 4) & 1;
    int rB = la + l8*8, cB = l16*8;

    int r0 = q0 + w*16 + g, r1 = r0 + 8;

    // persistent Q fragments
    unsigned aq[2][4];
    {
        const __half* qb = qkv + (size_t)(b*LSEQ)*384 + h*HDIM;
        #pragma unroll
        for (int kc = 0; kc < 2; ++kc) {
            int k = kc*16;
            aq[kc][0] = *(const unsigned*)(qb + (size_t)r0*384 + k + 2*tg);
            aq[kc][1] = *(const unsigned*)(qb + (size_t)r1*384 + k + 2*tg);
            aq[kc][2] = *(const unsigned*)(qb + (size_t)r0*384 + k + 2*tg + 8);
            aq[kc][3] = *(const unsigned*)(qb + (size_t)r1*384 + k + 2*tg + 8);
        }
    }

    float co[4][4];
    #pragma unroll
    for (int nt=0;nt<4;++nt)
        #pragma unroll
        for (int i=0;i<4;++i) co[nt][i]=0.f;
    float sum0 = 0.f, sum1 = 0.f;

    int srow = tid >> 2, scol = (tid & 3) * 8;
    const __half* kvbase = qkv + (size_t)(b*LSEQ)*384 + h*HDIM + 128;

    #define STAGE(s, j0) do { \
        const __half* kb_ = kvbase + (size_t)((j0) + srow)*384; \
        CP16(sptr(&Ks[s][srow*KSTH + scol]), kb_ + scol); \
        CP16(sptr(&Vs[s][srow*KSTH + scol]), kb_ + 128 + scol); \
        CP_COMMIT(); \
    } while (0)

    STAGE(0, 0);

    for (int jt = 0; jt < LSEQ/64; ++jt) {
        int s = jt & 1;
        if (jt + 1 < LSEQ/64) { STAGE(s^1, (jt+1)*64); CP_WAIT1(); }
        else                  { CP_WAIT0(); }
        __syncthreads();

        // S = Q @ K^T : 16 x 64 per warp (8 n8-tiles)
        float cs[8][4];
        #pragma unroll
        for (int nt=0;nt<8;++nt)
            #pragma unroll
            for (int i=0;i<4;++i) cs[nt][i]=0.f;
        #pragma unroll
        for (int kc = 0; kc < 2; ++kc) {
            int kk = kc*16;
            unsigned bq[4][4];
            #pragma unroll
            for (int p = 0; p < 4; ++p)
                LDSM4(bq[p][0],bq[p][1],bq[p][2],bq[p][3],
                      sptr(&Ks[s][(p*16 + rB)*KSTH + kk + cB]));
            #pragma unroll
            for (int p = 0; p < 4; ++p)
                #pragma unroll
                for (int q = 0; q < 2; ++q)
                    MMA_F16(cs[p*2+q], aq[kc][0],aq[kc][1],aq[kc][2],aq[kc][3],
                            bq[p][q], bq[p][q+2]);
        }

        // softmax in registers -> pack P directly as A fragments
        int j0 = jt*64;
        unsigned ap[4][4];
        #pragma unroll
        for (int nt = 0; nt < 8; ++nt) {
            int j = j0 + nt*8 + 2*tg;
            int d00 = j   - r0; d00 = d00 < -32 ? -32 : (d00 > 32 ? 32 : d00);
            int d01 = j+1 - r0; d01 = d01 < -32 ? -32 : (d01 > 32 ? 32 : d01);
            int d10 = j   - r1; d10 = d10 < -32 ? -32 : (d10 > 32 ? 32 : d10);
            int d11 = j+1 - r1; d11 = d11 < -32 ? -32 : (d11 > 32 ? 32 : d11);
            float s0 = fminf(cs[nt][0]*SCALE + rs[d00+32], 60.f);
            float s1 = fminf(cs[nt][1]*SCALE + rs[d01+32], 60.f);
            float s2 = fminf(cs[nt][2]*SCALE + rs[d10+32], 60.f);
            float s3 = fminf(cs[nt][3]*SCALE + rs[d11+32], 60.f);
            float p0 = __expf(s0), p1 = __expf(s1), p2 = __expf(s2), p3 = __expf(s3);
            sum0 += p0 + p1;
            sum1 += p2 + p3;
            // A-fragment packing: tile pair (2ks, 2ks+1) -> regs (a0,a1) , (a2,a3)
            int ks = nt >> 1, hi = nt & 1;
            ap[ks][hi*2+0] = h2u(__floats2half2_rn(p0, p1));
            ap[ks][hi*2+1] = h2u(__floats2half2_rn(p2, p3));
        }

        // O += P @ V  (16 x 32, k = 64, V via ldmatrix.trans on Vs[j][d])
        #pragma unroll
        for (int ks = 0; ks < 4; ++ks) {
            int kk = ks*16;
            unsigned bv[2][4];
            #pragma unroll
            for (int dg = 0; dg < 2; ++dg)
                LDSM4T(bv[dg][0],bv[dg][1],bv[dg][2],bv[dg][3],
                       sptr(&Vs[s][(kk + la + l8*8)*KSTH + dg*16 + l16*8]));
            #pragma unroll
            for (int dg = 0; dg < 2; ++dg)
                #pragma unroll
                for (int q = 0; q < 2; ++q)
                    MMA_F16(co[dg*2+q], ap[ks][0],ap[ks][1],ap[ks][2],ap[ks][3],
                            bv[dg][q*2], bv[dg][q*2+1]);
        }
        __syncthreads();
    }
    #undef STAGE

    sum0 += __shfl_xor_sync(0xffffffffu, sum0, 1);
    sum0 += __shfl_xor_sync(0xffffffffu, sum0, 2);
    sum1 += __shfl_xor_sync(0xffffffffu, sum1, 1);
    sum1 += __shfl_xor_sync(0xffffffffu, sum1, 2);
    float inv0 = 1.f / sum0, inv1 = 1.f / sum1;

    #pragma unroll
    for (int nt2 = 0; nt2 < 4; ++nt2) {
        int d = nt2*8 + 2*tg;
        *(__half2*)(o + ((size_t)(b*LSEQ + r0))*DM + h*HDIM + d) =
            __floats2half2_rn(co[nt2][0]*inv0, co[nt2][1]*inv0);
        *(__half2*)(o + ((size_t)(b*LSEQ + r1))*DM + h*HDIM + d) =
            __floats2half2_rn(co[nt2][2]*inv1, co[nt2][3]*inv1);
    }
}

// ---------------- residual add + layernorm (f32 out + optional f16 copy) ----------------
__global__ void add_ln_kernel(const float* __restrict__ a, const float* __restrict__ bres,
                              const float* __restrict__ g, const float* __restrict__ beta,
                              float* __restrict__ out, __half* __restrict__ outh)
{
    int row = blockIdx.x;
    int t = threadIdx.x;
    float v = a[(size_t)row*DM + t] + bres[(size_t)row*DM + t];
    float s = v, s2 = v*v;
    #pragma unroll
    for (int off = 16; off; off >>= 1) {
        s  += __shfl_xor_sync(0xffffffffu, s,  off);
        s2 += __shfl_xor_sync(0xffffffffu, s2, off);
    }
    __shared__ float ws[4], ws2[4];
    int w = t >> 5;
    if ((t & 31) == 0) { ws[w] = s; ws2[w] = s2; }
    __syncthreads();
    s  = ws[0]+ws[1]+ws[2]+ws[3];
    s2 = ws2[0]+ws2[1]+ws2[2]+ws2[3];
    float mean = s * (1.f/128.f);
    float var  = s2 * (1.f/128.f) - mean*mean;
    float f = rsqrtf(var + EPSV);
    float r = (v - mean)*f*g[t] + beta[t];
    out[(size_t)row*DM + t] = r;
    if (outh) outh[(size_t)row*DM + t] = __float2half_rn(r);
}

// ---------------- im2col conv1 (pad=2), f16 out ----------------
__global__ void im2col1_kernel(const float* __restrict__ x2, __half* __restrict__ col)
{
    long long e = (long long)blockIdx.x*256 + threadIdx.x;
    if (e >= (long long)BL*640) return;
    int c = (int)(e % 640); int row = (int)(e / 640);
    int ci = c/5, k = c%5;
    int b = row >> 11, l = row & 2047;
    int lx = l + k - 2;
    float v = (lx >= 0 && lx < LSEQ) ? x2[((size_t)(b*LSEQ + lx))*DM + ci] : 0.f;
    col[e] = __float2half_rn(v);
}

// ---------------- im2col conv2 (valid), f16 out ----------------
__global__ void im2col2_kernel(const float* __restrict__ p1, __half* __restrict__ col)
{
    long long e = (long long)blockIdx.x*256 + threadIdx.x;
    if (e >= (long long)M2*640) return;
    int c = (int)(e % 640); int row = (int)(e / 640);
    int c1 = c/5, k = c%5;
    int b = row / L2OUT, l = row % L2OUT;
    col[e] = __float2half_rn(p1[((size_t)(b*L2HALF + l + k))*C1 + c1]);
}

// ---------------- BN stats ----------------
__global__ void bnstats_kernel(const float* __restrict__ y, int rows, int Cc, int rpb,
                               float* __restrict__ sum, float* __restrict__ sumsq)
{
    int c = threadIdx.x;
    int r0 = blockIdx.x * rpb;
    int r1 = r0 + rpb; if (r1 > rows) r1 = rows;
    float s = 0.f, s2 = 0.f;
    for (int r = r0; r < r1; ++r) {
        float v = y[(size_t)r*Cc + c];
        s += v; s2 += v*v;
    }
    atomicAdd(&sum[c], s);
    atomicAdd(&sumsq[c], s2);
}

__global__ void zero_kernel(float* p, int n)
{
    int i = blockIdx.x*256 + threadIdx.x;
    if (i < n) p[i] = 0.f;
}

// ---------------- BN + ReLU + maxpool(2) ----------------
__global__ void bnpool_kernel(const float* __restrict__ y1,
                              const float* __restrict__ sum, const float* __restrict__ sq,
                              const float* __restrict__ g, const float* __restrict__ bb,
                              float* __restrict__ p1)
{
    int c = threadIdx.x;
    int row2 = blockIdx.x;
    int b = row2 >> 10, l2 = row2 & 1023;
    float mean = sum[c]*(1.f/(float)BL);
    float var  = sq[c]*(1.f/(float)BL) - mean*mean;
    float f = rsqrtf(var + EPSV)*g[c];
    float v0 = (y1[((size_t)(b*LSEQ + 2*l2  ))*C1 + c] - mean)*f + bb[c];
    float v1 = (y1[((size_t)(b*LSEQ + 2*l2+1))*C1 + c] - mean)*f + bb[c];
    v0 = fmaxf(v0, 0.f); v1 = fmaxf(v1, 0.f);
    p1[(size_t)row2*C1 + c] = fmaxf(v0, v1);
}

// ---------------- BN + ReLU + global max (parallel, atomicMax) ----------------
__global__ void gmax_kernel(const float* __restrict__ y2,
                            const float* __restrict__ sum, const float* __restrict__ sq,
                            const float* __restrict__ g, const float* __restrict__ bb,
                            float* __restrict__ z)
{
    int c = threadIdx.x;
    int b = blockIdx.x;
    int part = blockIdx.y;
    float mean = sum[c]*(1.f/(float)M2);
    float var  = sq[c]*(1.f/(float)M2) - mean*mean;
    float f = rsqrtf(var + EPSV)*g[c];
    int l0 = part * 128;
    int l1 = l0 + 128; if (l1 > L2OUT) l1 = L2OUT;
    float vm = 0.f;
    for (int l = l0; l < l1; ++l) {
        float v = (y2[((size_t)(b*L2OUT + l))*C2 + c] - mean)*f + bb[c];
        vm = fmaxf(vm, v);
    }
    vm = fmaxf(vm, 0.f);
    atomicMax((int*)&z[b*C2 + c], __float_as_int(vm));
}

// ---------------- final fc ----------------
__global__ void fc_kernel(const float* __restrict__ z, const float* __restrict__ w,
                          const float* __restrict__ bias, float* __restrict__ out)
{
    int b = blockIdx.x, n = blockIdx.y;
    int t = threadIdx.x;
    float p = z[b*C2 + t] * w[n*C2 + t];
    #pragma unroll
    for (int off = 16; off; off >>= 1) p += __shfl_xor_sync(0xffffffffu, p, off);
    __shared__ float ws[8];
    if ((t & 31) == 0) ws[t >> 5] = p;
    __syncthreads();
    if (t == 0) {
        float s = 0.f;
        #pragma unroll
        for (int i = 0; i < 8; ++i) s += ws[i];
        out[b*2 + n] = s + bias[n];
    }
}

// ---------------- launch ----------------
extern "C" void kernel_launch(void* const* d_in, const int* in_sizes, int n_in,
                              void* d_out, int out_size)
{
    const int*   X    = (const int*)  d_in[0];
    const float* sa   = (const float*)d_in[1];
    const int*   ptm  = (const int*)  d_in[2];
    const float* emb  = (const float*)d_in[3];
    const float* pemb = (const float*)d_in[4];
    const float* rpe  = (const float*)d_in[5];
    const float* inw  = (const float*)d_in[6];
    const float* inb  = (const float*)d_in[7];
    const float* opw  = (const float*)d_in[8];
    const float* opb  = (const float*)d_in[9];
    const float* l1w  = (const float*)d_in[10];
    const float* l1b  = (const float*)d_in[11];
    const float* l2w  = (const float*)d_in[12];
    const float* l2b  = (const float*)d_in[13];
    const float* ln1g = (const float*)d_in[14];
    const float* ln1b = (const float*)d_in[15];
    const float* ln2g = (const float*)d_in[16];
    const float* ln2b = (const float*)d_in[17];
    const float* c1w  = (const float*)d_in[18];
    const float* c1b  = (const float*)d_in[19];
    const float* bn1g = (const float*)d_in[20];
    const float* bn1b = (const float*)d_in[21];
    const float* c2w  = (const float*)d_in[22];
    const float* c2b  = (const float*)d_in[23];
    const float* bn2g = (const float*)d_in[24];
    const float* bn2b = (const float*)d_in[25];
    const float* fcw  = (const float*)d_in[26];
    const float* fcb  = (const float*)d_in[27];
    float* out = (float*)d_out;

    float *x0,*tmp,*x1,*x2,*y1,*p1,*y2,*z,*stats;
    __half *x0h,*qkvh,*atth,*x1h,*ff1h,*colh,*wh;
    cudaGetSymbolAddress((void**)&x0,   g_x0);
    cudaGetSymbolAddress((void**)&x0h,  g_x0h);
    cudaGetSymbolAddress((void**)&qkvh, g_qkvh);
    cudaGetSymbolAddress((void**)&atth, g_atth);
    cudaGetSymbolAddress((void**)&tmp,  g_tmp);
    cudaGetSymbolAddress((void**)&x1,   g_x1);
    cudaGetSymbolAddress((void**)&x1h,  g_x1h);
    cudaGetSymbolAddress((void**)&ff1h, g_ff1h);
    cudaGetSymbolAddress((void**)&x2,   g_x2);
    cudaGetSymbolAddress((void**)&colh, g_colh);
    cudaGetSymbolAddress((void**)&y1,   g_y1);
    cudaGetSymbolAddress((void**)&p1,   g_p1);
    cudaGetSymbolAddress((void**)&y2,   g_y2);
    cudaGetSymbolAddress((void**)&z,    g_z);
    cudaGetSymbolAddress((void**)&stats,g_stats);
    cudaGetSymbolAddress((void**)&wh,   g_wh);

    __half* inwh = wh;
    __half* opwh = wh + 49152;
    __half* l1wh = wh + 65536;
    __half* l2wh = wh + 98304;
    __half* c1wh = wh + 131072;
    __half* c2wh = wh + 212992;

    // 0) merged weight conversion (f32 -> f16), one launch
    f2h_all<<<(376832 + 255)/256, 256>>>(inw, opw, l1w, l2w, c1w, c2w, wh);

    // 1) embedding + concat (f32 + f16)
    embed_kernel<<<BL, 128>>>(X, sa, ptm, emb, pemb, x0, x0h);

    // 2) qkv projection -> f16 [BL,384]
    gemm_f16<<<dim3(384/128, BL/128), 256>>>(x0h, inwh, inb, nullptr, qkvh, BL, 3*DM, DM, 0);

    // 3) attention -> f16
    attn_f16<<<dim3(LSEQ/128, HH, BB), 256>>>(qkvh, rpe, atth);

    // 4) out projection -> f32 tmp
    gemm_f16<<<dim3(DM/128, BL/128), 256>>>(atth, opwh, opb, tmp, nullptr, BL, DM, DM, 0);

    // 5) x1 = LN(x0 + attn_out) (f32 + f16)
    add_ln_kernel<<<BL, 128>>>(x0, tmp, ln1g, ln1b, x1, x1h);

    // 6) FF
    gemm_f16<<<dim3(FFD/128, BL/128), 256>>>(x1h, l1wh, l1b, nullptr, ff1h, BL, FFD, DM, 1);
    gemm_f16<<<dim3(DM/128,  BL/128), 256>>>(ff1h, l2wh, l2b, tmp, nullptr, BL, DM, FFD, 0);

    // 7) x2 = LN(x1 + ff) (f32 only)
    add_ln_kernel<<<BL, 128>>>(x1, tmp, ln2g, ln2b, x2, nullptr);

    // 8) conv1 via im2col (f16) + GEMM
    im2col1_kernel<<<(int)(((long long)BL*640 + 255)/256), 256>>>(x2, colh);
    gemm_f16<<<dim3(C1/128, BL/128), 256>>>(colh, c1wh, c1b, y1, nullptr, BL, C1, DM*KK, 0);

    // 9) zero stats + z, BN1 stats
    zero_kernel<<<3, 256>>>(stats, 2*C1 + 2*C2);
    zero_kernel<<<16, 256>>>(z, BB*C2);
    bnstats_kernel<<<128, C1>>>(y1, BL, C1, 256, stats, stats + C1);

    // 10) BN1 + ReLU + maxpool2
    bnpool_kernel<<<BB*L2HALF, C1>>>(y1, stats, stats + C1, bn1g, bn1b, p1);

    // 11) conv2 via im2col (f16) + GEMM
    im2col2_kernel<<<(int)(((long long)M2*640 + 255)/256), 256>>>(p1, colh);
    gemm_f16<<<dim3(C2/128, (M2+127)/128), 256>>>(colh, c2wh, c2b, y2, nullptr, M2, C2, C1*KK, 0);

    // 12) BN2 stats
    bnstats_kernel<<<128, C2>>>(y2, M2, C2, 128, stats + 2*C1, stats + 2*C1 + C2);

    // 13) BN2 + ReLU + global max
    gmax_kernel<<<dim3(BB, 8), C2>>>(y2, stats + 2*C1, stats + 2*C1 + C2, bn2g, bn2b, z);

    // 14) fc
    fc_kernel<<<dim3(BB, 2), 256>>>(z, fcw, fcb, out);
}

// round 10
// speedup vs baseline: 5.1800x; 1.0397x over previous
#include <cuda_runtime.h>
#include <cuda_fp16.h>
#include <math.h>

// ---------------- problem constants ----------------
#define BB    16
#define LSEQ  2048
#define BL    (BB*LSEQ)        // 32768
#define DM    128
#define HH    4
#define HDIM  32
#define FFD   256
#define C1    128
#define C2    256
#define KK    5
#define L2HALF 1024
#define L2OUT  1020
#define M2    (BB*L2OUT)       // 16320
#define EPSV  1e-5f
#define SCALE 0.17677669529663687f
#define SCALE2 0.25501650f     // SCALE * log2(e)

// ---------------- scratch ----------------
__device__ float  g_x0 [BL*DM];
__device__ __half g_x0h[BL*DM];
__device__ __half g_qkvh[BL*3*DM];
__device__ __half g_atth[BL*DM];
__device__ float  g_tmp[BL*DM];
__device__ float  g_x1 [BL*DM];
__device__ __half g_x1h[BL*DM];
__device__ __half g_ff1h[BL*FFD];
__device__ float  g_x2 [BL*DM];
__device__ __half g_colh[BL*640];
__device__ float  g_y1 [BL*C1];
__device__ float  g_p1 [BB*L2HALF*C1];
__device__ float  g_y2 [M2*C2];
__device__ float  g_z  [BB*C2];
__device__ float  g_stats[2*C1 + 2*C2];
// fp16 weight pool: inw(49152) opw(16384) l1w(32768) l2w(32768) c1w(81920) c2w(163840) = 376832
__device__ __half g_wh[376832];

// ---------------- helpers ----------------
__device__ __forceinline__ unsigned sptr(const void* p) {
    return (unsigned)__cvta_generic_to_shared(p);
}
__device__ __forceinline__ unsigned h2u(__half2 h) {
    unsigned u; asm("mov.b32 %0, %1;" : "=r"(u) : "r"(*(unsigned*)&h)); return u;
}
#define CP16(dst, src) asm volatile("cp.async.cg.shared.global [%0], [%1], 16;" :: "r"(dst), "l"(src))
#define CP_COMMIT()    asm volatile("cp.async.commit_group;")
#define CP_WAIT1()     asm volatile("cp.async.wait_group 1;")
#define CP_WAIT0()     asm volatile("cp.async.wait_group 0;")

#define MMA_F16(C, a0,a1,a2,a3, b0,b1) \
    asm volatile("mma.sync.aligned.m16n8k16.row.col.f32.f16.f16.f32 " \
                 "{%0,%1,%2,%3},{%4,%5,%6,%7},{%8,%9},{%0,%1,%2,%3};" \
                 : "+f"((C)[0]),"+f"((C)[1]),"+f"((C)[2]),"+f"((C)[3]) \
                 : "r"(a0),"r"(a1),"r"(a2),"r"(a3),"r"(b0),"r"(b1))

#define LDSM4(R0,R1,R2,R3, A) \
    asm volatile("ldmatrix.sync.aligned.m8n8.x4.shared.b16 {%0,%1,%2,%3}, [%4];" \
                 : "=r"(R0),"=r"(R1),"=r"(R2),"=r"(R3) : "r"(A))
#define LDSM4T(R0,R1,R2,R3, A) \
    asm volatile("ldmatrix.sync.aligned.m8n8.x4.trans.shared.b16 {%0,%1,%2,%3}, [%4];" \
                 : "=r"(R0),"=r"(R1),"=r"(R2),"=r"(R3) : "r"(A))

// ---------------- merged f32 -> f16 weight conversion ----------------
__global__ void f2h_all(const float* __restrict__ s0, const float* __restrict__ s1,
                        const float* __restrict__ s2, const float* __restrict__ s3,
                        const float* __restrict__ s4, const float* __restrict__ s5,
                        __half* __restrict__ dst)
{
    int i = blockIdx.x*256 + threadIdx.x;
    const float* src; int off;
    if      (i < 49152)  { src = s0; off = 0; }
    else if (i < 65536)  { src = s1; off = 49152; }
    else if (i < 98304)  { src = s2; off = 65536; }
    else if (i < 131072) { src = s3; off = 98304; }
    else if (i < 212992) { src = s4; off = 131072; }
    else if (i < 376832) { src = s5; off = 212992; }
    else return;
    dst[i] = __float2half_rn(src[i - off]);
}

// ---------------- embed (writes f32 + f16) ----------------
__global__ void embed_kernel(const int* __restrict__ X, const float* __restrict__ sa,
                             const int* __restrict__ ptm,
                             const float* __restrict__ emb, const float* __restrict__ pemb,
                             float* __restrict__ x0, __half* __restrict__ x0h)
{
    int row = blockIdx.x;
    int t = threadIdx.x;
    float v;
    if (t < 120) v = emb[X[row]*120 + t] * sa[row];
    else         v = pemb[ptm[row]*8 + (t-120)];
    x0[(size_t)row*DM + t] = v;
    x0h[(size_t)row*DM + t] = __float2half_rn(v);
}

// ---------------- fp16 GEMM: 128x128 tile, 3-stage cp.async + ldmatrix ----------------
#define GSTH 40
__global__ __launch_bounds__(256,2) void gemm_f16(const __half* __restrict__ A,
                                                  const __half* __restrict__ W,
                                                  const float* __restrict__ bias,
                                                  float* __restrict__ Cf,
                                                  __half* __restrict__ Ch,
                                                  int M, int N, int K, int relu)
{
    __shared__ __align__(16) __half As[3][128*GSTH];
    __shared__ __align__(16) __half Bs[3][128*GSTH];
    int tid = threadIdx.x;
    int w = tid >> 5, lane = tid & 31, g = lane >> 2, tg = lane & 3;
    int wm = w & 3, wn = w >> 2;
    int row0 = blockIdx.y * 128, col0 = blockIdx.x * 128;

    int la = lane & 7, l8 = (lane >> 3) & 1, l16 = (lane >> 4) & 1;
    int rA = la + l8*8, cA = l16*8;
    int rB = la + l8*8, cB = l16*8;

    int lr = tid >> 2, lc8 = (tid & 3) * 8;
    int ar0 = row0 + lr;      if (ar0 > M-1) ar0 = M-1;
    int ar1 = row0 + lr + 64; if (ar1 > M-1) ar1 = M-1;
    const __half* ap0 = A + (size_t)ar0*K + lc8;
    const __half* ap1 = A + (size_t)ar1*K + lc8;
    const __half* wp0 = W + (size_t)(col0 + lr)*K + lc8;
    const __half* wp1 = W + (size_t)(col0 + lr + 64)*K + lc8;

    float c[2][8][4];
    #pragma unroll
    for (int mt=0; mt<2; ++mt)
        #pragma unroll
        for (int nt=0; nt<8; ++nt)
            #pragma unroll
            for (int i=0;i<4;++i) c[mt][nt][i]=0.f;

    int kt = K >> 5;

    #define GLOAD(s, k0) do { \
        CP16(sptr(&As[s][lr*GSTH + lc8]),      ap0 + (k0)); \
        CP16(sptr(&As[s][(lr+64)*GSTH + lc8]), ap1 + (k0)); \
        CP16(sptr(&Bs[s][lr*GSTH + lc8]),      wp0 + (k0)); \
        CP16(sptr(&Bs[s][(lr+64)*GSTH + lc8]), wp1 + (k0)); \
        CP_COMMIT(); \
    } while (0)

    GLOAD(0, 0);
    GLOAD(1, 32);

    for (int t = 0; t < kt; ++t) {
        int s = t % 3;
        CP_WAIT1();
        __syncthreads();
        if (t + 2 < kt) { GLOAD((t+2)%3, (t+2)*32); }
        else            { CP_COMMIT(); }

        #pragma unroll
        for (int ks = 0; ks < 2; ++ks) {
            int kk = ks*16;
            unsigned a[2][4], bq[4][4];
            #pragma unroll
            for (int mt = 0; mt < 2; ++mt)
                LDSM4(a[mt][0],a[mt][1],a[mt][2],a[mt][3],
                      sptr(&As[s][(wm*32 + mt*16 + rA)*GSTH + kk + cA]));
            #pragma unroll
            for (int p = 0; p < 4; ++p)
                LDSM4(bq[p][0],bq[p][1],bq[p][2],bq[p][3],
                      sptr(&Bs[s][(wn*64 + p*16 + rB)*GSTH + kk + cB]));
            #pragma unroll
            for (int p = 0; p < 4; ++p)
                #pragma unroll
                for (int q = 0; q < 2; ++q) {
                    int nt = p*2 + q;
                    MMA_F16(c[0][nt], a[0][0],a[0][1],a[0][2],a[0][3], bq[p][q], bq[p][q+2]);
                    MMA_F16(c[1][nt], a[1][0],a[1][1],a[1][2],a[1][3], bq[p][q], bq[p][q+2]);
                }
        }
    }
    #undef GLOAD

    #pragma unroll
    for (int mt = 0; mt < 2; ++mt) {
        int r0 = row0 + wm*32 + mt*16 + g;
        #pragma unroll
        for (int nt = 0; nt < 8; ++nt) {
            int cc = col0 + wn*64 + nt*8 + 2*tg;
            float b0v = bias[cc], b1v = bias[cc+1];
            float v0 = c[mt][nt][0] + b0v, v1 = c[mt][nt][1] + b1v;
            float v2 = c[mt][nt][2] + b0v, v3 = c[mt][nt][3] + b1v;
            if (relu) { v0=fmaxf(v0,0.f); v1=fmaxf(v1,0.f); v2=fmaxf(v2,0.f); v3=fmaxf(v3,0.f); }
            if (Cf) {
                if (r0 < M)     { float2 s2={v0,v1}; *(float2*)(Cf + (size_t)r0*N + cc) = s2; }
                if (r0 + 8 < M) { float2 s2={v2,v3}; *(float2*)(Cf + (size_t)(r0+8)*N + cc) = s2; }
            }
            if (Ch) {
                if (r0 < M)     *(__half2*)(Ch + (size_t)r0*N + cc)     = __floats2half2_rn(v0, v1);
                if (r0 + 8 < M) *(__half2*)(Ch + (size_t)(r0+8)*N + cc) = __floats2half2_rn(v2, v3);
            }
        }
    }
}

// ---------------- fp16 flash attention: reg-resident P, bias table, f16x2 exp ----------------
// grid (L/128, H, B), block 256 (8 warps); each warp owns 16 query rows x 64 keys.
#define KSTH 40
#define RSN  2176
__global__ __launch_bounds__(256,2) void attn_f16(const __half* __restrict__ qkv,
                                                  const float* __restrict__ rpe,
                                                  __half* __restrict__ o)
{
    __shared__ __align__(16) __half Ks[2][64*KSTH];   // [j][d]
    __shared__ __align__(16) __half Vs[2][64*KSTH];   // [j][d]
    __shared__ float rs[RSN];   // extended bias table, pre-scaled by log2(e)

    int tid = threadIdx.x;
    int w = tid >> 5, lane = tid & 31, g = lane >> 2, tg = lane & 3;
    int b = blockIdx.z, h = blockIdx.y;
    int q0 = blockIdx.x * 128;

    // bias table: rs[idx] = rpe[clip(idx - 127 - q0, -32, 32) + 32][h] * log2e
    // covers idx = j - (r - q0) + 127 for all j in [0,2048), (r-q0) in [0,128)
    for (int i = tid; i < RSN; i += 256) {
        int d = i - 127 - q0;
        d = d < -32 ? -32 : (d > 32 ? 32 : d);
        rs[i] = rpe[(d + 32)*HH + h] * 1.44269504f;
    }

    int la = lane & 7, l8 = (lane >> 3) & 1, l16 = (lane >> 4) & 1;
    int rB = la + l8*8, cB = l16*8;

    int r0 = q0 + w*16 + g, r1 = r0 + 8;
    int rbase = 127 - (w*16 + g) + 2*tg;   // idx for (row r0, key j) = j + rbase

    // persistent Q fragments
    unsigned aq[2][4];
    {
        const __half* qb = qkv + (size_t)(b*LSEQ)*384 + h*HDIM;
        #pragma unroll
        for (int kc = 0; kc < 2; ++kc) {
            int k = kc*16;
            aq[kc][0] = *(const unsigned*)(qb + (size_t)r0*384 + k + 2*tg);
            aq[kc][1] = *(const unsigned*)(qb + (size_t)r1*384 + k + 2*tg);
            aq[kc][2] = *(const unsigned*)(qb + (size_t)r0*384 + k + 2*tg + 8);
            aq[kc][3] = *(const unsigned*)(qb + (size_t)r1*384 + k + 2*tg + 8);
        }
    }

    float co[4][4];
    #pragma unroll
    for (int nt=0;nt<4;++nt)
        #pragma unroll
        for (int i=0;i<4;++i) co[nt][i]=0.f;
    float sum0 = 0.f, sum1 = 0.f;

    int srow = tid >> 2, scol = (tid & 3) * 8;
    const __half* kvbase = qkv + (size_t)(b*LSEQ)*384 + h*HDIM + 128;

    #define STAGE(s, j0) do { \
        const __half* kb_ = kvbase + (size_t)((j0) + srow)*384; \
        CP16(sptr(&Ks[s][srow*KSTH + scol]), kb_ + scol); \
        CP16(sptr(&Vs[s][srow*KSTH + scol]), kb_ + 128 + scol); \
        CP_COMMIT(); \
    } while (0)

    STAGE(0, 0);

    for (int jt = 0; jt < LSEQ/64; ++jt) {
        int s = jt & 1;
        if (jt + 1 < LSEQ/64) { STAGE(s^1, (jt+1)*64); CP_WAIT1(); }
        else                  { CP_WAIT0(); }
        __syncthreads();

        // S = Q @ K^T : 16 x 64 per warp (8 n8-tiles)
        float cs[8][4];
        #pragma unroll
        for (int nt=0;nt<8;++nt)
            #pragma unroll
            for (int i=0;i<4;++i) cs[nt][i]=0.f;
        #pragma unroll
        for (int kc = 0; kc < 2; ++kc) {
            int kk = kc*16;
            unsigned bq[4][4];
            #pragma unroll
            for (int p = 0; p < 4; ++p)
                LDSM4(bq[p][0],bq[p][1],bq[p][2],bq[p][3],
                      sptr(&Ks[s][(p*16 + rB)*KSTH + kk + cB]));
            #pragma unroll
            for (int p = 0; p < 4; ++p)
                #pragma unroll
                for (int q = 0; q < 2; ++q)
                    MMA_F16(cs[p*2+q], aq[kc][0],aq[kc][1],aq[kc][2],aq[kc][3],
                            bq[p][q], bq[p][q+2]);
        }

        // softmax (log2 domain, bias table, f16x2 exp) -> P packed as A fragments
        int ixb = jt*64 + rbase;
        unsigned ap[4][4];
        #pragma unroll
        for (int nt = 0; nt < 8; ++nt) {
            int ix = ixb + nt*8;
            float s0 = fminf(cs[nt][0]*SCALE2 + rs[ix],   15.f);
            float s1 = fminf(cs[nt][1]*SCALE2 + rs[ix+1], 15.f);
            float s2 = fminf(cs[nt][2]*SCALE2 + rs[ix-8], 15.f);
            float s3 = fminf(cs[nt][3]*SCALE2 + rs[ix-7], 15.f);
            unsigned u0, u1;
            asm("ex2.approx.f16x2 %0, %1;" : "=r"(u0) : "r"(h2u(__floats2half2_rn(s0, s1))));
            asm("ex2.approx.f16x2 %0, %1;" : "=r"(u1) : "r"(h2u(__floats2half2_rn(s2, s3))));
            float2 f0 = __half22float2(*(__half2*)&u0);
            float2 f1 = __half22float2(*(__half2*)&u1);
            sum0 += f0.x + f0.y;
            sum1 += f1.x + f1.y;
            int ks = nt >> 1, hi = nt & 1;
            ap[ks][hi*2+0] = u0;
            ap[ks][hi*2+1] = u1;
        }

        // O += P @ V  (16 x 32, k = 64, V via ldmatrix.trans on Vs[j][d])
        #pragma unroll
        for (int ks = 0; ks < 4; ++ks) {
            int kk = ks*16;
            unsigned bv[2][4];
            #pragma unroll
            for (int dg = 0; dg < 2; ++dg)
                LDSM4T(bv[dg][0],bv[dg][1],bv[dg][2],bv[dg][3],
                       sptr(&Vs[s][(kk + la + l8*8)*KSTH + dg*16 + l16*8]));
            #pragma unroll
            for (int dg = 0; dg < 2; ++dg)
                #pragma unroll
                for (int q = 0; q < 2; ++q)
                    MMA_F16(co[dg*2+q], ap[ks][0],ap[ks][1],ap[ks][2],ap[ks][3],
                            bv[dg][q*2], bv[dg][q*2+1]);
        }
        __syncthreads();
    }
    #undef STAGE

    sum0 += __shfl_xor_sync(0xffffffffu, sum0, 1);
    sum0 += __shfl_xor_sync(0xffffffffu, sum0, 2);
    sum1 += __shfl_xor_sync(0xffffffffu, sum1, 1);
    sum1 += __shfl_xor_sync(0xffffffffu, sum1, 2);
    float inv0 = 1.f / sum0, inv1 = 1.f / sum1;

    #pragma unroll
    for (int nt2 = 0; nt2 < 4; ++nt2) {
        int d = nt2*8 + 2*tg;
        *(__half2*)(o + ((size_t)(b*LSEQ + r0))*DM + h*HDIM + d) =
            __floats2half2_rn(co[nt2][0]*inv0, co[nt2][1]*inv0);
        *(__half2*)(o + ((size_t)(b*LSEQ + r1))*DM + h*HDIM + d) =
            __floats2half2_rn(co[nt2][2]*inv1, co[nt2][3]*inv1);
    }
}

// ---------------- residual add + layernorm (f32 out + optional f16 copy) ----------------
__global__ void add_ln_kernel(const float* __restrict__ a, const float* __restrict__ bres,
                              const float* __restrict__ g, const float* __restrict__ beta,
                              float* __restrict__ out, __half* __restrict__ outh)
{
    int row = blockIdx.x;
    int t = threadIdx.x;
    float v = a[(size_t)row*DM + t] + bres[(size_t)row*DM + t];
    float s = v, s2 = v*v;
    #pragma unroll
    for (int off = 16; off; off >>= 1) {
        s  += __shfl_xor_sync(0xffffffffu, s,  off);
        s2 += __shfl_xor_sync(0xffffffffu, s2, off);
    }
    __shared__ float ws[4], ws2[4];
    int w = t >> 5;
    if ((t & 31) == 0) { ws[w] = s; ws2[w] = s2; }
    __syncthreads();
    s  = ws[0]+ws[1]+ws[2]+ws[3];
    s2 = ws2[0]+ws2[1]+ws2[2]+ws2[3];
    float mean = s * (1.f/128.f);
    float var  = s2 * (1.f/128.f) - mean*mean;
    float f = rsqrtf(var + EPSV);
    float r = (v - mean)*f*g[t] + beta[t];
    out[(size_t)row*DM + t] = r;
    if (outh) outh[(size_t)row*DM + t] = __float2half_rn(r);
}

// ---------------- im2col conv1 (pad=2), f16 out ----------------
__global__ void im2col1_kernel(const float* __restrict__ x2, __half* __restrict__ col)
{
    long long e = (long long)blockIdx.x*256 + threadIdx.x;
    if (e >= (long long)BL*640) return;
    int c = (int)(e % 640); int row = (int)(e / 640);
    int ci = c/5, k = c%5;
    int b = row >> 11, l = row & 2047;
    int lx = l + k - 2;
    float v = (lx >= 0 && lx < LSEQ) ? x2[((size_t)(b*LSEQ + lx))*DM + ci] : 0.f;
    col[e] = __float2half_rn(v);
}

// ---------------- im2col conv2 (valid), f16 out ----------------
__global__ void im2col2_kernel(const float* __restrict__ p1, __half* __restrict__ col)
{
    long long e = (long long)blockIdx.x*256 + threadIdx.x;
    if (e >= (long long)M2*640) return;
    int c = (int)(e % 640); int row = (int)(e / 640);
    int c1 = c/5, k = c%5;
    int b = row / L2OUT, l = row % L2OUT;
    col[e] = __float2half_rn(p1[((size_t)(b*L2HALF + l + k))*C1 + c1]);
}

// ---------------- BN stats ----------------
__global__ void bnstats_kernel(const float* __restrict__ y, int rows, int Cc, int rpb,
                               float* __restrict__ sum, float* __restrict__ sumsq)
{
    int c = threadIdx.x;
    int r0 = blockIdx.x * rpb;
    int r1 = r0 + rpb; if (r1 > rows) r1 = rows;
    float s = 0.f, s2 = 0.f;
    for (int r = r0; r < r1; ++r) {
        float v = y[(size_t)r*Cc + c];
        s += v; s2 += v*v;
    }
    atomicAdd(&sum[c], s);
    atomicAdd(&sumsq[c], s2);
}

__global__ void zero_kernel(float* p, int n)
{
    int i = blockIdx.x*256 + threadIdx.x;
    if (i < n) p[i] = 0.f;
}

// ---------------- BN + ReLU + maxpool(2) ----------------
__global__ void bnpool_kernel(const float* __restrict__ y1,
                              const float* __restrict__ sum, const float* __restrict__ sq,
                              const float* __restrict__ g, const float* __restrict__ bb,
                              float* __restrict__ p1)
{
    int c = threadIdx.x;
    int row2 = blockIdx.x;
    int b = row2 >> 10, l2 = row2 & 1023;
    float mean = sum[c]*(1.f/(float)BL);
    float var  = sq[c]*(1.f/(float)BL) - mean*mean;
    float f = rsqrtf(var + EPSV)*g[c];
    float v0 = (y1[((size_t)(b*LSEQ + 2*l2  ))*C1 + c] - mean)*f + bb[c];
    float v1 = (y1[((size_t)(b*LSEQ + 2*l2+1))*C1 + c] - mean)*f + bb[c];
    v0 = fmaxf(v0, 0.f); v1 = fmaxf(v1, 0.f);
    p1[(size_t)row2*C1 + c] = fmaxf(v0, v1);
}

// ---------------- BN + ReLU + global max (parallel, atomicMax) ----------------
__global__ void gmax_kernel(const float* __restrict__ y2,
                            const float* __restrict__ sum, const float* __restrict__ sq,
                            const float* __restrict__ g, const float* __restrict__ bb,
                            float* __restrict__ z)
{
    int c = threadIdx.x;
    int b = blockIdx.x;
    int part = blockIdx.y;
    float mean = sum[c]*(1.f/(float)M2);
    float var  = sq[c]*(1.f/(float)M2) - mean*mean;
    float f = rsqrtf(var + EPSV)*g[c];
    int l0 = part * 128;
    int l1 = l0 + 128; if (l1 > L2OUT) l1 = L2OUT;
    float vm = 0.f;
    for (int l = l0; l < l1; ++l) {
        float v = (y2[((size_t)(b*L2OUT + l))*C2 + c] - mean)*f + bb[c];
        vm = fmaxf(vm, v);
    }
    vm = fmaxf(vm, 0.f);
    atomicMax((int*)&z[b*C2 + c], __float_as_int(vm));
}

// ---------------- final fc ----------------
__global__ void fc_kernel(const float* __restrict__ z, const float* __restrict__ w,
                          const float* __restrict__ bias, float* __restrict__ out)
{
    int b = blockIdx.x, n = blockIdx.y;
    int t = threadIdx.x;
    float p = z[b*C2 + t] * w[n*C2 + t];
    #pragma unroll
    for (int off = 16; off; off >>= 1) p += __shfl_xor_sync(0xffffffffu, p, off);
    __shared__ float ws[8];
    if ((t & 31) == 0) ws[t >> 5] = p;
    __syncthreads();
    if (t == 0) {
        float s = 0.f;
        #pragma unroll
        for (int i = 0; i < 8; ++i) s += ws[i];
        out[b*2 + n] = s + bias[n];
    }
}

// ---------------- launch ----------------
extern "C" void kernel_launch(void* const* d_in, const int* in_sizes, int n_in,
                              void* d_out, int out_size)
{
    const int*   X    = (const int*)  d_in[0];
    const float* sa   = (const float*)d_in[1];
    const int*   ptm  = (const int*)  d_in[2];
    const float* emb  = (const float*)d_in[3];
    const float* pemb = (const float*)d_in[4];
    const float* rpe  = (const float*)d_in[5];
    const float* inw  = (const float*)d_in[6];
    const float* inb  = (const float*)d_in[7];
    const float* opw  = (const float*)d_in[8];
    const float* opb  = (const float*)d_in[9];
    const float* l1w  = (const float*)d_in[10];
    const float* l1b  = (const float*)d_in[11];
    const float* l2w  = (const float*)d_in[12];
    const float* l2b  = (const float*)d_in[13];
    const float* ln1g = (const float*)d_in[14];
    const float* ln1b = (const float*)d_in[15];
    const float* ln2g = (const float*)d_in[16];
    const float* ln2b = (const float*)d_in[17];
    const float* c1w  = (const float*)d_in[18];
    const float* c1b  = (const float*)d_in[19];
    const float* bn1g = (const float*)d_in[20];
    const float* bn1b = (const float*)d_in[21];
    const float* c2w  = (const float*)d_in[22];
    const float* c2b  = (const float*)d_in[23];
    const float* bn2g = (const float*)d_in[24];
    const float* bn2b = (const float*)d_in[25];
    const float* fcw  = (const float*)d_in[26];
    const float* fcb  = (const float*)d_in[27];
    float* out = (float*)d_out;

    float *x0,*tmp,*x1,*x2,*y1,*p1,*y2,*z,*stats;
    __half *x0h,*qkvh,*atth,*x1h,*ff1h,*colh,*wh;
    cudaGetSymbolAddress((void**)&x0,   g_x0);
    cudaGetSymbolAddress((void**)&x0h,  g_x0h);
    cudaGetSymbolAddress((void**)&qkvh, g_qkvh);
    cudaGetSymbolAddress((void**)&atth, g_atth);
    cudaGetSymbolAddress((void**)&tmp,  g_tmp);
    cudaGetSymbolAddress((void**)&x1,   g_x1);
    cudaGetSymbolAddress((void**)&x1h,  g_x1h);
    cudaGetSymbolAddress((void**)&ff1h, g_ff1h);
    cudaGetSymbolAddress((void**)&x2,   g_x2);
    cudaGetSymbolAddress((void**)&colh, g_colh);
    cudaGetSymbolAddress((void**)&y1,   g_y1);
    cudaGetSymbolAddress((void**)&p1,   g_p1);
    cudaGetSymbolAddress((void**)&y2,   g_y2);
    cudaGetSymbolAddress((void**)&z,    g_z);
    cudaGetSymbolAddress((void**)&stats,g_stats);
    cudaGetSymbolAddress((void**)&wh,   g_wh);

    __half* inwh = wh;
    __half* opwh = wh + 49152;
    __half* l1wh = wh + 65536;
    __half* l2wh = wh + 98304;
    __half* c1wh = wh + 131072;
    __half* c2wh = wh + 212992;

    // 0) merged weight conversion (f32 -> f16), one launch
    f2h_all<<<(376832 + 255)/256, 256>>>(inw, opw, l1w, l2w, c1w, c2w, wh);

    // 1) embedding + concat (f32 + f16)
    embed_kernel<<<BL, 128>>>(X, sa, ptm, emb, pemb, x0, x0h);

    // 2) qkv projection -> f16 [BL,384]
    gemm_f16<<<dim3(384/128, BL/128), 256>>>(x0h, inwh, inb, nullptr, qkvh, BL, 3*DM, DM, 0);

    // 3) attention -> f16
    attn_f16<<<dim3(LSEQ/128, HH, BB), 256>>>(qkvh, rpe, atth);

    // 4) out projection -> f32 tmp
    gemm_f16<<<dim3(DM/128, BL/128), 256>>>(atth, opwh, opb, tmp, nullptr, BL, DM, DM, 0);

    // 5) x1 = LN(x0 + attn_out) (f32 + f16)
    add_ln_kernel<<<BL, 128>>>(x0, tmp, ln1g, ln1b, x1, x1h);

    // 6) FF
    gemm_f16<<<dim3(FFD/128, BL/128), 256>>>(x1h, l1wh, l1b, nullptr, ff1h, BL, FFD, DM, 1);
    gemm_f16<<<dim3(DM/128,  BL/128), 256>>>(ff1h, l2wh, l2b, tmp, nullptr, BL, DM, FFD, 0);

    // 7) x2 = LN(x1 + ff) (f32 only)
    add_ln_kernel<<<BL, 128>>>(x1, tmp, ln2g, ln2b, x2, nullptr);

    // 8) conv1 via im2col (f16) + GEMM
    im2col1_kernel<<<(int)(((long long)BL*640 + 255)/256), 256>>>(x2, colh);
    gemm_f16<<<dim3(C1/128, BL/128), 256>>>(colh, c1wh, c1b, y1, nullptr, BL, C1, DM*KK, 0);

    // 9) zero stats + z, BN1 stats
    zero_kernel<<<3, 256>>>(stats, 2*C1 + 2*C2);
    zero_kernel<<<16, 256>>>(z, BB*C2);
    bnstats_kernel<<<128, C1>>>(y1, BL, C1, 256, stats, stats + C1);

    // 10) BN1 + ReLU + maxpool2
    bnpool_kernel<<<BB*L2HALF, C1>>>(y1, stats, stats + C1, bn1g, bn1b, p1);

    // 11) conv2 via im2col (f16) + GEMM
    im2col2_kernel<<<(int)(((long long)M2*640 + 255)/256), 256>>>(p1, colh);
    gemm_f16<<<dim3(C2/128, (M2+127)/128), 256>>>(colh, c2wh, c2b, y2, nullptr, M2, C2, C1*KK, 0);

    // 12) BN2 stats
    bnstats_kernel<<<128, C2>>>(y2, M2, C2, 128, stats + 2*C1, stats + 2*C1 + C2);

    // 13) BN2 + ReLU + global max
    gmax_kernel<<<dim3(BB, 8), C2>>>(y2, stats + 2*C1, stats + 2*C1 + C2, bn2g, bn2b, z);

    // 14) fc
    fc_kernel<<<dim3(BB, 2), 256>>>(z, fcw, fcb, out);
}

// round 11
// speedup vs baseline: 5.4290x; 1.0481x over previous
#include <cuda_runtime.h>
#include <cuda_fp16.h>
#include <math.h>

// ---------------- problem constants ----------------
#define BB    16
#define LSEQ  2048
#define BL    (BB*LSEQ)        // 32768
#define DM    128
#define HH    4
#define HDIM  32
#define FFD   256
#define C1    128
#define C2    256
#define KK    5
#define L2HALF 1024
#define L2OUT  1020
#define M2    (BB*L2OUT)       // 16320
#define EPSV  1e-5f
#define SCALE 0.17677669529663687f
#define SCALE2 0.25501650f     // SCALE * log2(e)

// ---------------- scratch ----------------
__device__ float  g_x0 [BL*DM];
__device__ __half g_x0h[BL*DM];
__device__ __half g_qkvh[BL*3*DM];
__device__ __half g_atth[BL*DM];
__device__ float  g_tmp[BL*DM];
__device__ float  g_x1 [BL*DM];
__device__ __half g_x1h[BL*DM];
__device__ __half g_ff1h[BL*FFD];
__device__ float  g_x2 [BL*DM];
__device__ __half g_colh[BL*640];
__device__ float  g_y1 [BL*C1];
__device__ float  g_p1 [BB*L2HALF*C1];
__device__ float  g_y2 [M2*C2];
__device__ float  g_z  [BB*C2];
__device__ float  g_stats[2*C1 + 2*C2];
// fp16 weight pool: inw(49152) opw(16384) l1w(32768) l2w(32768) c1w(81920) c2w(163840) = 376832
__device__ __half g_wh[376832];

// ---------------- helpers ----------------
__device__ __forceinline__ unsigned sptr(const void* p) {
    return (unsigned)__cvta_generic_to_shared(p);
}
__device__ __forceinline__ unsigned h2u(__half2 h) {
    unsigned u; asm("mov.b32 %0, %1;" : "=r"(u) : "r"(*(unsigned*)&h)); return u;
}
#define CP16(dst, src) asm volatile("cp.async.cg.shared.global [%0], [%1], 16;" :: "r"(dst), "l"(src))
#define CP_COMMIT()    asm volatile("cp.async.commit_group;")
#define CP_WAIT1()     asm volatile("cp.async.wait_group 1;")
#define CP_WAIT0()     asm volatile("cp.async.wait_group 0;")

#define MMA_F16(C, a0,a1,a2,a3, b0,b1) \
    asm volatile("mma.sync.aligned.m16n8k16.row.col.f32.f16.f16.f32 " \
                 "{%0,%1,%2,%3},{%4,%5,%6,%7},{%8,%9},{%0,%1,%2,%3};" \
                 : "+f"((C)[0]),"+f"((C)[1]),"+f"((C)[2]),"+f"((C)[3]) \
                 : "r"(a0),"r"(a1),"r"(a2),"r"(a3),"r"(b0),"r"(b1))

#define LDSM4(R0,R1,R2,R3, A) \
    asm volatile("ldmatrix.sync.aligned.m8n8.x4.shared.b16 {%0,%1,%2,%3}, [%4];" \
                 : "=r"(R0),"=r"(R1),"=r"(R2),"=r"(R3) : "r"(A))
#define LDSM4T(R0,R1,R2,R3, A) \
    asm volatile("ldmatrix.sync.aligned.m8n8.x4.trans.shared.b16 {%0,%1,%2,%3}, [%4];" \
                 : "=r"(R0),"=r"(R1),"=r"(R2),"=r"(R3) : "r"(A))

// ---------------- merged f32 -> f16 weight conversion ----------------
__global__ void f2h_all(const float* __restrict__ s0, const float* __restrict__ s1,
                        const float* __restrict__ s2, const float* __restrict__ s3,
                        const float* __restrict__ s4, const float* __restrict__ s5,
                        __half* __restrict__ dst)
{
    int i = blockIdx.x*256 + threadIdx.x;
    const float* src; int off;
    if      (i < 49152)  { src = s0; off = 0; }
    else if (i < 65536)  { src = s1; off = 49152; }
    else if (i < 98304)  { src = s2; off = 65536; }
    else if (i < 131072) { src = s3; off = 98304; }
    else if (i < 212992) { src = s4; off = 131072; }
    else if (i < 376832) { src = s5; off = 212992; }
    else return;
    dst[i] = __float2half_rn(src[i - off]);
}

// ---------------- embed (writes f32 + f16) ----------------
__global__ void embed_kernel(const int* __restrict__ X, const float* __restrict__ sa,
                             const int* __restrict__ ptm,
                             const float* __restrict__ emb, const float* __restrict__ pemb,
                             float* __restrict__ x0, __half* __restrict__ x0h)
{
    int row = blockIdx.x;
    int t = threadIdx.x;
    float v;
    if (t < 120) v = emb[X[row]*120 + t] * sa[row];
    else         v = pemb[ptm[row]*8 + (t-120)];
    x0[(size_t)row*DM + t] = v;
    x0h[(size_t)row*DM + t] = __float2half_rn(v);
}

// ---------------- fp16 GEMM: 128x128 tile, 3-stage cp.async + ldmatrix ----------------
#define GSTH 40
__global__ __launch_bounds__(256,2) void gemm_f16(const __half* __restrict__ A,
                                                  const __half* __restrict__ W,
                                                  const float* __restrict__ bias,
                                                  float* __restrict__ Cf,
                                                  __half* __restrict__ Ch,
                                                  int M, int N, int K, int relu)
{
    __shared__ __align__(16) __half As[3][128*GSTH];
    __shared__ __align__(16) __half Bs[3][128*GSTH];
    int tid = threadIdx.x;
    int w = tid >> 5, lane = tid & 31, g = lane >> 2, tg = lane & 3;
    int wm = w & 3, wn = w >> 2;
    int row0 = blockIdx.y * 128, col0 = blockIdx.x * 128;

    int la = lane & 7, l8 = (lane >> 3) & 1, l16 = (lane >> 4) & 1;
    int rA = la + l8*8, cA = l16*8;
    int rB = la + l8*8, cB = l16*8;

    int lr = tid >> 2, lc8 = (tid & 3) * 8;
    int ar0 = row0 + lr;      if (ar0 > M-1) ar0 = M-1;
    int ar1 = row0 + lr + 64; if (ar1 > M-1) ar1 = M-1;
    const __half* ap0 = A + (size_t)ar0*K + lc8;
    const __half* ap1 = A + (size_t)ar1*K + lc8;
    const __half* wp0 = W + (size_t)(col0 + lr)*K + lc8;
    const __half* wp1 = W + (size_t)(col0 + lr + 64)*K + lc8;

    float c[2][8][4];
    #pragma unroll
    for (int mt=0; mt<2; ++mt)
        #pragma unroll
        for (int nt=0; nt<8; ++nt)
            #pragma unroll
            for (int i=0;i<4;++i) c[mt][nt][i]=0.f;

    int kt = K >> 5;

    #define GLOAD(s, k0) do { \
        CP16(sptr(&As[s][lr*GSTH + lc8]),      ap0 + (k0)); \
        CP16(sptr(&As[s][(lr+64)*GSTH + lc8]), ap1 + (k0)); \
        CP16(sptr(&Bs[s][lr*GSTH + lc8]),      wp0 + (k0)); \
        CP16(sptr(&Bs[s][(lr+64)*GSTH + lc8]), wp1 + (k0)); \
        CP_COMMIT(); \
    } while (0)

    GLOAD(0, 0);
    GLOAD(1, 32);

    for (int t = 0; t < kt; ++t) {
        int s = t % 3;
        CP_WAIT1();
        __syncthreads();
        if (t + 2 < kt) { GLOAD((t+2)%3, (t+2)*32); }
        else            { CP_COMMIT(); }

        #pragma unroll
        for (int ks = 0; ks < 2; ++ks) {
            int kk = ks*16;
            unsigned a[2][4], bq[4][4];
            #pragma unroll
            for (int mt = 0; mt < 2; ++mt)
                LDSM4(a[mt][0],a[mt][1],a[mt][2],a[mt][3],
                      sptr(&As[s][(wm*32 + mt*16 + rA)*GSTH + kk + cA]));
            #pragma unroll
            for (int p = 0; p < 4; ++p)
                LDSM4(bq[p][0],bq[p][1],bq[p][2],bq[p][3],
                      sptr(&Bs[s][(wn*64 + p*16 + rB)*GSTH + kk + cB]));
            #pragma unroll
            for (int p = 0; p < 4; ++p)
                #pragma unroll
                for (int q = 0; q < 2; ++q) {
                    int nt = p*2 + q;
                    MMA_F16(c[0][nt], a[0][0],a[0][1],a[0][2],a[0][3], bq[p][q], bq[p][q+2]);
                    MMA_F16(c[1][nt], a[1][0],a[1][1],a[1][2],a[1][3], bq[p][q], bq[p][q+2]);
                }
        }
    }
    #undef GLOAD

    #pragma unroll
    for (int mt = 0; mt < 2; ++mt) {
        int r0 = row0 + wm*32 + mt*16 + g;
        #pragma unroll
        for (int nt = 0; nt < 8; ++nt) {
            int cc = col0 + wn*64 + nt*8 + 2*tg;
            float b0v = bias[cc], b1v = bias[cc+1];
            float v0 = c[mt][nt][0] + b0v, v1 = c[mt][nt][1] + b1v;
            float v2 = c[mt][nt][2] + b0v, v3 = c[mt][nt][3] + b1v;
            if (relu) { v0=fmaxf(v0,0.f); v1=fmaxf(v1,0.f); v2=fmaxf(v2,0.f); v3=fmaxf(v3,0.f); }
            if (Cf) {
                if (r0 < M)     { float2 s2={v0,v1}; *(float2*)(Cf + (size_t)r0*N + cc) = s2; }
                if (r0 + 8 < M) { float2 s2={v2,v3}; *(float2*)(Cf + (size_t)(r0+8)*N + cc) = s2; }
            }
            if (Ch) {
                if (r0 < M)     *(__half2*)(Ch + (size_t)r0*N + cc)     = __floats2half2_rn(v0, v1);
                if (r0 + 8 < M) *(__half2*)(Ch + (size_t)(r0+8)*N + cc) = __floats2half2_rn(v2, v3);
            }
        }
    }
}

// ---------------- fp16 flash attention: f16x2 softmax + MMA row-sums ----------------
// grid (L/128, H, B), block 256 (8 warps); each warp owns 16 query rows x 64 keys.
#define KSTH 40
#define RSN  2176
__global__ __launch_bounds__(256,2) void attn_f16(const __half* __restrict__ qkv,
                                                  const float* __restrict__ rpe,
                                                  __half* __restrict__ o)
{
    __shared__ __align__(16) __half Ks[2][64*KSTH];   // [j][d]
    __shared__ __align__(16) __half Vs[2][64*KSTH];   // [j][d]
    __shared__ __half2 rsh2[RSN];  // bias pairs (b(i), b(i+1)), pre-scaled by log2e

    int tid = threadIdx.x;
    int w = tid >> 5, lane = tid & 31, g = lane >> 2, tg = lane & 3;
    int b = blockIdx.z, h = blockIdx.y;
    int q0 = blockIdx.x * 128;

    // bias-pair table: idx = j - (r - q0) + 127 for all j in [0,2048), (r-q0) in [0,128)
    for (int i = tid; i < RSN; i += 256) {
        int d0 = i - 127 - q0;     d0 = d0 < -32 ? -32 : (d0 > 32 ? 32 : d0);
        int d1 = i + 1 - 127 - q0; d1 = d1 < -32 ? -32 : (d1 > 32 ? 32 : d1);
        rsh2[i] = __floats2half2_rn(rpe[(d0 + 32)*HH + h] * 1.44269504f,
                                    rpe[(d1 + 32)*HH + h] * 1.44269504f);
    }

    int la = lane & 7, l8 = (lane >> 3) & 1, l16 = (lane >> 4) & 1;
    int rB = la + l8*8, cB = l16*8;

    int r0 = q0 + w*16 + g, r1 = r0 + 8;
    int rbase = 127 - (w*16 + g) + 2*tg;   // idx for (row r0, key j) = j + rbase

    const unsigned sc2  = h2u(__floats2half2_rn(SCALE2, SCALE2));
    const unsigned cl15 = h2u(__floats2half2_rn(15.f, 15.f));
    const unsigned ones = h2u(__floats2half2_rn(1.f, 1.f));

    // persistent Q fragments
    unsigned aq[2][4];
    {
        const __half* qb = qkv + (size_t)(b*LSEQ)*384 + h*HDIM;
        #pragma unroll
        for (int kc = 0; kc < 2; ++kc) {
            int k = kc*16;
            aq[kc][0] = *(const unsigned*)(qb + (size_t)r0*384 + k + 2*tg);
            aq[kc][1] = *(const unsigned*)(qb + (size_t)r1*384 + k + 2*tg);
            aq[kc][2] = *(const unsigned*)(qb + (size_t)r0*384 + k + 2*tg + 8);
            aq[kc][3] = *(const unsigned*)(qb + (size_t)r1*384 + k + 2*tg + 8);
        }
    }

    float co[4][4];
    #pragma unroll
    for (int nt=0;nt<4;++nt)
        #pragma unroll
        for (int i=0;i<4;++i) co[nt][i]=0.f;
    float csum[4] = {0.f, 0.f, 0.f, 0.f};   // row sums accumulated via MMA vs ones

    int srow = tid >> 2, scol = (tid & 3) * 8;
    const __half* kvbase = qkv + (size_t)(b*LSEQ)*384 + h*HDIM + 128;

    #define STAGE(s, j0) do { \
        const __half* kb_ = kvbase + (size_t)((j0) + srow)*384; \
        CP16(sptr(&Ks[s][srow*KSTH + scol]), kb_ + scol); \
        CP16(sptr(&Vs[s][srow*KSTH + scol]), kb_ + 128 + scol); \
        CP_COMMIT(); \
    } while (0)

    STAGE(0, 0);

    for (int jt = 0; jt < LSEQ/64; ++jt) {
        int s = jt & 1;
        if (jt + 1 < LSEQ/64) { STAGE(s^1, (jt+1)*64); CP_WAIT1(); }
        else                  { CP_WAIT0(); }
        __syncthreads();

        // S = Q @ K^T : 16 x 64 per warp (8 n8-tiles)
        float cs[8][4];
        #pragma unroll
        for (int nt=0;nt<8;++nt)
            #pragma unroll
            for (int i=0;i<4;++i) cs[nt][i]=0.f;
        #pragma unroll
        for (int kc = 0; kc < 2; ++kc) {
            int kk = kc*16;
            unsigned bq[4][4];
            #pragma unroll
            for (int p = 0; p < 4; ++p)
                LDSM4(bq[p][0],bq[p][1],bq[p][2],bq[p][3],
                      sptr(&Ks[s][(p*16 + rB)*KSTH + kk + cB]));
            #pragma unroll
            for (int p = 0; p < 4; ++p)
                #pragma unroll
                for (int q = 0; q < 2; ++q)
                    MMA_F16(cs[p*2+q], aq[kc][0],aq[kc][1],aq[kc][2],aq[kc][3],
                            bq[p][q], bq[p][q+2]);
        }

        // f16x2 softmax: pack -> hfma2(scale,bias) -> hmin2 -> ex2.f16x2 -> P A-frags
        int ixb = jt*64 + rbase;
        unsigned ap[4][4];
        #pragma unroll
        for (int nt = 0; nt < 8; ++nt) {
            int ix = ixb + nt*8;
            unsigned x01 = h2u(__floats2half2_rn(cs[nt][0], cs[nt][1]));
            unsigned x23 = h2u(__floats2half2_rn(cs[nt][2], cs[nt][3]));
            unsigned b01 = *(const unsigned*)&rsh2[ix];
            unsigned b23 = *(const unsigned*)&rsh2[ix-8];
            asm("fma.rn.f16x2 %0, %1, %2, %3;" : "=r"(x01) : "r"(x01), "r"(sc2), "r"(b01));
            asm("fma.rn.f16x2 %0, %1, %2, %3;" : "=r"(x23) : "r"(x23), "r"(sc2), "r"(b23));
            asm("min.f16x2 %0, %1, %2;" : "=r"(x01) : "r"(x01), "r"(cl15));
            asm("min.f16x2 %0, %1, %2;" : "=r"(x23) : "r"(x23), "r"(cl15));
            asm("ex2.approx.f16x2 %0, %1;" : "=r"(x01) : "r"(x01));
            asm("ex2.approx.f16x2 %0, %1;" : "=r"(x23) : "r"(x23));
            int ks = nt >> 1, hi = nt & 1;
            ap[ks][hi*2+0] = x01;
            ap[ks][hi*2+1] = x23;
        }

        // row sums: csum += P @ ones (every output column = row sum)
        #pragma unroll
        for (int ks = 0; ks < 4; ++ks)
            MMA_F16(csum, ap[ks][0],ap[ks][1],ap[ks][2],ap[ks][3], ones, ones);

        // O += P @ V  (16 x 32, k = 64, V via ldmatrix.trans on Vs[j][d])
        #pragma unroll
        for (int ks = 0; ks < 4; ++ks) {
            int kk = ks*16;
            unsigned bv[2][4];
            #pragma unroll
            for (int dg = 0; dg < 2; ++dg)
                LDSM4T(bv[dg][0],bv[dg][1],bv[dg][2],bv[dg][3],
                       sptr(&Vs[s][(kk + la + l8*8)*KSTH + dg*16 + l16*8]));
            #pragma unroll
            for (int dg = 0; dg < 2; ++dg)
                #pragma unroll
                for (int q = 0; q < 2; ++q)
                    MMA_F16(co[dg*2+q], ap[ks][0],ap[ks][1],ap[ks][2],ap[ks][3],
                            bv[dg][q*2], bv[dg][q*2+1]);
        }
        __syncthreads();
    }
    #undef STAGE

    float inv0 = 1.f / csum[0], inv1 = 1.f / csum[2];

    #pragma unroll
    for (int nt2 = 0; nt2 < 4; ++nt2) {
        int d = nt2*8 + 2*tg;
        *(__half2*)(o + ((size_t)(b*LSEQ + r0))*DM + h*HDIM + d) =
            __floats2half2_rn(co[nt2][0]*inv0, co[nt2][1]*inv0);
        *(__half2*)(o + ((size_t)(b*LSEQ + r1))*DM + h*HDIM + d) =
            __floats2half2_rn(co[nt2][2]*inv1, co[nt2][3]*inv1);
    }
}

// ---------------- residual add + layernorm (f32 out + optional f16 copy) ----------------
__global__ void add_ln_kernel(const float* __restrict__ a, const float* __restrict__ bres,
                              const float* __restrict__ g, const float* __restrict__ beta,
                              float* __restrict__ out, __half* __restrict__ outh)
{
    int row = blockIdx.x;
    int t = threadIdx.x;
    float v = a[(size_t)row*DM + t] + bres[(size_t)row*DM + t];
    float s = v, s2 = v*v;
    #pragma unroll
    for (int off = 16; off; off >>= 1) {
        s  += __shfl_xor_sync(0xffffffffu, s,  off);
        s2 += __shfl_xor_sync(0xffffffffu, s2, off);
    }
    __shared__ float ws[4], ws2[4];
    int w = t >> 5;
    if ((t & 31) == 0) { ws[w] = s; ws2[w] = s2; }
    __syncthreads();
    s  = ws[0]+ws[1]+ws[2]+ws[3];
    s2 = ws2[0]+ws2[1]+ws2[2]+ws2[3];
    float mean = s * (1.f/128.f);
    float var  = s2 * (1.f/128.f) - mean*mean;
    float f = rsqrtf(var + EPSV);
    float r = (v - mean)*f*g[t] + beta[t];
    out[(size_t)row*DM + t] = r;
    if (outh) outh[(size_t)row*DM + t] = __float2half_rn(r);
}

// ---------------- im2col conv1 (pad=2), f16 out ----------------
__global__ void im2col1_kernel(const float* __restrict__ x2, __half* __restrict__ col)
{
    long long e = (long long)blockIdx.x*256 + threadIdx.x;
    if (e >= (long long)BL*640) return;
    int c = (int)(e % 640); int row = (int)(e / 640);
    int ci = c/5, k = c%5;
    int b = row >> 11, l = row & 2047;
    int lx = l + k - 2;
    float v = (lx >= 0 && lx < LSEQ) ? x2[((size_t)(b*LSEQ + lx))*DM + ci] : 0.f;
    col[e] = __float2half_rn(v);
}

// ---------------- im2col conv2 (valid), f16 out ----------------
__global__ void im2col2_kernel(const float* __restrict__ p1, __half* __restrict__ col)
{
    long long e = (long long)blockIdx.x*256 + threadIdx.x;
    if (e >= (long long)M2*640) return;
    int c = (int)(e % 640); int row = (int)(e / 640);
    int c1 = c/5, k = c%5;
    int b = row / L2OUT, l = row % L2OUT;
    col[e] = __float2half_rn(p1[((size_t)(b*L2HALF + l + k))*C1 + c1]);
}

// ---------------- BN stats ----------------
__global__ void bnstats_kernel(const float* __restrict__ y, int rows, int Cc, int rpb,
                               float* __restrict__ sum, float* __restrict__ sumsq)
{
    int c = threadIdx.x;
    int r0 = blockIdx.x * rpb;
    int r1 = r0 + rpb; if (r1 > rows) r1 = rows;
    float s = 0.f, s2 = 0.f;
    for (int r = r0; r < r1; ++r) {
        float v = y[(size_t)r*Cc + c];
        s += v; s2 += v*v;
    }
    atomicAdd(&sum[c], s);
    atomicAdd(&sumsq[c], s2);
}

__global__ void zero_kernel(float* p, int n)
{
    int i = blockIdx.x*256 + threadIdx.x;
    if (i < n) p[i] = 0.f;
}

// ---------------- BN + ReLU + maxpool(2) ----------------
__global__ void bnpool_kernel(const float* __restrict__ y1,
                              const float* __restrict__ sum, const float* __restrict__ sq,
                              const float* __restrict__ g, const float* __restrict__ bb,
                              float* __restrict__ p1)
{
    int c = threadIdx.x;
    int row2 = blockIdx.x;
    int b = row2 >> 10, l2 = row2 & 1023;
    float mean = sum[c]*(1.f/(float)BL);
    float var  = sq[c]*(1.f/(float)BL) - mean*mean;
    float f = rsqrtf(var + EPSV)*g[c];
    float v0 = (y1[((size_t)(b*LSEQ + 2*l2  ))*C1 + c] - mean)*f + bb[c];
    float v1 = (y1[((size_t)(b*LSEQ + 2*l2+1))*C1 + c] - mean)*f + bb[c];
    v0 = fmaxf(v0, 0.f); v1 = fmaxf(v1, 0.f);
    p1[(size_t)row2*C1 + c] = fmaxf(v0, v1);
}

// ---------------- BN + ReLU + global max (parallel, atomicMax) ----------------
__global__ void gmax_kernel(const float* __restrict__ y2,
                            const float* __restrict__ sum, const float* __restrict__ sq,
                            const float* __restrict__ g, const float* __restrict__ bb,
                            float* __restrict__ z)
{
    int c = threadIdx.x;
    int b = blockIdx.x;
    int part = blockIdx.y;
    float mean = sum[c]*(1.f/(float)M2);
    float var  = sq[c]*(1.f/(float)M2) - mean*mean;
    float f = rsqrtf(var + EPSV)*g[c];
    int l0 = part * 128;
    int l1 = l0 + 128; if (l1 > L2OUT) l1 = L2OUT;
    float vm = 0.f;
    for (int l = l0; l < l1; ++l) {
        float v = (y2[((size_t)(b*L2OUT + l))*C2 + c] - mean)*f + bb[c];
        vm = fmaxf(vm, v);
    }
    vm = fmaxf(vm, 0.f);
    atomicMax((int*)&z[b*C2 + c], __float_as_int(vm));
}

// ---------------- final fc ----------------
__global__ void fc_kernel(const float* __restrict__ z, const float* __restrict__ w,
                          const float* __restrict__ bias, float* __restrict__ out)
{
    int b = blockIdx.x, n = blockIdx.y;
    int t = threadIdx.x;
    float p = z[b*C2 + t] * w[n*C2 + t];
    #pragma unroll
    for (int off = 16; off; off >>= 1) p += __shfl_xor_sync(0xffffffffu, p, off);
    __shared__ float ws[8];
    if ((t & 31) == 0) ws[t >> 5] = p;
    __syncthreads();
    if (t == 0) {
        float s = 0.f;
        #pragma unroll
        for (int i = 0; i < 8; ++i) s += ws[i];
        out[b*2 + n] = s + bias[n];
    }
}

// ---------------- launch ----------------
extern "C" void kernel_launch(void* const* d_in, const int* in_sizes, int n_in,
                              void* d_out, int out_size)
{
    const int*   X    = (const int*)  d_in[0];
    const float* sa   = (const float*)d_in[1];
    const int*   ptm  = (const int*)  d_in[2];
    const float* emb  = (const float*)d_in[3];
    const float* pemb = (const float*)d_in[4];
    const float* rpe  = (const float*)d_in[5];
    const float* inw  = (const float*)d_in[6];
    const float* inb  = (const float*)d_in[7];
    const float* opw  = (const float*)d_in[8];
    const float* opb  = (const float*)d_in[9];
    const float* l1w  = (const float*)d_in[10];
    const float* l1b  = (const float*)d_in[11];
    const float* l2w  = (const float*)d_in[12];
    const float* l2b  = (const float*)d_in[13];
    const float* ln1g = (const float*)d_in[14];
    const float* ln1b = (const float*)d_in[15];
    const float* ln2g = (const float*)d_in[16];
    const float* ln2b = (const float*)d_in[17];
    const float* c1w  = (const float*)d_in[18];
    const float* c1b  = (const float*)d_in[19];
    const float* bn1g = (const float*)d_in[20];
    const float* bn1b = (const float*)d_in[21];
    const float* c2w  = (const float*)d_in[22];
    const float* c2b  = (const float*)d_in[23];
    const float* bn2g = (const float*)d_in[24];
    const float* bn2b = (const float*)d_in[25];
    const float* fcw  = (const float*)d_in[26];
    const float* fcb  = (const float*)d_in[27];
    float* out = (float*)d_out;

    float *x0,*tmp,*x1,*x2,*y1,*p1,*y2,*z,*stats;
    __half *x0h,*qkvh,*atth,*x1h,*ff1h,*colh,*wh;
    cudaGetSymbolAddress((void**)&x0,   g_x0);
    cudaGetSymbolAddress((void**)&x0h,  g_x0h);
    cudaGetSymbolAddress((void**)&qkvh, g_qkvh);
    cudaGetSymbolAddress((void**)&atth, g_atth);
    cudaGetSymbolAddress((void**)&tmp,  g_tmp);
    cudaGetSymbolAddress((void**)&x1,   g_x1);
    cudaGetSymbolAddress((void**)&x1h,  g_x1h);
    cudaGetSymbolAddress((void**)&ff1h, g_ff1h);
    cudaGetSymbolAddress((void**)&x2,   g_x2);
    cudaGetSymbolAddress((void**)&colh, g_colh);
    cudaGetSymbolAddress((void**)&y1,   g_y1);
    cudaGetSymbolAddress((void**)&p1,   g_p1);
    cudaGetSymbolAddress((void**)&y2,   g_y2);
    cudaGetSymbolAddress((void**)&z,    g_z);
    cudaGetSymbolAddress((void**)&stats,g_stats);
    cudaGetSymbolAddress((void**)&wh,   g_wh);

    __half* inwh = wh;
    __half* opwh = wh + 49152;
    __half* l1wh = wh + 65536;
    __half* l2wh = wh + 98304;
    __half* c1wh = wh + 131072;
    __half* c2wh = wh + 212992;

    // 0) merged weight conversion (f32 -> f16), one launch
    f2h_all<<<(376832 + 255)/256, 256>>>(inw, opw, l1w, l2w, c1w, c2w, wh);

    // 1) embedding + concat (f32 + f16)
    embed_kernel<<<BL, 128>>>(X, sa, ptm, emb, pemb, x0, x0h);

    // 2) qkv projection -> f16 [BL,384]
    gemm_f16<<<dim3(384/128, BL/128), 256>>>(x0h, inwh, inb, nullptr, qkvh, BL, 3*DM, DM, 0);

    // 3) attention -> f16
    attn_f16<<<dim3(LSEQ/128, HH, BB), 256>>>(qkvh, rpe, atth);

    // 4) out projection -> f32 tmp
    gemm_f16<<<dim3(DM/128, BL/128), 256>>>(atth, opwh, opb, tmp, nullptr, BL, DM, DM, 0);

    // 5) x1 = LN(x0 + attn_out) (f32 + f16)
    add_ln_kernel<<<BL, 128>>>(x0, tmp, ln1g, ln1b, x1, x1h);

    // 6) FF
    gemm_f16<<<dim3(FFD/128, BL/128), 256>>>(x1h, l1wh, l1b, nullptr, ff1h, BL, FFD, DM, 1);
    gemm_f16<<<dim3(DM/128,  BL/128), 256>>>(ff1h, l2wh, l2b, tmp, nullptr, BL, DM, FFD, 0);

    // 7) x2 = LN(x1 + ff) (f32 only)
    add_ln_kernel<<<BL, 128>>>(x1, tmp, ln2g, ln2b, x2, nullptr);

    // 8) conv1 via im2col (f16) + GEMM
    im2col1_kernel<<<(int)(((long long)BL*640 + 255)/256), 256>>>(x2, colh);
    gemm_f16<<<dim3(C1/128, BL/128), 256>>>(colh, c1wh, c1b, y1, nullptr, BL, C1, DM*KK, 0);

    // 9) zero stats + z, BN1 stats
    zero_kernel<<<3, 256>>>(stats, 2*C1 + 2*C2);
    zero_kernel<<<16, 256>>>(z, BB*C2);
    bnstats_kernel<<<128, C1>>>(y1, BL, C1, 256, stats, stats + C1);

    // 10) BN1 + ReLU + maxpool2
    bnpool_kernel<<<BB*L2HALF, C1>>>(y1, stats, stats + C1, bn1g, bn1b, p1);

    // 11) conv2 via im2col (f16) + GEMM
    im2col2_kernel<<<(int)(((long long)M2*640 + 255)/256), 256>>>(p1, colh);
    gemm_f16<<<dim3(C2/128, (M2+127)/128), 256>>>(colh, c2wh, c2b, y2, nullptr, M2, C2, C1*KK, 0);

    // 12) BN2 stats
    bnstats_kernel<<<128, C2>>>(y2, M2, C2, 128, stats + 2*C1, stats + 2*C1 + C2);

    // 13) BN2 + ReLU + global max
    gmax_kernel<<<dim3(BB, 8), C2>>>(y2, stats + 2*C1, stats + 2*C1 + C2, bn2g, bn2b, z);

    // 14) fc
    fc_kernel<<<dim3(BB, 2), 256>>>(z, fcw, fcb, out);
}